// round 1
// baseline (speedup 1.0000x reference)
#include <cuda_runtime.h>

// GAU block: B=4, S=2048, D=512, QKD=256, HID=1536
// Round 1: correct fp32 baseline. Tiled SGEMM (64x64x16, 4x4 micro-tile) +
// two LayerNorm kernels. All scratch in __device__ globals (no allocs).

constexpr int Bn = 4, Sn = 2048, Dn = 512, QKDn = 256, HIDn = 1536;
constexpr int BSn = Bn * Sn;               // 8192 rows
constexpr float LN_EPS = 1e-5f;

// ---------------- scratch (device globals; ~281 MB total) ----------------
static __device__ float g_tmp1[BSn * Dn];                    // x + x@Wm^T + bm
static __device__ float g_norm[BSn * Dn];                    // LN1 output
static __device__ float g_h[BSn * 2 * HIDn];                 // relu(normed@Wh^T+bh): [v | gate]
static __device__ float g_Z[BSn * QKDn];                     // relu(normed@Wq^T+bq)
static __device__ float g_ZW[BSn * QKDn];                    // Z @ Wb
static __device__ float g_A[Bn * Sn * Sn];                   // relu(QK)^2
static __device__ float g_V[BSn * HIDn];                     // (A@v)*gate
static __device__ float g_U[BSn * Dn];                       // V@Wo^T + bo

// ---------------- generic tiled GEMM ----------------
// C[m,n] = sum_k A[m,k] * (TRANS_B ? B[n,k] : B[k,n]), plus epilogue.
// All M % 64 == 0, N % 64 == 0, K % 16 == 0 for this problem -> no bounds checks.
enum { EPI_NONE = 0, EPI_BIAS = 1, EPI_BIAS_RELU = 2, EPI_BIAS_ADDX = 3,
       EPI_RELUSQ = 4, EPI_GATE = 5 };

template<bool TRANS_B, int EPI>
__global__ __launch_bounds__(256)
void gemm_kernel(const float* __restrict__ A, const float* __restrict__ B,
                 const float* __restrict__ bias, const float* __restrict__ extra,
                 float* __restrict__ C,
                 int M, int N, int K, int lda, int ldb, int ldc,
                 long long sA, long long sB, long long sC, long long sE,
                 int lde, float scale)
{
    __shared__ float As[16][65];   // [k][m], padded to kill store conflicts
    __shared__ float Bs[16][65];   // [k][n]

    const int z = blockIdx.z;
    A += (long long)z * sA;
    B += (long long)z * sB;
    C += (long long)z * sC;
    const float* Ex = extra ? extra + (long long)z * sE : nullptr;

    const int m0 = blockIdx.y * 64;
    const int n0 = blockIdx.x * 64;
    const int tid = threadIdx.x;
    const int tx = tid & 15;        // 0..15  -> 4 cols each
    const int ty = tid >> 4;        // 0..15  -> 4 rows each

    float acc[4][4] = {};

    for (int k0 = 0; k0 < K; k0 += 16) {
        // load A tile 64(m) x 16(k): consecutive tid -> consecutive k (coalesced rows)
        #pragma unroll
        for (int p = 0; p < 4; p++) {
            int idx = tid + p * 256;
            int k = idx & 15, m = idx >> 4;
            As[k][m] = A[(long long)(m0 + m) * lda + (k0 + k)];
        }
        if (TRANS_B) {
            #pragma unroll
            for (int p = 0; p < 4; p++) {
                int idx = tid + p * 256;
                int k = idx & 15, n = idx >> 4;
                Bs[k][n] = B[(long long)(n0 + n) * ldb + (k0 + k)];
            }
        } else {
            #pragma unroll
            for (int p = 0; p < 4; p++) {
                int idx = tid + p * 256;
                int n = idx & 63, k = idx >> 6;
                Bs[k][n] = B[(long long)(k0 + k) * ldb + (n0 + n)];
            }
        }
        __syncthreads();

        #pragma unroll
        for (int k = 0; k < 16; k++) {
            float af[4], bf[4];
            #pragma unroll
            for (int i = 0; i < 4; i++) af[i] = As[k][ty * 4 + i];
            #pragma unroll
            for (int j = 0; j < 4; j++) bf[j] = Bs[k][tx * 4 + j];
            #pragma unroll
            for (int i = 0; i < 4; i++)
                #pragma unroll
                for (int j = 0; j < 4; j++)
                    acc[i][j] = fmaf(af[i], bf[j], acc[i][j]);
        }
        __syncthreads();
    }

    #pragma unroll
    for (int i = 0; i < 4; i++) {
        int m = m0 + ty * 4 + i;
        #pragma unroll
        for (int j = 0; j < 4; j++) {
            int n = n0 + tx * 4 + j;
            float v = acc[i][j];
            if (EPI == EPI_BIAS || EPI == EPI_BIAS_RELU || EPI == EPI_BIAS_ADDX)
                v += bias[n];
            if (EPI == EPI_BIAS_RELU)
                v = fmaxf(v, 0.0f);
            if (EPI == EPI_BIAS_ADDX)
                v += Ex[(long long)m * lde + n];
            if (EPI == EPI_RELUSQ) {
                v *= scale;
                v = fmaxf(v, 0.0f);
                v = v * v;
            }
            if (EPI == EPI_GATE)
                v *= Ex[(long long)m * lde + n];
            C[(long long)m * ldc + n] = v;
        }
    }
}

// ---------------- LayerNorm (two-pass, one block per row, D=512) ----------------
__device__ __forceinline__ float block_sum_512(float v, float* red)
{
    #pragma unroll
    for (int o = 16; o > 0; o >>= 1) v += __shfl_down_sync(0xffffffffu, v, o);
    if ((threadIdx.x & 31) == 0) red[threadIdx.x >> 5] = v;
    __syncthreads();
    if (threadIdx.x == 0) {
        float s = 0.0f;
        #pragma unroll
        for (int i = 0; i < 8; i++) s += red[i];
        red[0] = s;
    }
    __syncthreads();
    float r = red[0];
    __syncthreads();   // allow red[] reuse by a later call
    return r;
}

__global__ __launch_bounds__(256)
void ln_kernel(const float* __restrict__ in, const float* __restrict__ g,
               const float* __restrict__ b, const float* __restrict__ resid,
               float* __restrict__ out)
{
    __shared__ float red[8];
    const long long row = blockIdx.x;
    const int t = threadIdx.x;
    const float* rp = in + row * Dn;

    float v0 = rp[t];
    float v1 = rp[t + 256];

    float mean = block_sum_512(v0 + v1, red) * (1.0f / Dn);
    float d0 = v0 - mean, d1 = v1 - mean;
    float var = block_sum_512(d0 * d0 + d1 * d1, red) * (1.0f / Dn);
    float inv = rsqrtf(var + LN_EPS);

    float o0 = d0 * inv * g[t]       + b[t];
    float o1 = d1 * inv * g[t + 256] + b[t + 256];
    if (resid) {
        o0 += resid[row * Dn + t];
        o1 += resid[row * Dn + t + 256];
    }
    out[row * Dn + t]       = o0;
    out[row * Dn + t + 256] = o1;
}

// ---------------- launch ----------------
extern "C" void kernel_launch(void* const* d_in, const int* in_sizes, int n_in,
                              void* d_out, int out_size)
{
    const float* x  = (const float*)d_in[0];
    const float* Wm = (const float*)d_in[1];
    const float* bm = (const float*)d_in[2];
    const float* g1 = (const float*)d_in[3];
    const float* b1 = (const float*)d_in[4];
    const float* Wh = (const float*)d_in[5];
    const float* bh = (const float*)d_in[6];
    const float* Wq = (const float*)d_in[7];
    const float* bq = (const float*)d_in[8];
    const float* Wb = (const float*)d_in[9];
    const float* Wo = (const float*)d_in[10];
    const float* bo = (const float*)d_in[11];
    const float* g2 = (const float*)d_in[12];
    const float* b2 = (const float*)d_in[13];
    float* out = (float*)d_out;

    float *tmp1, *nrm, *h, *Z, *ZW, *Ab, *Vb, *U;
    cudaGetSymbolAddress((void**)&tmp1, g_tmp1);
    cudaGetSymbolAddress((void**)&nrm,  g_norm);
    cudaGetSymbolAddress((void**)&h,    g_h);
    cudaGetSymbolAddress((void**)&Z,    g_Z);
    cudaGetSymbolAddress((void**)&ZW,   g_ZW);
    cudaGetSymbolAddress((void**)&Ab,   g_A);
    cudaGetSymbolAddress((void**)&Vb,   g_V);
    cudaGetSymbolAddress((void**)&U,    g_U);

    const float inv_s = 1.0f / (float)Sn;

    // 1) tmp1 = x @ Wm^T + bm + x     (M=8192, N=512, K=512)
    gemm_kernel<true, EPI_BIAS_ADDX><<<dim3(Dn / 64, BSn / 64, 1), 256>>>(
        x, Wm, bm, x, tmp1, BSn, Dn, Dn, Dn, Dn, Dn, 0, 0, 0, 0, Dn, 1.0f);

    // 2) nrm = LN(tmp1; g1, b1)
    ln_kernel<<<BSn, 256>>>(tmp1, g1, b1, nullptr, nrm);

    // 3) h = relu(nrm @ Wh^T + bh)    (N=3072)
    gemm_kernel<true, EPI_BIAS_RELU><<<dim3(2 * HIDn / 64, BSn / 64, 1), 256>>>(
        nrm, Wh, bh, nullptr, h, BSn, 2 * HIDn, Dn, Dn, Dn, 2 * HIDn, 0, 0, 0, 0, 0, 1.0f);

    // 4) Z = relu(nrm @ Wq^T + bq)    (N=256)
    gemm_kernel<true, EPI_BIAS_RELU><<<dim3(QKDn / 64, BSn / 64, 1), 256>>>(
        nrm, Wq, bq, nullptr, Z, BSn, QKDn, Dn, Dn, Dn, QKDn, 0, 0, 0, 0, 0, 1.0f);

    // 5) ZW = Z @ Wb                  (nn, N=K=256)
    gemm_kernel<false, EPI_NONE><<<dim3(QKDn / 64, BSn / 64, 1), 256>>>(
        Z, Wb, nullptr, nullptr, ZW, BSn, QKDn, QKDn, QKDn, QKDn, QKDn, 0, 0, 0, 0, 0, 1.0f);

    // 6) A = relu((ZW @ Z^T) / S)^2   (batched over B, M=N=2048, K=256)
    gemm_kernel<true, EPI_RELUSQ><<<dim3(Sn / 64, Sn / 64, Bn), 256>>>(
        ZW, Z, nullptr, nullptr, Ab, Sn, Sn, QKDn, QKDn, QKDn, Sn,
        (long long)Sn * QKDn, (long long)Sn * QKDn, (long long)Sn * Sn, 0, 0, inv_s);

    // 7) V = (A @ v) * gate           (batched, nn, N=1536, K=2048; v/gate strided in h)
    gemm_kernel<false, EPI_GATE><<<dim3(HIDn / 64, Sn / 64, Bn), 256>>>(
        Ab, h, nullptr, h + HIDn, Vb, Sn, HIDn, Sn, Sn, 2 * HIDn, HIDn,
        (long long)Sn * Sn, (long long)Sn * 2 * HIDn, (long long)Sn * HIDn,
        (long long)Sn * 2 * HIDn, 2 * HIDn, 1.0f);

    // 8) U = V @ Wo^T + bo            (N=512, K=1536)
    gemm_kernel<true, EPI_BIAS><<<dim3(Dn / 64, BSn / 64, 1), 256>>>(
        Vb, Wo, bo, nullptr, U, BSn, Dn, HIDn, HIDn, HIDn, Dn, 0, 0, 0, 0, 0, 1.0f);

    // 9) out = LN(U; g2, b2) + x
    ln_kernel<<<BSn, 256>>>(U, g2, b2, x, out);
}

// round 3
// speedup vs baseline: 3.0307x; 3.0307x over previous
#include <cuda_runtime.h>
#include <cuda_bf16.h>
#include <cstdint>

// GAU block on GB300 (sm_103, no 'a' features available from this toolchain path):
// bf16 hi/lo-split GEMMs on mma.sync.m16n8k16 + ldmatrix + cp.async.
// B=4, S=2048, D=512, QKD=256, HID=1536

constexpr int Bn = 4, Sn = 2048, Dn = 512, QKDn = 256, HIDn = 1536;
constexpr int BSn = Bn * Sn;                 // 8192
constexpr float LN_EPS = 1e-5f;

// ----------------------------------------------------------------------------
// scratch (device globals)
// ----------------------------------------------------------------------------
static __device__ __align__(16) __nv_bfloat16 g_xh[BSn * Dn],        g_xl[BSn * Dn];
static __device__ __align__(16) __nv_bfloat16 g_Wmh[Dn * Dn],        g_Wml[Dn * Dn];
static __device__ __align__(16) __nv_bfloat16 g_Whh[2 * HIDn * Dn],  g_Whl[2 * HIDn * Dn];
static __device__ __align__(16) __nv_bfloat16 g_Wqh[QKDn * Dn],      g_Wql[QKDn * Dn];
static __device__ __align__(16) __nv_bfloat16 g_Woh[Dn * HIDn],      g_Wol[Dn * HIDn];
static __device__ __align__(16) __nv_bfloat16 g_WbTh[QKDn * QKDn],   g_WbTl[QKDn * QKDn];
static __device__ __align__(16) float         g_tmp1[BSn * Dn];
static __device__ __align__(16) __nv_bfloat16 g_nh[BSn * Dn],        g_nl[BSn * Dn];
static __device__ __align__(16) float         g_hbuf[BSn * 2 * HIDn];     // [v | gate]
static __device__ __align__(16) __nv_bfloat16 g_Zh[BSn * QKDn],      g_Zl[BSn * QKDn];
static __device__ __align__(16) __nv_bfloat16 g_ZWh[BSn * QKDn],     g_ZWl[BSn * QKDn];
static __device__ __align__(16) __nv_bfloat16 g_Amh[(long long)Bn * Sn * Sn], g_Aml[(long long)Bn * Sn * Sn];
static __device__ __align__(16) __nv_bfloat16 g_vTh[(long long)Bn * HIDn * Sn], g_vTl[(long long)Bn * HIDn * Sn];
static __device__ __align__(16) __nv_bfloat16 g_Vh[BSn * HIDn],      g_Vl[BSn * HIDn];
static __device__ __align__(16) float         g_U[BSn * Dn];

// ----------------------------------------------------------------------------
// PTX helpers (all sm_80-class: work on plain sm_103 target)
// ----------------------------------------------------------------------------
__device__ __forceinline__ uint32_t smem_u32(const void* p) {
    uint32_t a;
    asm("{ .reg .u64 t; cvta.to.shared.u64 t, %1; cvt.u32.u64 %0, t; }"
        : "=r"(a) : "l"(p));
    return a;
}
__device__ __forceinline__ void cpa16(uint32_t saddr, const void* gaddr) {
    asm volatile("cp.async.cg.shared.global [%0], [%1], 16;"
                 :: "r"(saddr), "l"(gaddr) : "memory");
}
__device__ __forceinline__ void cpa_commit() {
    asm volatile("cp.async.commit_group;" ::: "memory");
}
template<int N>
__device__ __forceinline__ void cpa_wait() {
    asm volatile("cp.async.wait_group %0;" :: "n"(N) : "memory");
}
__device__ __forceinline__ void ldm_x4(uint32_t a, uint32_t& r0, uint32_t& r1,
                                       uint32_t& r2, uint32_t& r3) {
    asm volatile("ldmatrix.sync.aligned.m8n8.x4.shared.b16 {%0,%1,%2,%3}, [%4];"
                 : "=r"(r0), "=r"(r1), "=r"(r2), "=r"(r3) : "r"(a));
}
__device__ __forceinline__ void mma_bf16(float* c, const uint32_t* a, uint32_t b0, uint32_t b1) {
    asm volatile(
        "mma.sync.aligned.m16n8k16.row.col.f32.bf16.bf16.f32 "
        "{%0,%1,%2,%3}, {%4,%5,%6,%7}, {%8,%9}, {%0,%1,%2,%3};"
        : "+f"(c[0]), "+f"(c[1]), "+f"(c[2]), "+f"(c[3])
        : "r"(a[0]), "r"(a[1]), "r"(a[2]), "r"(a[3]), "r"(b0), "r"(b1));
}

// ----------------------------------------------------------------------------
// tensor GEMM: C[m,n] = sum_k A[m,k]*B[n,k] (both K-major, fp32 via hi/lo bf16)
// CTA tile 128x128, K-tile 32, 8 warps (4m x 2n -> warp tile 32x64).
// smem tile: 128 rows x 80B (64B data + 16B pad) -> conflict-free ldmatrix.
// ----------------------------------------------------------------------------
enum { EPI_NONE = 0, EPI_BIAS = 1, EPI_BIAS_RELU = 2, EPI_BIAS_ADDX = 3,
       EPI_RELUSQ = 4, EPI_GATE = 5 };

constexpr int TROW = 80;                         // padded row bytes
constexpr int TILE_B = 128 * TROW;               // 10240 per tile
constexpr int STAGE_B = 4 * TILE_B;              // Ah, Al, Bh, Bl = 40960
constexpr int SMEM_BYTES = 2 * STAGE_B;          // 81920

__device__ __forceinline__ void fill_tile(uint32_t sbase,
                                          const __nv_bfloat16* __restrict__ g,
                                          long long row0, int ld, long long k0, int tid)
{
    #pragma unroll
    for (int it = 0; it < 2; ++it) {
        int q = tid + it * 256;               // 0..511
        int r = q >> 2, c = q & 3;
        cpa16(sbase + r * TROW + c * 16,
              g + (row0 + r) * (long long)ld + k0 + c * 8);
    }
}

template<int EPI, bool SPLIT>
__global__ void __launch_bounds__(256, 1)
tgemm(const __nv_bfloat16* __restrict__ pAh, const __nv_bfloat16* __restrict__ pAl,
      const __nv_bfloat16* __restrict__ pBh, const __nv_bfloat16* __restrict__ pBl,
      const float* __restrict__ bias, const float* __restrict__ extra,
      float* __restrict__ Cf, __nv_bfloat16* __restrict__ Ch, __nv_bfloat16* __restrict__ Cl,
      int K, int lda, int ldb, int ldc,
      long long sA, long long sB, long long sC, long long sE,
      int lde, float scale)
{
    extern __shared__ char smem[];
    const int tid = threadIdx.x;
    const int wid = tid >> 5, lane = tid & 31;
    const int z = blockIdx.z;
    pAh += (long long)z * sA;  pAl += (long long)z * sA;
    pBh += (long long)z * sB;  pBl += (long long)z * sB;
    const float* Ex = extra ? extra + (long long)z * sE : nullptr;
    const long long coff = (long long)z * sC;
    const long long m0 = (long long)blockIdx.y * 128;
    const long long n0 = (long long)blockIdx.x * 128;
    const uint32_t sb = smem_u32(smem);

    const int wm = (wid >> 1) * 32;      // warp m offset (0,32,64,96)
    const int wn = (wid & 1) * 64;       // warp n offset (0,64)

    // per-lane ldmatrix addressing pieces
    const int rowL = (lane & 7) + ((lane >> 3) & 1) * 8;   // 0..15
    const int cOff = lane >> 4;                            // 0..1

    float acc[2][8][4];
    #pragma unroll
    for (int i = 0; i < 2; ++i)
        #pragma unroll
        for (int j = 0; j < 8; ++j)
            #pragma unroll
            for (int t = 0; t < 4; ++t) acc[i][j][t] = 0.0f;

    const int KT = K >> 5;   // K-tiles of 32

    // prologue: fill stage 0
    {
        uint32_t s0 = sb;
        fill_tile(s0,              pAh, m0, lda, 0, tid);
        fill_tile(s0 + TILE_B,     pAl, m0, lda, 0, tid);
        fill_tile(s0 + 2 * TILE_B, pBh, n0, ldb, 0, tid);
        fill_tile(s0 + 3 * TILE_B, pBl, n0, ldb, 0, tid);
        cpa_commit();
    }

    for (int kt = 0; kt < KT; ++kt) {
        if (kt + 1 < KT) {
            uint32_t s1 = sb + ((kt + 1) & 1) * STAGE_B;
            long long k0 = (long long)(kt + 1) * 32;
            fill_tile(s1,              pAh, m0, lda, k0, tid);
            fill_tile(s1 + TILE_B,     pAl, m0, lda, k0, tid);
            fill_tile(s1 + 2 * TILE_B, pBh, n0, ldb, k0, tid);
            fill_tile(s1 + 3 * TILE_B, pBl, n0, ldb, k0, tid);
            cpa_commit();
            cpa_wait<1>();
        } else {
            cpa_wait<0>();
        }
        __syncthreads();

        const uint32_t st = sb + (kt & 1) * STAGE_B;
        const uint32_t aBh = st;
        const uint32_t aBl = st + TILE_B;
        const uint32_t bBh = st + 2 * TILE_B;
        const uint32_t bBl = st + 3 * TILE_B;

        #pragma unroll
        for (int kk = 0; kk < 2; ++kk) {
            const int cc = kk * 2 + cOff;
            uint32_t ah[2][4], al[2][4];
            #pragma unroll
            for (int im = 0; im < 2; ++im) {
                uint32_t off = (uint32_t)((wm + im * 16 + rowL) * TROW + cc * 16);
                ldm_x4(aBh + off, ah[im][0], ah[im][1], ah[im][2], ah[im][3]);
                ldm_x4(aBl + off, al[im][0], al[im][1], al[im][2], al[im][3]);
            }
            uint32_t bh[4][4], bl[4][4];
            #pragma unroll
            for (int nb = 0; nb < 4; ++nb) {
                uint32_t off = (uint32_t)((wn + nb * 16 + rowL) * TROW + cc * 16);
                ldm_x4(bBh + off, bh[nb][0], bh[nb][1], bh[nb][2], bh[nb][3]);
                ldm_x4(bBl + off, bl[nb][0], bl[nb][1], bl[nb][2], bl[nb][3]);
            }
            #pragma unroll
            for (int im = 0; im < 2; ++im) {
                #pragma unroll
                for (int j = 0; j < 8; ++j) {
                    const int nb = j >> 1, sel = j & 1;
                    mma_bf16(acc[im][j], ah[im], bh[nb][sel], bh[nb][sel + 2]);
                    mma_bf16(acc[im][j], ah[im], bl[nb][sel], bl[nb][sel + 2]);
                    mma_bf16(acc[im][j], al[im], bh[nb][sel], bh[nb][sel + 2]);
                }
            }
        }
        __syncthreads();
    }

    // ---- epilogue: direct register -> gmem ----
    const int rql = lane >> 2;          // 0..7
    const int cql = (lane & 3) * 2;     // 0,2,4,6

    #pragma unroll
    for (int im = 0; im < 2; ++im) {
        #pragma unroll
        for (int j = 0; j < 8; ++j) {
            #pragma unroll
            for (int half = 0; half < 2; ++half) {
                const long long gm = m0 + wm + im * 16 + rql + half * 8;
                const long long gn = n0 + wn + j * 8 + cql;
                float v0 = acc[im][j][half * 2 + 0];
                float v1 = acc[im][j][half * 2 + 1];

                if (EPI == EPI_BIAS || EPI == EPI_BIAS_RELU || EPI == EPI_BIAS_ADDX) {
                    float2 bv = *reinterpret_cast<const float2*>(&bias[gn]);
                    v0 += bv.x; v1 += bv.y;
                }
                if (EPI == EPI_BIAS_RELU) { v0 = fmaxf(v0, 0.0f); v1 = fmaxf(v1, 0.0f); }
                if (EPI == EPI_BIAS_ADDX || EPI == EPI_GATE) {
                    float2 ev = *reinterpret_cast<const float2*>(&Ex[gm * lde + gn]);
                    if (EPI == EPI_BIAS_ADDX) { v0 += ev.x; v1 += ev.y; }
                    else                      { v0 *= ev.x; v1 *= ev.y; }
                }
                if (EPI == EPI_RELUSQ) {
                    float r0 = fmaxf(v0 * scale, 0.0f), r1 = fmaxf(v1 * scale, 0.0f);
                    v0 = r0 * r0; v1 = r1 * r1;
                }

                const long long oi = coff + gm * ldc + gn;
                if (SPLIT) {
                    __nv_bfloat16 h0 = __float2bfloat16(v0), h1 = __float2bfloat16(v1);
                    __nv_bfloat16 l0 = __float2bfloat16(v0 - __bfloat162float(h0));
                    __nv_bfloat16 l1 = __float2bfloat16(v1 - __bfloat162float(h1));
                    uint32_t hp, lp2;
                    hp  = (uint32_t)__bfloat16_as_ushort(h0) | ((uint32_t)__bfloat16_as_ushort(h1) << 16);
                    lp2 = (uint32_t)__bfloat16_as_ushort(l0) | ((uint32_t)__bfloat16_as_ushort(l1) << 16);
                    *reinterpret_cast<uint32_t*>(&Ch[oi]) = hp;
                    *reinterpret_cast<uint32_t*>(&Cl[oi]) = lp2;
                } else {
                    *reinterpret_cast<float2*>(&Cf[oi]) = make_float2(v0, v1);
                }
            }
        }
    }
}

// ----------------------------------------------------------------------------
// LayerNorm (D=512), optionally emitting hi/lo bf16
// ----------------------------------------------------------------------------
__device__ __forceinline__ float block_sum_512(float v, float* red)
{
    #pragma unroll
    for (int o = 16; o > 0; o >>= 1) v += __shfl_down_sync(0xffffffffu, v, o);
    if ((threadIdx.x & 31) == 0) red[threadIdx.x >> 5] = v;
    __syncthreads();
    if (threadIdx.x == 0) {
        float s = 0.0f;
        #pragma unroll
        for (int i = 0; i < 8; i++) s += red[i];
        red[0] = s;
    }
    __syncthreads();
    float r = red[0];
    __syncthreads();
    return r;
}

template<bool SPLIT>
__global__ void __launch_bounds__(256)
ln_kernel(const float* __restrict__ in, const float* __restrict__ g,
          const float* __restrict__ b, const float* __restrict__ resid,
          float* __restrict__ outf, __nv_bfloat16* __restrict__ oh,
          __nv_bfloat16* __restrict__ ol)
{
    __shared__ float red[8];
    const long long row = blockIdx.x;
    const int t = threadIdx.x;
    const float* rp = in + row * Dn;

    float v0 = rp[t], v1 = rp[t + 256];
    float mean = block_sum_512(v0 + v1, red) * (1.0f / Dn);
    float d0 = v0 - mean, d1 = v1 - mean;
    float var = block_sum_512(d0 * d0 + d1 * d1, red) * (1.0f / Dn);
    float inv = rsqrtf(var + LN_EPS);

    float o0 = d0 * inv * g[t]       + b[t];
    float o1 = d1 * inv * g[t + 256] + b[t + 256];
    if (SPLIT) {
        __nv_bfloat16 h0 = __float2bfloat16(o0), h1 = __float2bfloat16(o1);
        oh[row * Dn + t]       = h0;
        oh[row * Dn + t + 256] = h1;
        ol[row * Dn + t]       = __float2bfloat16(o0 - __bfloat162float(h0));
        ol[row * Dn + t + 256] = __float2bfloat16(o1 - __bfloat162float(h1));
    } else {
        if (resid) {
            o0 += resid[row * Dn + t];
            o1 += resid[row * Dn + t + 256];
        }
        outf[row * Dn + t]       = o0;
        outf[row * Dn + t + 256] = o1;
    }
}

// ----------------------------------------------------------------------------
// fp32 -> (hi, lo) bf16 converters
// ----------------------------------------------------------------------------
__global__ void __launch_bounds__(256)
cvt_split_kernel(const float* __restrict__ in, __nv_bfloat16* __restrict__ oh,
                 __nv_bfloat16* __restrict__ ol, int n4)
{
    int i = blockIdx.x * 256 + threadIdx.x;
    if (i >= n4) return;
    float4 v = reinterpret_cast<const float4*>(in)[i];
    float vv[4] = {v.x, v.y, v.z, v.w};
    __nv_bfloat16 h[4], l[4];
    #pragma unroll
    for (int t = 0; t < 4; ++t) {
        h[t] = __float2bfloat16(vv[t]);
        l[t] = __float2bfloat16(vv[t] - __bfloat162float(h[t]));
    }
    reinterpret_cast<uint2*>(oh)[i] = *reinterpret_cast<uint2*>(h);
    reinterpret_cast<uint2*>(ol)[i] = *reinterpret_cast<uint2*>(l);
}

// transpose + split: out[c][r] = in[r][c]
__global__ void __launch_bounds__(256)
cvt_tr_kernel(const float* __restrict__ in, __nv_bfloat16* __restrict__ oh,
              __nv_bfloat16* __restrict__ ol,
              int ldin, long long sIn, long long sOut, int ldout)
{
    __shared__ float tbuf[32][33];
    const int z = blockIdx.z;
    const float* ip = in + (long long)z * sIn;
    const long long obase = (long long)z * sOut;
    const int c0 = blockIdx.x * 32, r0 = blockIdx.y * 32;
    const int tx = threadIdx.x & 31, ty = threadIdx.x >> 5;   // 32 x 8

    #pragma unroll
    for (int i = 0; i < 4; i++)
        tbuf[ty + i * 8][tx] = ip[(long long)(r0 + ty + i * 8) * ldin + c0 + tx];
    __syncthreads();
    #pragma unroll
    for (int i = 0; i < 4; i++) {
        float v = tbuf[tx][ty + i * 8];
        __nv_bfloat16 h = __float2bfloat16(v);
        long long oi = obase + (long long)(c0 + ty + i * 8) * ldout + r0 + tx;
        oh[oi] = h;
        ol[oi] = __float2bfloat16(v - __bfloat162float(h));
    }
}

// ----------------------------------------------------------------------------
// launch
// ----------------------------------------------------------------------------
extern "C" void kernel_launch(void* const* d_in, const int* in_sizes, int n_in,
                              void* d_out, int out_size)
{
    const float* x  = (const float*)d_in[0];
    const float* Wm = (const float*)d_in[1];
    const float* bm = (const float*)d_in[2];
    const float* g1 = (const float*)d_in[3];
    const float* b1 = (const float*)d_in[4];
    const float* Wh = (const float*)d_in[5];
    const float* bh = (const float*)d_in[6];
    const float* Wq = (const float*)d_in[7];
    const float* bq = (const float*)d_in[8];
    const float* Wb = (const float*)d_in[9];
    const float* Wo = (const float*)d_in[10];
    const float* bo = (const float*)d_in[11];
    const float* g2 = (const float*)d_in[12];
    const float* b2 = (const float*)d_in[13];
    float* out = (float*)d_out;

    __nv_bfloat16 *xh, *xl, *Wmh, *Wml, *Whh, *Whl, *Wqh, *Wql, *Woh, *Wol, *WbTh, *WbTl;
    __nv_bfloat16 *nh, *nl, *Zh, *Zl, *ZWh, *ZWl, *Amh, *Aml, *vTh, *vTl, *Vh, *Vl;
    float *tmp1, *hb, *U;
    cudaGetSymbolAddress((void**)&xh, g_xh);     cudaGetSymbolAddress((void**)&xl, g_xl);
    cudaGetSymbolAddress((void**)&Wmh, g_Wmh);   cudaGetSymbolAddress((void**)&Wml, g_Wml);
    cudaGetSymbolAddress((void**)&Whh, g_Whh);   cudaGetSymbolAddress((void**)&Whl, g_Whl);
    cudaGetSymbolAddress((void**)&Wqh, g_Wqh);   cudaGetSymbolAddress((void**)&Wql, g_Wql);
    cudaGetSymbolAddress((void**)&Woh, g_Woh);   cudaGetSymbolAddress((void**)&Wol, g_Wol);
    cudaGetSymbolAddress((void**)&WbTh, g_WbTh); cudaGetSymbolAddress((void**)&WbTl, g_WbTl);
    cudaGetSymbolAddress((void**)&nh, g_nh);     cudaGetSymbolAddress((void**)&nl, g_nl);
    cudaGetSymbolAddress((void**)&Zh, g_Zh);     cudaGetSymbolAddress((void**)&Zl, g_Zl);
    cudaGetSymbolAddress((void**)&ZWh, g_ZWh);   cudaGetSymbolAddress((void**)&ZWl, g_ZWl);
    cudaGetSymbolAddress((void**)&Amh, g_Amh);   cudaGetSymbolAddress((void**)&Aml, g_Aml);
    cudaGetSymbolAddress((void**)&vTh, g_vTh);   cudaGetSymbolAddress((void**)&vTl, g_vTl);
    cudaGetSymbolAddress((void**)&Vh, g_Vh);     cudaGetSymbolAddress((void**)&Vl, g_Vl);
    cudaGetSymbolAddress((void**)&tmp1, g_tmp1);
    cudaGetSymbolAddress((void**)&hb, g_hbuf);
    cudaGetSymbolAddress((void**)&U, g_U);

    cudaFuncSetAttribute((const void*)tgemm<EPI_BIAS_ADDX, false>, cudaFuncAttributeMaxDynamicSharedMemorySize, SMEM_BYTES);
    cudaFuncSetAttribute((const void*)tgemm<EPI_BIAS_RELU, false>, cudaFuncAttributeMaxDynamicSharedMemorySize, SMEM_BYTES);
    cudaFuncSetAttribute((const void*)tgemm<EPI_BIAS_RELU, true>,  cudaFuncAttributeMaxDynamicSharedMemorySize, SMEM_BYTES);
    cudaFuncSetAttribute((const void*)tgemm<EPI_NONE, true>,       cudaFuncAttributeMaxDynamicSharedMemorySize, SMEM_BYTES);
    cudaFuncSetAttribute((const void*)tgemm<EPI_RELUSQ, true>,     cudaFuncAttributeMaxDynamicSharedMemorySize, SMEM_BYTES);
    cudaFuncSetAttribute((const void*)tgemm<EPI_GATE, true>,       cudaFuncAttributeMaxDynamicSharedMemorySize, SMEM_BYTES);
    cudaFuncSetAttribute((const void*)tgemm<EPI_BIAS, false>,      cudaFuncAttributeMaxDynamicSharedMemorySize, SMEM_BYTES);

    const float inv_s = 1.0f / (float)Sn;

    // 0) convert inputs/weights to hi/lo bf16
    cvt_split_kernel<<<(BSn * Dn / 4 + 255) / 256, 256>>>(x,  xh,  xl,  BSn * Dn / 4);
    cvt_split_kernel<<<(Dn * Dn / 4 + 255) / 256, 256>>>(Wm, Wmh, Wml, Dn * Dn / 4);
    cvt_split_kernel<<<(2 * HIDn * Dn / 4 + 255) / 256, 256>>>(Wh, Whh, Whl, 2 * HIDn * Dn / 4);
    cvt_split_kernel<<<(QKDn * Dn / 4 + 255) / 256, 256>>>(Wq, Wqh, Wql, QKDn * Dn / 4);
    cvt_split_kernel<<<(Dn * HIDn / 4 + 255) / 256, 256>>>(Wo, Woh, Wol, Dn * HIDn / 4);
    cvt_tr_kernel<<<dim3(QKDn / 32, QKDn / 32, 1), 256>>>(Wb, WbTh, WbTl, QKDn, 0, 0, QKDn);

    // 1) tmp1 = x @ Wm^T + bm + x
    tgemm<EPI_BIAS_ADDX, false><<<dim3(Dn / 128, BSn / 128, 1), 256, SMEM_BYTES>>>(
        xh, xl, Wmh, Wml, bm, x, tmp1, nullptr, nullptr,
        Dn, Dn, Dn, Dn, 0, 0, 0, 0, Dn, 1.0f);

    // 2) nrm = LN(tmp1)  -> hi/lo
    ln_kernel<true><<<BSn, 256>>>(tmp1, g1, b1, nullptr, nullptr, nh, nl);

    // 3) h = relu(nrm @ Wh^T + bh)   fp32 (v + gate source)
    tgemm<EPI_BIAS_RELU, false><<<dim3(2 * HIDn / 128, BSn / 128, 1), 256, SMEM_BYTES>>>(
        nh, nl, Whh, Whl, bh, nullptr, hb, nullptr, nullptr,
        Dn, Dn, Dn, 2 * HIDn, 0, 0, 0, 0, 0, 1.0f);

    // 4) Z = relu(nrm @ Wq^T + bq)   -> hi/lo
    tgemm<EPI_BIAS_RELU, true><<<dim3(QKDn / 128, BSn / 128, 1), 256, SMEM_BYTES>>>(
        nh, nl, Wqh, Wql, bq, nullptr, nullptr, Zh, Zl,
        Dn, Dn, Dn, QKDn, 0, 0, 0, 0, 0, 1.0f);

    // 5) ZW = Z @ Wb  (= Z @ (WbT)^T) -> hi/lo
    tgemm<EPI_NONE, true><<<dim3(QKDn / 128, BSn / 128, 1), 256, SMEM_BYTES>>>(
        Zh, Zl, WbTh, WbTl, nullptr, nullptr, nullptr, ZWh, ZWl,
        QKDn, QKDn, QKDn, QKDn, 0, 0, 0, 0, 0, 1.0f);

    // 6) A = relu((ZW @ Z^T)/S)^2  batched -> hi/lo
    tgemm<EPI_RELUSQ, true><<<dim3(Sn / 128, Sn / 128, Bn), 256, SMEM_BYTES>>>(
        ZWh, ZWl, Zh, Zl, nullptr, nullptr, nullptr, Amh, Aml,
        QKDn, QKDn, QKDn, Sn,
        (long long)Sn * QKDn, (long long)Sn * QKDn, (long long)Sn * Sn, 0, 0, inv_s);

    // 7) vT = transpose(v) per batch -> hi/lo  (v = h[..., :HID])
    cvt_tr_kernel<<<dim3(HIDn / 32, Sn / 32, Bn), 256>>>(
        hb, vTh, vTl, 2 * HIDn, (long long)Sn * 2 * HIDn, (long long)HIDn * Sn, Sn);

    // 8) V = (A @ v) * gate  batched -> hi/lo
    tgemm<EPI_GATE, true><<<dim3(HIDn / 128, Sn / 128, Bn), 256, SMEM_BYTES>>>(
        Amh, Aml, vTh, vTl, nullptr, hb + HIDn, nullptr, Vh, Vl,
        Sn, Sn, Sn, HIDn,
        (long long)Sn * Sn, (long long)HIDn * Sn, (long long)Sn * HIDn,
        (long long)Sn * 2 * HIDn, 2 * HIDn, 1.0f);

    // 9) U = V @ Wo^T + bo  fp32
    tgemm<EPI_BIAS, false><<<dim3(Dn / 128, BSn / 128, 1), 256, SMEM_BYTES>>>(
        Vh, Vl, Woh, Wol, bo, nullptr, U, nullptr, nullptr,
        HIDn, HIDn, HIDn, Dn, 0, 0, 0, 0, 0, 1.0f);

    // 10) out = LN(U) + x
    ln_kernel<false><<<BSn, 256>>>(U, g2, b2, x, out, nullptr, nullptr);
}

// round 4
// speedup vs baseline: 4.2961x; 1.4175x over previous
#include <cuda_runtime.h>
#include <cuda_fp16.h>
#include <cstdint>

// GAU block on GB300 (plain sm_103 target): fp16 hi/lo-split GEMMs on
// mma.sync.m16n8k16 + ldmatrix + cp.async.
// Error-critical small GEMMs: 3-pass (both operands split).
// Big GEMMs: 2-pass (A hi-only, B split).
// B=4, S=2048, D=512, QKD=256, HID=1536

constexpr int Bn = 4, Sn = 2048, Dn = 512, QKDn = 256, HIDn = 1536;
constexpr int BSn = Bn * Sn;                 // 8192
constexpr float LN_EPS = 1e-5f;

// ----------------------------------------------------------------------------
// scratch (device globals)
// ----------------------------------------------------------------------------
static __device__ __align__(16) __half g_xh[BSn * Dn],        g_xl[BSn * Dn];
static __device__ __align__(16) __half g_Wmh[Dn * Dn],        g_Wml[Dn * Dn];
static __device__ __align__(16) __half g_Whh[2 * HIDn * Dn],  g_Whl[2 * HIDn * Dn];
static __device__ __align__(16) __half g_Wqh[QKDn * Dn],      g_Wql[QKDn * Dn];
static __device__ __align__(16) __half g_Woh[Dn * HIDn],      g_Wol[Dn * HIDn];
static __device__ __align__(16) __half g_WbTh[QKDn * QKDn],   g_WbTl[QKDn * QKDn];
static __device__ __align__(16) float  g_tmp1[BSn * Dn];
static __device__ __align__(16) __half g_nh[BSn * Dn],        g_nl[BSn * Dn];
static __device__ __align__(16) float  g_hbuf[BSn * 2 * HIDn];          // [v | gate]
static __device__ __align__(16) __half g_Zh[BSn * QKDn],      g_Zl[BSn * QKDn];
static __device__ __align__(16) __half g_ZWh[BSn * QKDn],     g_ZWl[BSn * QKDn];
static __device__ __align__(16) __half g_Amh[(long long)Bn * Sn * Sn];  // hi only
static __device__ __align__(16) __half g_vTh[(long long)Bn * HIDn * Sn], g_vTl[(long long)Bn * HIDn * Sn];
static __device__ __align__(16) __half g_Vh[BSn * HIDn];                // hi only
static __device__ __align__(16) float  g_U[BSn * Dn];

// ----------------------------------------------------------------------------
// PTX helpers (sm_80-class, valid on plain sm_103)
// ----------------------------------------------------------------------------
__device__ __forceinline__ uint32_t smem_u32(const void* p) {
    uint32_t a;
    asm("{ .reg .u64 t; cvta.to.shared.u64 t, %1; cvt.u32.u64 %0, t; }"
        : "=r"(a) : "l"(p));
    return a;
}
__device__ __forceinline__ void cpa16(uint32_t saddr, const void* gaddr) {
    asm volatile("cp.async.cg.shared.global [%0], [%1], 16;"
                 :: "r"(saddr), "l"(gaddr) : "memory");
}
__device__ __forceinline__ void cpa_commit() {
    asm volatile("cp.async.commit_group;" ::: "memory");
}
template<int N>
__device__ __forceinline__ void cpa_wait() {
    asm volatile("cp.async.wait_group %0;" :: "n"(N) : "memory");
}
__device__ __forceinline__ void ldm_x4(uint32_t a, uint32_t& r0, uint32_t& r1,
                                       uint32_t& r2, uint32_t& r3) {
    asm volatile("ldmatrix.sync.aligned.m8n8.x4.shared.b16 {%0,%1,%2,%3}, [%4];"
                 : "=r"(r0), "=r"(r1), "=r"(r2), "=r"(r3) : "r"(a));
}
__device__ __forceinline__ void mma_f16(float* c, const uint32_t* a, uint32_t b0, uint32_t b1) {
    asm volatile(
        "mma.sync.aligned.m16n8k16.row.col.f32.f16.f16.f32 "
        "{%0,%1,%2,%3}, {%4,%5,%6,%7}, {%8,%9}, {%0,%1,%2,%3};"
        : "+f"(c[0]), "+f"(c[1]), "+f"(c[2]), "+f"(c[3])
        : "r"(a[0]), "r"(a[1]), "r"(a[2]), "r"(a[3]), "r"(b0), "r"(b1));
}
__device__ __forceinline__ void fsplit(float v, __half& h, __half& l) {
    h = __float2half_rn(v);
    l = __float2half_rn(v - __half2float(h));
}
__device__ __forceinline__ uint32_t pack2(__half a, __half b) {
    return (uint32_t)__half_as_ushort(a) | ((uint32_t)__half_as_ushort(b) << 16);
}

// ----------------------------------------------------------------------------
// tensor GEMM: C[m,n] = sum_k A[m,k]*B[n,k]  (both K-major)
// NPASS==3: acc = Ah*Bh + Ah*Bl + Al*Bh   (A split, B split)
// NPASS==2: acc = Ah*Bh + Ah*Bl           (A hi-only, B split)
// CTA 128x128, K-tile 32, 8 warps (4m x 2n), 2-stage cp.async pipeline.
// OUT: 0 = fp32, 1 = fp16 hi only, 2 = fp16 hi+lo
// ----------------------------------------------------------------------------
enum { EPI_NONE = 0, EPI_BIAS = 1, EPI_BIAS_RELU = 2, EPI_BIAS_ADDX = 3,
       EPI_RELUSQ = 4, EPI_GATE = 5 };

constexpr int TROW = 80;                         // padded row bytes (64B data + 16B)
constexpr int TILE_B = 128 * TROW;               // 10240
template<int NPASS> struct StageCfg {
    static constexpr int NT = (NPASS == 3) ? 4 : 3;          // Ah,Bh,Bl[,Al]
    static constexpr int STAGE_B = NT * TILE_B;
    static constexpr int SMEM = 2 * STAGE_B;
};

__device__ __forceinline__ void fill_tile(uint32_t sbase,
                                          const __half* __restrict__ g,
                                          long long row0, int ld, long long k0, int tid)
{
    #pragma unroll
    for (int it = 0; it < 2; ++it) {
        int q = tid + it * 256;               // 0..511
        int r = q >> 2, c = q & 3;
        cpa16(sbase + r * TROW + c * 16,
              g + (row0 + r) * (long long)ld + k0 + c * 8);
    }
}

template<int EPI, int OUT, int NPASS>
__global__ void __launch_bounds__(256, 1)
tgemm(const __half* __restrict__ pAh, const __half* __restrict__ pAl,
      const __half* __restrict__ pBh, const __half* __restrict__ pBl,
      const float* __restrict__ bias, const float* __restrict__ extra,
      float* __restrict__ Cf, __half* __restrict__ Ch, __half* __restrict__ Cl,
      int K, int lda, int ldb, int ldc,
      long long sA, long long sB, long long sC, long long sE,
      int lde, float scale)
{
    constexpr int STAGE_B = StageCfg<NPASS>::STAGE_B;
    extern __shared__ char smem[];
    const int tid = threadIdx.x;
    const int wid = tid >> 5, lane = tid & 31;
    const int z = blockIdx.z;
    pAh += (long long)z * sA;
    if (NPASS == 3) pAl += (long long)z * sA;
    pBh += (long long)z * sB;  pBl += (long long)z * sB;
    const float* Ex = extra ? extra + (long long)z * sE : nullptr;
    const long long coff = (long long)z * sC;
    const long long m0 = (long long)blockIdx.y * 128;
    const long long n0 = (long long)blockIdx.x * 128;
    const uint32_t sb = smem_u32(smem);

    const int wm = (wid >> 1) * 32;      // warp m offset
    const int wn = (wid & 1) * 64;       // warp n offset
    const int rowL = (lane & 7) + ((lane >> 3) & 1) * 8;
    const int cOff = lane >> 4;

    float acc[2][8][4];
    #pragma unroll
    for (int i = 0; i < 2; ++i)
        #pragma unroll
        for (int j = 0; j < 8; ++j)
            #pragma unroll
            for (int t = 0; t < 4; ++t) acc[i][j][t] = 0.0f;

    const int KT = K >> 5;

    auto fill_stage = [&](int stage, long long k0) {
        uint32_t s = sb + stage * STAGE_B;
        fill_tile(s,              pAh, m0, lda, k0, tid);
        fill_tile(s + TILE_B,     pBh, n0, ldb, k0, tid);
        fill_tile(s + 2 * TILE_B, pBl, n0, ldb, k0, tid);
        if (NPASS == 3)
            fill_tile(s + 3 * TILE_B, pAl, m0, lda, k0, tid);
        cpa_commit();
    };

    fill_stage(0, 0);

    for (int kt = 0; kt < KT; ++kt) {
        if (kt + 1 < KT) {
            fill_stage((kt + 1) & 1, (long long)(kt + 1) * 32);
            cpa_wait<1>();
        } else {
            cpa_wait<0>();
        }
        __syncthreads();

        const uint32_t st  = sb + (kt & 1) * STAGE_B;
        const uint32_t aH  = st;
        const uint32_t bH  = st + TILE_B;
        const uint32_t bL  = st + 2 * TILE_B;
        const uint32_t aL  = st + 3 * TILE_B;   // valid only NPASS==3

        #pragma unroll
        for (int kk = 0; kk < 2; ++kk) {
            const int cc = kk * 2 + cOff;
            uint32_t ah[2][4], al[2][4];
            #pragma unroll
            for (int im = 0; im < 2; ++im) {
                uint32_t off = (uint32_t)((wm + im * 16 + rowL) * TROW + cc * 16);
                ldm_x4(aH + off, ah[im][0], ah[im][1], ah[im][2], ah[im][3]);
                if (NPASS == 3)
                    ldm_x4(aL + off, al[im][0], al[im][1], al[im][2], al[im][3]);
            }
            uint32_t bh[4][4], bl[4][4];
            #pragma unroll
            for (int nb = 0; nb < 4; ++nb) {
                uint32_t off = (uint32_t)((wn + nb * 16 + rowL) * TROW + cc * 16);
                ldm_x4(bH + off, bh[nb][0], bh[nb][1], bh[nb][2], bh[nb][3]);
                ldm_x4(bL + off, bl[nb][0], bl[nb][1], bl[nb][2], bl[nb][3]);
            }
            #pragma unroll
            for (int im = 0; im < 2; ++im) {
                #pragma unroll
                for (int j = 0; j < 8; ++j) {
                    const int nb = j >> 1, sel = j & 1;
                    mma_f16(acc[im][j], ah[im], bh[nb][sel], bh[nb][sel + 2]);
                    mma_f16(acc[im][j], ah[im], bl[nb][sel], bl[nb][sel + 2]);
                    if (NPASS == 3)
                        mma_f16(acc[im][j], al[im], bh[nb][sel], bh[nb][sel + 2]);
                }
            }
        }
        __syncthreads();
    }

    // ---- epilogue ----
    const int rql = lane >> 2;
    const int cql = (lane & 3) * 2;

    #pragma unroll
    for (int im = 0; im < 2; ++im) {
        #pragma unroll
        for (int j = 0; j < 8; ++j) {
            #pragma unroll
            for (int half = 0; half < 2; ++half) {
                const long long gm = m0 + wm + im * 16 + rql + half * 8;
                const long long gn = n0 + wn + j * 8 + cql;
                float v0 = acc[im][j][half * 2 + 0];
                float v1 = acc[im][j][half * 2 + 1];

                if (EPI == EPI_BIAS || EPI == EPI_BIAS_RELU || EPI == EPI_BIAS_ADDX) {
                    float2 bv = *reinterpret_cast<const float2*>(&bias[gn]);
                    v0 += bv.x; v1 += bv.y;
                }
                if (EPI == EPI_BIAS_RELU) { v0 = fmaxf(v0, 0.0f); v1 = fmaxf(v1, 0.0f); }
                if (EPI == EPI_BIAS_ADDX || EPI == EPI_GATE) {
                    float2 ev = *reinterpret_cast<const float2*>(&Ex[gm * lde + gn]);
                    if (EPI == EPI_BIAS_ADDX) { v0 += ev.x; v1 += ev.y; }
                    else                      { v0 *= ev.x; v1 *= ev.y; }
                }
                if (EPI == EPI_RELUSQ) {
                    float r0 = fmaxf(v0 * scale, 0.0f), r1 = fmaxf(v1 * scale, 0.0f);
                    v0 = r0 * r0; v1 = r1 * r1;
                }

                const long long oi = coff + gm * ldc + gn;
                if (OUT == 0) {
                    *reinterpret_cast<float2*>(&Cf[oi]) = make_float2(v0, v1);
                } else if (OUT == 1) {
                    *reinterpret_cast<uint32_t*>(&Ch[oi]) =
                        pack2(__float2half_rn(v0), __float2half_rn(v1));
                } else {
                    __half h0, l0, h1, l1;
                    fsplit(v0, h0, l0);
                    fsplit(v1, h1, l1);
                    *reinterpret_cast<uint32_t*>(&Ch[oi]) = pack2(h0, h1);
                    *reinterpret_cast<uint32_t*>(&Cl[oi]) = pack2(l0, l1);
                }
            }
        }
    }
}

// ----------------------------------------------------------------------------
// LayerNorm (D=512)
// ----------------------------------------------------------------------------
__device__ __forceinline__ float block_sum_512(float v, float* red)
{
    #pragma unroll
    for (int o = 16; o > 0; o >>= 1) v += __shfl_down_sync(0xffffffffu, v, o);
    if ((threadIdx.x & 31) == 0) red[threadIdx.x >> 5] = v;
    __syncthreads();
    if (threadIdx.x == 0) {
        float s = 0.0f;
        #pragma unroll
        for (int i = 0; i < 8; i++) s += red[i];
        red[0] = s;
    }
    __syncthreads();
    float r = red[0];
    __syncthreads();
    return r;
}

template<bool SPLIT>
__global__ void __launch_bounds__(256)
ln_kernel(const float* __restrict__ in, const float* __restrict__ g,
          const float* __restrict__ b, const float* __restrict__ resid,
          float* __restrict__ outf, __half* __restrict__ oh, __half* __restrict__ ol)
{
    __shared__ float red[8];
    const long long row = blockIdx.x;
    const int t = threadIdx.x;
    const float* rp = in + row * Dn;

    float v0 = rp[t], v1 = rp[t + 256];
    float mean = block_sum_512(v0 + v1, red) * (1.0f / Dn);
    float d0 = v0 - mean, d1 = v1 - mean;
    float var = block_sum_512(d0 * d0 + d1 * d1, red) * (1.0f / Dn);
    float inv = rsqrtf(var + LN_EPS);

    float o0 = d0 * inv * g[t]       + b[t];
    float o1 = d1 * inv * g[t + 256] + b[t + 256];
    if (SPLIT) {
        __half h0, l0, h1, l1;
        fsplit(o0, h0, l0);
        fsplit(o1, h1, l1);
        oh[row * Dn + t]       = h0;  ol[row * Dn + t]       = l0;
        oh[row * Dn + t + 256] = h1;  ol[row * Dn + t + 256] = l1;
    } else {
        if (resid) {
            o0 += resid[row * Dn + t];
            o1 += resid[row * Dn + t + 256];
        }
        outf[row * Dn + t]       = o0;
        outf[row * Dn + t + 256] = o1;
    }
}

// ----------------------------------------------------------------------------
// fused fp32 -> (hi, lo) fp16 converter for x + 4 weights
// ----------------------------------------------------------------------------
constexpr int Q_X  = BSn * Dn / 4;
constexpr int Q_WM = Dn * Dn / 4;
constexpr int Q_WH = 2 * HIDn * Dn / 4;
constexpr int Q_WQ = QKDn * Dn / 4;
constexpr int Q_WO = Dn * HIDn / 4;
constexpr int Q_TOT = Q_X + Q_WM + Q_WH + Q_WQ + Q_WO;

__global__ void __launch_bounds__(256)
cvt_all_kernel(const float* __restrict__ x,  __half* xh,  __half* xl,
               const float* __restrict__ wm, __half* wmh, __half* wml,
               const float* __restrict__ wh, __half* whh, __half* whl,
               const float* __restrict__ wq, __half* wqh, __half* wql,
               const float* __restrict__ wo, __half* woh, __half* wol)
{
    int i = blockIdx.x * 256 + threadIdx.x;
    if (i >= Q_TOT) return;
    const float* in; __half *oh, *ol;
    if (i < Q_X)                        { in = x;  oh = xh;  ol = xl; }
    else if ((i -= Q_X)  < Q_WM)        { in = wm; oh = wmh; ol = wml; }
    else if ((i -= Q_WM) < Q_WH)        { in = wh; oh = whh; ol = whl; }
    else if ((i -= Q_WH) < Q_WQ)        { in = wq; oh = wqh; ol = wql; }
    else     { i -= Q_WQ;                 in = wo; oh = woh; ol = wol; }

    float4 v = reinterpret_cast<const float4*>(in)[i];
    __half h0, l0, h1, l1, h2, l2, h3, l3;
    fsplit(v.x, h0, l0); fsplit(v.y, h1, l1);
    fsplit(v.z, h2, l2); fsplit(v.w, h3, l3);
    uint2 hp = make_uint2(pack2(h0, h1), pack2(h2, h3));
    uint2 lp = make_uint2(pack2(l0, l1), pack2(l2, l3));
    reinterpret_cast<uint2*>(oh)[i] = hp;
    reinterpret_cast<uint2*>(ol)[i] = lp;
}

// transpose + split: out[c][r] = in[r][c]
__global__ void __launch_bounds__(256)
cvt_tr_kernel(const float* __restrict__ in, __half* __restrict__ oh,
              __half* __restrict__ ol,
              int ldin, long long sIn, long long sOut, int ldout)
{
    __shared__ float tbuf[32][33];
    const int z = blockIdx.z;
    const float* ip = in + (long long)z * sIn;
    const long long obase = (long long)z * sOut;
    const int c0 = blockIdx.x * 32, r0 = blockIdx.y * 32;
    const int tx = threadIdx.x & 31, ty = threadIdx.x >> 5;

    #pragma unroll
    for (int i = 0; i < 4; i++)
        tbuf[ty + i * 8][tx] = ip[(long long)(r0 + ty + i * 8) * ldin + c0 + tx];
    __syncthreads();
    #pragma unroll
    for (int i = 0; i < 4; i++) {
        float v = tbuf[tx][ty + i * 8];
        __half h, l;
        fsplit(v, h, l);
        long long oi = obase + (long long)(c0 + ty + i * 8) * ldout + r0 + tx;
        oh[oi] = h;
        ol[oi] = l;
    }
}

// ----------------------------------------------------------------------------
// launch
// ----------------------------------------------------------------------------
extern "C" void kernel_launch(void* const* d_in, const int* in_sizes, int n_in,
                              void* d_out, int out_size)
{
    const float* x  = (const float*)d_in[0];
    const float* Wm = (const float*)d_in[1];
    const float* bm = (const float*)d_in[2];
    const float* g1 = (const float*)d_in[3];
    const float* b1 = (const float*)d_in[4];
    const float* Wh = (const float*)d_in[5];
    const float* bh = (const float*)d_in[6];
    const float* Wq = (const float*)d_in[7];
    const float* bq = (const float*)d_in[8];
    const float* Wb = (const float*)d_in[9];
    const float* Wo = (const float*)d_in[10];
    const float* bo = (const float*)d_in[11];
    const float* g2 = (const float*)d_in[12];
    const float* b2 = (const float*)d_in[13];
    float* out = (float*)d_out;

    __half *xh, *xl, *Wmh, *Wml, *Whh, *Whl, *Wqh, *Wql, *Woh, *Wol, *WbTh, *WbTl;
    __half *nh, *nl, *Zh, *Zl, *ZWh, *ZWl, *Amh, *vTh, *vTl, *Vh;
    float *tmp1, *hb, *U;
    cudaGetSymbolAddress((void**)&xh, g_xh);     cudaGetSymbolAddress((void**)&xl, g_xl);
    cudaGetSymbolAddress((void**)&Wmh, g_Wmh);   cudaGetSymbolAddress((void**)&Wml, g_Wml);
    cudaGetSymbolAddress((void**)&Whh, g_Whh);   cudaGetSymbolAddress((void**)&Whl, g_Whl);
    cudaGetSymbolAddress((void**)&Wqh, g_Wqh);   cudaGetSymbolAddress((void**)&Wql, g_Wql);
    cudaGetSymbolAddress((void**)&Woh, g_Woh);   cudaGetSymbolAddress((void**)&Wol, g_Wol);
    cudaGetSymbolAddress((void**)&WbTh, g_WbTh); cudaGetSymbolAddress((void**)&WbTl, g_WbTl);
    cudaGetSymbolAddress((void**)&nh, g_nh);     cudaGetSymbolAddress((void**)&nl, g_nl);
    cudaGetSymbolAddress((void**)&Zh, g_Zh);     cudaGetSymbolAddress((void**)&Zl, g_Zl);
    cudaGetSymbolAddress((void**)&ZWh, g_ZWh);   cudaGetSymbolAddress((void**)&ZWl, g_ZWl);
    cudaGetSymbolAddress((void**)&Amh, g_Amh);
    cudaGetSymbolAddress((void**)&vTh, g_vTh);   cudaGetSymbolAddress((void**)&vTl, g_vTl);
    cudaGetSymbolAddress((void**)&Vh, g_Vh);
    cudaGetSymbolAddress((void**)&tmp1, g_tmp1);
    cudaGetSymbolAddress((void**)&hb, g_hbuf);
    cudaGetSymbolAddress((void**)&U, g_U);

    constexpr int SM3 = StageCfg<3>::SMEM;   // 81920
    constexpr int SM2 = StageCfg<2>::SMEM;   // 61440
    cudaFuncSetAttribute((const void*)tgemm<EPI_BIAS_ADDX, 0, 3>, cudaFuncAttributeMaxDynamicSharedMemorySize, SM3);
    cudaFuncSetAttribute((const void*)tgemm<EPI_BIAS_RELU, 0, 2>, cudaFuncAttributeMaxDynamicSharedMemorySize, SM2);
    cudaFuncSetAttribute((const void*)tgemm<EPI_BIAS_RELU, 2, 3>, cudaFuncAttributeMaxDynamicSharedMemorySize, SM3);
    cudaFuncSetAttribute((const void*)tgemm<EPI_NONE, 2, 3>,      cudaFuncAttributeMaxDynamicSharedMemorySize, SM3);
    cudaFuncSetAttribute((const void*)tgemm<EPI_RELUSQ, 1, 3>,    cudaFuncAttributeMaxDynamicSharedMemorySize, SM3);
    cudaFuncSetAttribute((const void*)tgemm<EPI_GATE, 1, 2>,      cudaFuncAttributeMaxDynamicSharedMemorySize, SM2);
    cudaFuncSetAttribute((const void*)tgemm<EPI_BIAS, 0, 2>,      cudaFuncAttributeMaxDynamicSharedMemorySize, SM2);

    const float inv_s = 1.0f / (float)Sn;

    // 0) conversions
    cvt_all_kernel<<<(Q_TOT + 255) / 256, 256>>>(
        x, xh, xl, Wm, Wmh, Wml, Wh, Whh, Whl, Wq, Wqh, Wql, Wo, Woh, Wol);
    cvt_tr_kernel<<<dim3(QKDn / 32, QKDn / 32, 1), 256>>>(Wb, WbTh, WbTl, QKDn, 0, 0, QKDn);

    // 1) tmp1 = x @ Wm^T + bm + x            [3-pass]
    tgemm<EPI_BIAS_ADDX, 0, 3><<<dim3(Dn / 128, BSn / 128, 1), 256, SM3>>>(
        xh, xl, Wmh, Wml, bm, x, tmp1, nullptr, nullptr,
        Dn, Dn, Dn, Dn, 0, 0, 0, 0, Dn, 1.0f);

    // 2) nrm = LN(tmp1) -> hi/lo
    ln_kernel<true><<<BSn, 256>>>(tmp1, g1, b1, nullptr, nullptr, nh, nl);

    // 3) h = relu(nrm @ Wh^T + bh) fp32      [2-pass]
    tgemm<EPI_BIAS_RELU, 0, 2><<<dim3(2 * HIDn / 128, BSn / 128, 1), 256, SM2>>>(
        nh, nullptr, Whh, Whl, bh, nullptr, hb, nullptr, nullptr,
        Dn, Dn, Dn, 2 * HIDn, 0, 0, 0, 0, 0, 1.0f);

    // 4) Z = relu(nrm @ Wq^T + bq) -> hi/lo  [3-pass]
    tgemm<EPI_BIAS_RELU, 2, 3><<<dim3(QKDn / 128, BSn / 128, 1), 256, SM3>>>(
        nh, nl, Wqh, Wql, bq, nullptr, nullptr, Zh, Zl,
        Dn, Dn, Dn, QKDn, 0, 0, 0, 0, 0, 1.0f);

    // 5) ZW = Z @ Wb -> hi/lo                [3-pass]
    tgemm<EPI_NONE, 2, 3><<<dim3(QKDn / 128, BSn / 128, 1), 256, SM3>>>(
        Zh, Zl, WbTh, WbTl, nullptr, nullptr, nullptr, ZWh, ZWl,
        QKDn, QKDn, QKDn, QKDn, 0, 0, 0, 0, 0, 1.0f);

    // 6) A = relu((ZW @ Z^T)/S)^2 -> hi only [3-pass]
    tgemm<EPI_RELUSQ, 1, 3><<<dim3(Sn / 128, Sn / 128, Bn), 256, SM3>>>(
        ZWh, ZWl, Zh, Zl, nullptr, nullptr, nullptr, Amh, nullptr,
        QKDn, QKDn, QKDn, Sn,
        (long long)Sn * QKDn, (long long)Sn * QKDn, (long long)Sn * Sn, 0, 0, inv_s);

    // 7) vT = transpose(v) -> hi/lo
    cvt_tr_kernel<<<dim3(HIDn / 32, Sn / 32, Bn), 256>>>(
        hb, vTh, vTl, 2 * HIDn, (long long)Sn * 2 * HIDn, (long long)HIDn * Sn, Sn);

    // 8) V = (A @ v) * gate -> hi only       [2-pass]
    tgemm<EPI_GATE, 1, 2><<<dim3(HIDn / 128, Sn / 128, Bn), 256, SM2>>>(
        Amh, nullptr, vTh, vTl, nullptr, hb + HIDn, nullptr, Vh, nullptr,
        Sn, Sn, Sn, HIDn,
        (long long)Sn * Sn, (long long)HIDn * Sn, (long long)Sn * HIDn,
        (long long)Sn * 2 * HIDn, 2 * HIDn, 1.0f);

    // 9) U = V @ Wo^T + bo fp32              [2-pass]
    tgemm<EPI_BIAS, 0, 2><<<dim3(Dn / 128, BSn / 128, 1), 256, SM2>>>(
        Vh, nullptr, Woh, Wol, bo, nullptr, U, nullptr, nullptr,
        HIDn, HIDn, HIDn, Dn, 0, 0, 0, 0, 0, 1.0f);

    // 10) out = LN(U) + x
    ln_kernel<false><<<BSn, 256>>>(U, g2, b2, x, out, nullptr, nullptr);
}

// round 5
// speedup vs baseline: 5.8190x; 1.3545x over previous
#include <cuda_runtime.h>
#include <cuda_fp16.h>
#include <cstdint>

// GAU block on GB300 (plain sm_103 target): fp16 hi/lo-split GEMMs on
// mma.sync.m16n8k16 + ldmatrix + cp.async.
// Error-critical small GEMMs (Wm, Z, ZW, QK): 3-pass.
// Big GEMMs (Wh, A*v, Wo): 1-pass fp16 (hi only).
// B=4, S=2048, D=512, QKD=256, HID=1536

constexpr int Bn = 4, Sn = 2048, Dn = 512, QKDn = 256, HIDn = 1536;
constexpr int BSn = Bn * Sn;                 // 8192
constexpr float LN_EPS = 1e-5f;

// ----------------------------------------------------------------------------
// scratch (device globals)
// ----------------------------------------------------------------------------
static __device__ __align__(16) __half g_xh[BSn * Dn],        g_xl[BSn * Dn];
static __device__ __align__(16) __half g_Wmh[Dn * Dn],        g_Wml[Dn * Dn];
static __device__ __align__(16) __half g_Whh[2 * HIDn * Dn];             // hi only
static __device__ __align__(16) __half g_Wqh[QKDn * Dn],      g_Wql[QKDn * Dn];
static __device__ __align__(16) __half g_Woh[Dn * HIDn];                 // hi only
static __device__ __align__(16) __half g_WbTh[QKDn * QKDn],   g_WbTl[QKDn * QKDn];
static __device__ __align__(16) float  g_tmp1[BSn * Dn];
static __device__ __align__(16) __half g_nh[BSn * Dn],        g_nl[BSn * Dn];
static __device__ __align__(16) float  g_hbuf[BSn * 2 * HIDn];          // [v | gate]
static __device__ __align__(16) __half g_Zh[BSn * QKDn],      g_Zl[BSn * QKDn];
static __device__ __align__(16) __half g_ZWh[BSn * QKDn],     g_ZWl[BSn * QKDn];
static __device__ __align__(16) __half g_Amh[(long long)Bn * Sn * Sn];  // hi only
static __device__ __align__(16) __half g_vTh[(long long)Bn * HIDn * Sn];// hi only
static __device__ __align__(16) __half g_Vh[BSn * HIDn];                // hi only
static __device__ __align__(16) float  g_U[BSn * Dn];

// ----------------------------------------------------------------------------
// PTX helpers (sm_80-class, valid on plain sm_103)
// ----------------------------------------------------------------------------
__device__ __forceinline__ uint32_t smem_u32(const void* p) {
    uint32_t a;
    asm("{ .reg .u64 t; cvta.to.shared.u64 t, %1; cvt.u32.u64 %0, t; }"
        : "=r"(a) : "l"(p));
    return a;
}
__device__ __forceinline__ void cpa16(uint32_t saddr, const void* gaddr) {
    asm volatile("cp.async.cg.shared.global [%0], [%1], 16;"
                 :: "r"(saddr), "l"(gaddr) : "memory");
}
__device__ __forceinline__ void cpa_commit() {
    asm volatile("cp.async.commit_group;" ::: "memory");
}
template<int N>
__device__ __forceinline__ void cpa_wait() {
    asm volatile("cp.async.wait_group %0;" :: "n"(N) : "memory");
}
__device__ __forceinline__ void ldm_x4(uint32_t a, uint32_t& r0, uint32_t& r1,
                                       uint32_t& r2, uint32_t& r3) {
    asm volatile("ldmatrix.sync.aligned.m8n8.x4.shared.b16 {%0,%1,%2,%3}, [%4];"
                 : "=r"(r0), "=r"(r1), "=r"(r2), "=r"(r3) : "r"(a));
}
__device__ __forceinline__ void mma_f16(float* c, const uint32_t* a, uint32_t b0, uint32_t b1) {
    asm volatile(
        "mma.sync.aligned.m16n8k16.row.col.f32.f16.f16.f32 "
        "{%0,%1,%2,%3}, {%4,%5,%6,%7}, {%8,%9}, {%0,%1,%2,%3};"
        : "+f"(c[0]), "+f"(c[1]), "+f"(c[2]), "+f"(c[3])
        : "r"(a[0]), "r"(a[1]), "r"(a[2]), "r"(a[3]), "r"(b0), "r"(b1));
}
__device__ __forceinline__ void fsplit(float v, __half& h, __half& l) {
    h = __float2half_rn(v);
    l = __float2half_rn(v - __half2float(h));
}
__device__ __forceinline__ uint32_t pack2(__half a, __half b) {
    return (uint32_t)__half_as_ushort(a) | ((uint32_t)__half_as_ushort(b) << 16);
}

// ----------------------------------------------------------------------------
// tensor GEMM: C[m,n] = sum_k A[m,k]*B[n,k]  (both K-major)
// NPASS==3: acc = Ah*Bh + Ah*Bl + Al*Bh
// NPASS==2: acc = Ah*Bh + Ah*Bl
// NPASS==1: acc = Ah*Bh
// CTA 128x128, K-tile 32, 8 warps (4m x 2n), 2-stage cp.async pipeline.
// OUT: 0 = fp32, 1 = fp16 hi only, 2 = fp16 hi+lo
// ----------------------------------------------------------------------------
enum { EPI_NONE = 0, EPI_BIAS = 1, EPI_BIAS_RELU = 2, EPI_BIAS_ADDX = 3,
       EPI_RELUSQ = 4, EPI_GATE = 5 };

constexpr int TROW = 80;                         // padded row bytes (64B data + 16B)
constexpr int TILE_B = 128 * TROW;               // 10240
template<int NPASS> struct StageCfg {
    static constexpr int NT = (NPASS == 3) ? 4 : (NPASS == 2 ? 3 : 2);
    static constexpr int STAGE_B = NT * TILE_B;
    static constexpr int SMEM = 2 * STAGE_B;
};

__device__ __forceinline__ void fill_tile(uint32_t sbase,
                                          const __half* __restrict__ g,
                                          long long row0, int ld, long long k0, int tid)
{
    #pragma unroll
    for (int it = 0; it < 2; ++it) {
        int q = tid + it * 256;               // 0..511
        int r = q >> 2, c = q & 3;
        cpa16(sbase + r * TROW + c * 16,
              g + (row0 + r) * (long long)ld + k0 + c * 8);
    }
}

template<int EPI, int OUT, int NPASS>
__global__ void __launch_bounds__(256, 1)
tgemm(const __half* __restrict__ pAh, const __half* __restrict__ pAl,
      const __half* __restrict__ pBh, const __half* __restrict__ pBl,
      const float* __restrict__ bias, const float* __restrict__ extra,
      float* __restrict__ Cf, __half* __restrict__ Ch, __half* __restrict__ Cl,
      int K, int lda, int ldb, int ldc,
      long long sA, long long sB, long long sC, long long sE,
      int lde, float scale)
{
    constexpr int STAGE_B = StageCfg<NPASS>::STAGE_B;
    extern __shared__ char smem[];
    const int tid = threadIdx.x;
    const int wid = tid >> 5, lane = tid & 31;
    const int z = blockIdx.z;
    pAh += (long long)z * sA;
    if (NPASS == 3) pAl += (long long)z * sA;
    pBh += (long long)z * sB;
    if (NPASS >= 2) pBl += (long long)z * sB;
    const float* Ex = extra ? extra + (long long)z * sE : nullptr;
    const long long coff = (long long)z * sC;
    const long long m0 = (long long)blockIdx.y * 128;
    const long long n0 = (long long)blockIdx.x * 128;
    const uint32_t sb = smem_u32(smem);

    const int wm = (wid >> 1) * 32;      // warp m offset
    const int wn = (wid & 1) * 64;       // warp n offset
    const int rowL = (lane & 7) + ((lane >> 3) & 1) * 8;
    const int cOff = lane >> 4;

    float acc[2][8][4];
    #pragma unroll
    for (int i = 0; i < 2; ++i)
        #pragma unroll
        for (int j = 0; j < 8; ++j)
            #pragma unroll
            for (int t = 0; t < 4; ++t) acc[i][j][t] = 0.0f;

    const int KT = K >> 5;

    auto fill_stage = [&](int stage, long long k0) {
        uint32_t s = sb + stage * STAGE_B;
        fill_tile(s,              pAh, m0, lda, k0, tid);
        fill_tile(s + TILE_B,     pBh, n0, ldb, k0, tid);
        if (NPASS >= 2)
            fill_tile(s + 2 * TILE_B, pBl, n0, ldb, k0, tid);
        if (NPASS == 3)
            fill_tile(s + 3 * TILE_B, pAl, m0, lda, k0, tid);
        cpa_commit();
    };

    fill_stage(0, 0);

    for (int kt = 0; kt < KT; ++kt) {
        if (kt + 1 < KT) {
            fill_stage((kt + 1) & 1, (long long)(kt + 1) * 32);
            cpa_wait<1>();
        } else {
            cpa_wait<0>();
        }
        __syncthreads();

        const uint32_t st  = sb + (kt & 1) * STAGE_B;
        const uint32_t aH  = st;
        const uint32_t bH  = st + TILE_B;
        const uint32_t bL  = st + 2 * TILE_B;   // valid NPASS>=2
        const uint32_t aL  = st + 3 * TILE_B;   // valid NPASS==3

        #pragma unroll
        for (int kk = 0; kk < 2; ++kk) {
            const int cc = kk * 2 + cOff;
            uint32_t ah[2][4], al[2][4];
            #pragma unroll
            for (int im = 0; im < 2; ++im) {
                uint32_t off = (uint32_t)((wm + im * 16 + rowL) * TROW + cc * 16);
                ldm_x4(aH + off, ah[im][0], ah[im][1], ah[im][2], ah[im][3]);
                if (NPASS == 3)
                    ldm_x4(aL + off, al[im][0], al[im][1], al[im][2], al[im][3]);
            }
            uint32_t bh[4][4], bl[4][4];
            #pragma unroll
            for (int nb = 0; nb < 4; ++nb) {
                uint32_t off = (uint32_t)((wn + nb * 16 + rowL) * TROW + cc * 16);
                ldm_x4(bH + off, bh[nb][0], bh[nb][1], bh[nb][2], bh[nb][3]);
                if (NPASS >= 2)
                    ldm_x4(bL + off, bl[nb][0], bl[nb][1], bl[nb][2], bl[nb][3]);
            }
            #pragma unroll
            for (int im = 0; im < 2; ++im) {
                #pragma unroll
                for (int j = 0; j < 8; ++j) {
                    const int nb = j >> 1, sel = j & 1;
                    mma_f16(acc[im][j], ah[im], bh[nb][sel], bh[nb][sel + 2]);
                    if (NPASS >= 2)
                        mma_f16(acc[im][j], ah[im], bl[nb][sel], bl[nb][sel + 2]);
                    if (NPASS == 3)
                        mma_f16(acc[im][j], al[im], bh[nb][sel], bh[nb][sel + 2]);
                }
            }
        }
        __syncthreads();
    }

    // ---- epilogue ----
    const int rql = lane >> 2;
    const int cql = (lane & 3) * 2;

    #pragma unroll
    for (int im = 0; im < 2; ++im) {
        #pragma unroll
        for (int j = 0; j < 8; ++j) {
            #pragma unroll
            for (int half = 0; half < 2; ++half) {
                const long long gm = m0 + wm + im * 16 + rql + half * 8;
                const long long gn = n0 + wn + j * 8 + cql;
                float v0 = acc[im][j][half * 2 + 0];
                float v1 = acc[im][j][half * 2 + 1];

                if (EPI == EPI_BIAS || EPI == EPI_BIAS_RELU || EPI == EPI_BIAS_ADDX) {
                    float2 bv = *reinterpret_cast<const float2*>(&bias[gn]);
                    v0 += bv.x; v1 += bv.y;
                }
                if (EPI == EPI_BIAS_RELU) { v0 = fmaxf(v0, 0.0f); v1 = fmaxf(v1, 0.0f); }
                if (EPI == EPI_BIAS_ADDX || EPI == EPI_GATE) {
                    float2 ev = *reinterpret_cast<const float2*>(&Ex[gm * lde + gn]);
                    if (EPI == EPI_BIAS_ADDX) { v0 += ev.x; v1 += ev.y; }
                    else                      { v0 *= ev.x; v1 *= ev.y; }
                }
                if (EPI == EPI_RELUSQ) {
                    float r0 = fmaxf(v0 * scale, 0.0f), r1 = fmaxf(v1 * scale, 0.0f);
                    v0 = r0 * r0; v1 = r1 * r1;
                }

                const long long oi = coff + gm * ldc + gn;
                if (OUT == 0) {
                    *reinterpret_cast<float2*>(&Cf[oi]) = make_float2(v0, v1);
                } else if (OUT == 1) {
                    *reinterpret_cast<uint32_t*>(&Ch[oi]) =
                        pack2(__float2half_rn(v0), __float2half_rn(v1));
                } else {
                    __half h0, l0, h1, l1;
                    fsplit(v0, h0, l0);
                    fsplit(v1, h1, l1);
                    *reinterpret_cast<uint32_t*>(&Ch[oi]) = pack2(h0, h1);
                    *reinterpret_cast<uint32_t*>(&Cl[oi]) = pack2(l0, l1);
                }
            }
        }
    }
}

// ----------------------------------------------------------------------------
// LayerNorm (D=512)
// ----------------------------------------------------------------------------
__device__ __forceinline__ float block_sum_512(float v, float* red)
{
    #pragma unroll
    for (int o = 16; o > 0; o >>= 1) v += __shfl_down_sync(0xffffffffu, v, o);
    if ((threadIdx.x & 31) == 0) red[threadIdx.x >> 5] = v;
    __syncthreads();
    if (threadIdx.x == 0) {
        float s = 0.0f;
        #pragma unroll
        for (int i = 0; i < 8; i++) s += red[i];
        red[0] = s;
    }
    __syncthreads();
    float r = red[0];
    __syncthreads();
    return r;
}

template<bool SPLIT>
__global__ void __launch_bounds__(256)
ln_kernel(const float* __restrict__ in, const float* __restrict__ g,
          const float* __restrict__ b, const float* __restrict__ resid,
          float* __restrict__ outf, __half* __restrict__ oh, __half* __restrict__ ol)
{
    __shared__ float red[8];
    const long long row = blockIdx.x;
    const int t = threadIdx.x;
    const float* rp = in + row * Dn;

    float v0 = rp[t], v1 = rp[t + 256];
    float mean = block_sum_512(v0 + v1, red) * (1.0f / Dn);
    float d0 = v0 - mean, d1 = v1 - mean;
    float var = block_sum_512(d0 * d0 + d1 * d1, red) * (1.0f / Dn);
    float inv = rsqrtf(var + LN_EPS);

    float o0 = d0 * inv * g[t]       + b[t];
    float o1 = d1 * inv * g[t + 256] + b[t + 256];
    if (SPLIT) {
        __half h0, l0, h1, l1;
        fsplit(o0, h0, l0);
        fsplit(o1, h1, l1);
        oh[row * Dn + t]       = h0;  ol[row * Dn + t]       = l0;
        oh[row * Dn + t + 256] = h1;  ol[row * Dn + t + 256] = l1;
    } else {
        if (resid) {
            o0 += resid[row * Dn + t];
            o1 += resid[row * Dn + t + 256];
        }
        outf[row * Dn + t]       = o0;
        outf[row * Dn + t + 256] = o1;
    }
}

// ----------------------------------------------------------------------------
// fused fp32 -> (hi[, lo]) fp16 converter for x + 4 weights
// ----------------------------------------------------------------------------
constexpr int Q_X  = BSn * Dn / 4;
constexpr int Q_WM = Dn * Dn / 4;
constexpr int Q_WH = 2 * HIDn * Dn / 4;
constexpr int Q_WQ = QKDn * Dn / 4;
constexpr int Q_WO = Dn * HIDn / 4;
constexpr int Q_TOT = Q_X + Q_WM + Q_WH + Q_WQ + Q_WO;

__global__ void __launch_bounds__(256)
cvt_all_kernel(const float* __restrict__ x,  __half* xh,  __half* xl,
               const float* __restrict__ wm, __half* wmh, __half* wml,
               const float* __restrict__ wh, __half* whh,
               const float* __restrict__ wq, __half* wqh, __half* wql,
               const float* __restrict__ wo, __half* woh)
{
    int i = blockIdx.x * 256 + threadIdx.x;
    if (i >= Q_TOT) return;
    const float* in; __half *oh, *ol;
    if (i < Q_X)                        { in = x;  oh = xh;  ol = xl; }
    else if ((i -= Q_X)  < Q_WM)        { in = wm; oh = wmh; ol = wml; }
    else if ((i -= Q_WM) < Q_WH)        { in = wh; oh = whh; ol = nullptr; }
    else if ((i -= Q_WH) < Q_WQ)        { in = wq; oh = wqh; ol = wql; }
    else     { i -= Q_WQ;                 in = wo; oh = woh; ol = nullptr; }

    float4 v = reinterpret_cast<const float4*>(in)[i];
    __half h0, l0, h1, l1, h2, l2, h3, l3;
    fsplit(v.x, h0, l0); fsplit(v.y, h1, l1);
    fsplit(v.z, h2, l2); fsplit(v.w, h3, l3);
    reinterpret_cast<uint2*>(oh)[i] = make_uint2(pack2(h0, h1), pack2(h2, h3));
    if (ol)
        reinterpret_cast<uint2*>(ol)[i] = make_uint2(pack2(l0, l1), pack2(l2, l3));
}

// transpose + split: out[c][r] = in[r][c]; lo optional
__global__ void __launch_bounds__(256)
cvt_tr_kernel(const float* __restrict__ in, __half* __restrict__ oh,
              __half* __restrict__ ol,
              int ldin, long long sIn, long long sOut, int ldout)
{
    __shared__ float tbuf[32][33];
    const int z = blockIdx.z;
    const float* ip = in + (long long)z * sIn;
    const long long obase = (long long)z * sOut;
    const int c0 = blockIdx.x * 32, r0 = blockIdx.y * 32;
    const int tx = threadIdx.x & 31, ty = threadIdx.x >> 5;

    #pragma unroll
    for (int i = 0; i < 4; i++)
        tbuf[ty + i * 8][tx] = ip[(long long)(r0 + ty + i * 8) * ldin + c0 + tx];
    __syncthreads();
    #pragma unroll
    for (int i = 0; i < 4; i++) {
        float v = tbuf[tx][ty + i * 8];
        long long oi = obase + (long long)(c0 + ty + i * 8) * ldout + r0 + tx;
        if (ol) {
            __half h, l;
            fsplit(v, h, l);
            oh[oi] = h;
            ol[oi] = l;
        } else {
            oh[oi] = __float2half_rn(v);
        }
    }
}

// ----------------------------------------------------------------------------
// launch
// ----------------------------------------------------------------------------
extern "C" void kernel_launch(void* const* d_in, const int* in_sizes, int n_in,
                              void* d_out, int out_size)
{
    const float* x  = (const float*)d_in[0];
    const float* Wm = (const float*)d_in[1];
    const float* bm = (const float*)d_in[2];
    const float* g1 = (const float*)d_in[3];
    const float* b1 = (const float*)d_in[4];
    const float* Wh = (const float*)d_in[5];
    const float* bh = (const float*)d_in[6];
    const float* Wq = (const float*)d_in[7];
    const float* bq = (const float*)d_in[8];
    const float* Wb = (const float*)d_in[9];
    const float* Wo = (const float*)d_in[10];
    const float* bo = (const float*)d_in[11];
    const float* g2 = (const float*)d_in[12];
    const float* b2 = (const float*)d_in[13];
    float* out = (float*)d_out;

    __half *xh, *xl, *Wmh, *Wml, *Whh, *Wqh, *Wql, *Woh, *WbTh, *WbTl;
    __half *nh, *nl, *Zh, *Zl, *ZWh, *ZWl, *Amh, *vTh, *Vh;
    float *tmp1, *hb, *U;
    cudaGetSymbolAddress((void**)&xh, g_xh);     cudaGetSymbolAddress((void**)&xl, g_xl);
    cudaGetSymbolAddress((void**)&Wmh, g_Wmh);   cudaGetSymbolAddress((void**)&Wml, g_Wml);
    cudaGetSymbolAddress((void**)&Whh, g_Whh);
    cudaGetSymbolAddress((void**)&Wqh, g_Wqh);   cudaGetSymbolAddress((void**)&Wql, g_Wql);
    cudaGetSymbolAddress((void**)&Woh, g_Woh);
    cudaGetSymbolAddress((void**)&WbTh, g_WbTh); cudaGetSymbolAddress((void**)&WbTl, g_WbTl);
    cudaGetSymbolAddress((void**)&nh, g_nh);     cudaGetSymbolAddress((void**)&nl, g_nl);
    cudaGetSymbolAddress((void**)&Zh, g_Zh);     cudaGetSymbolAddress((void**)&Zl, g_Zl);
    cudaGetSymbolAddress((void**)&ZWh, g_ZWh);   cudaGetSymbolAddress((void**)&ZWl, g_ZWl);
    cudaGetSymbolAddress((void**)&Amh, g_Amh);
    cudaGetSymbolAddress((void**)&vTh, g_vTh);
    cudaGetSymbolAddress((void**)&Vh, g_Vh);
    cudaGetSymbolAddress((void**)&tmp1, g_tmp1);
    cudaGetSymbolAddress((void**)&hb, g_hbuf);
    cudaGetSymbolAddress((void**)&U, g_U);

    constexpr int SM3 = StageCfg<3>::SMEM;   // 81920
    constexpr int SM1 = StageCfg<1>::SMEM;   // 40960
    cudaFuncSetAttribute((const void*)tgemm<EPI_BIAS_ADDX, 0, 3>, cudaFuncAttributeMaxDynamicSharedMemorySize, SM3);
    cudaFuncSetAttribute((const void*)tgemm<EPI_BIAS_RELU, 0, 1>, cudaFuncAttributeMaxDynamicSharedMemorySize, SM1);
    cudaFuncSetAttribute((const void*)tgemm<EPI_BIAS_RELU, 2, 3>, cudaFuncAttributeMaxDynamicSharedMemorySize, SM3);
    cudaFuncSetAttribute((const void*)tgemm<EPI_NONE, 2, 3>,      cudaFuncAttributeMaxDynamicSharedMemorySize, SM3);
    cudaFuncSetAttribute((const void*)tgemm<EPI_RELUSQ, 1, 3>,    cudaFuncAttributeMaxDynamicSharedMemorySize, SM3);
    cudaFuncSetAttribute((const void*)tgemm<EPI_GATE, 1, 1>,      cudaFuncAttributeMaxDynamicSharedMemorySize, SM1);
    cudaFuncSetAttribute((const void*)tgemm<EPI_BIAS, 0, 1>,      cudaFuncAttributeMaxDynamicSharedMemorySize, SM1);

    const float inv_s = 1.0f / (float)Sn;

    // 0) conversions
    cvt_all_kernel<<<(Q_TOT + 255) / 256, 256>>>(
        x, xh, xl, Wm, Wmh, Wml, Wh, Whh, Wq, Wqh, Wql, Wo, Woh);
    cvt_tr_kernel<<<dim3(QKDn / 32, QKDn / 32, 1), 256>>>(Wb, WbTh, WbTl, QKDn, 0, 0, QKDn);

    // 1) tmp1 = x @ Wm^T + bm + x            [3-pass]
    tgemm<EPI_BIAS_ADDX, 0, 3><<<dim3(Dn / 128, BSn / 128, 1), 256, SM3>>>(
        xh, xl, Wmh, Wml, bm, x, tmp1, nullptr, nullptr,
        Dn, Dn, Dn, Dn, 0, 0, 0, 0, Dn, 1.0f);

    // 2) nrm = LN(tmp1) -> hi/lo
    ln_kernel<true><<<BSn, 256>>>(tmp1, g1, b1, nullptr, nullptr, nh, nl);

    // 3) h = relu(nrm @ Wh^T + bh) fp32      [1-pass]
    tgemm<EPI_BIAS_RELU, 0, 1><<<dim3(2 * HIDn / 128, BSn / 128, 1), 256, SM1>>>(
        nh, nullptr, Whh, nullptr, bh, nullptr, hb, nullptr, nullptr,
        Dn, Dn, Dn, 2 * HIDn, 0, 0, 0, 0, 0, 1.0f);

    // 4) Z = relu(nrm @ Wq^T + bq) -> hi/lo  [3-pass]
    tgemm<EPI_BIAS_RELU, 2, 3><<<dim3(QKDn / 128, BSn / 128, 1), 256, SM3>>>(
        nh, nl, Wqh, Wql, bq, nullptr, nullptr, Zh, Zl,
        Dn, Dn, Dn, QKDn, 0, 0, 0, 0, 0, 1.0f);

    // 5) ZW = Z @ Wb -> hi/lo                [3-pass]
    tgemm<EPI_NONE, 2, 3><<<dim3(QKDn / 128, BSn / 128, 1), 256, SM3>>>(
        Zh, Zl, WbTh, WbTl, nullptr, nullptr, nullptr, ZWh, ZWl,
        QKDn, QKDn, QKDn, QKDn, 0, 0, 0, 0, 0, 1.0f);

    // 6) A = relu((ZW @ Z^T)/S)^2 -> hi only [3-pass]
    tgemm<EPI_RELUSQ, 1, 3><<<dim3(Sn / 128, Sn / 128, Bn), 256, SM3>>>(
        ZWh, ZWl, Zh, Zl, nullptr, nullptr, nullptr, Amh, nullptr,
        QKDn, QKDn, QKDn, Sn,
        (long long)Sn * QKDn, (long long)Sn * QKDn, (long long)Sn * Sn, 0, 0, inv_s);

    // 7) vT = transpose(v) -> hi only
    cvt_tr_kernel<<<dim3(HIDn / 32, Sn / 32, Bn), 256>>>(
        hb, vTh, nullptr, 2 * HIDn, (long long)Sn * 2 * HIDn, (long long)HIDn * Sn, Sn);

    // 8) V = (A @ v) * gate -> hi only       [1-pass]
    tgemm<EPI_GATE, 1, 1><<<dim3(HIDn / 128, Sn / 128, Bn), 256, SM1>>>(
        Amh, nullptr, vTh, nullptr, nullptr, hb + HIDn, nullptr, Vh, nullptr,
        Sn, Sn, Sn, HIDn,
        (long long)Sn * Sn, (long long)HIDn * Sn, (long long)Sn * HIDn,
        (long long)Sn * 2 * HIDn, 2 * HIDn, 1.0f);

    // 9) U = V @ Wo^T + bo fp32              [1-pass]
    tgemm<EPI_BIAS, 0, 1><<<dim3(Dn / 128, BSn / 128, 1), 256, SM1>>>(
        Vh, nullptr, Woh, nullptr, bo, nullptr, U, nullptr, nullptr,
        HIDn, HIDn, HIDn, Dn, 0, 0, 0, 0, 0, 1.0f);

    // 10) out = LN(U) + x
    ln_kernel<false><<<BSn, 256>>>(U, g2, b2, x, out, nullptr, nullptr);
}

// round 6
// speedup vs baseline: 6.2501x; 1.0741x over previous
#include <cuda_runtime.h>
#include <cuda_fp16.h>
#include <cstdint>

// GAU block on GB300 (plain sm_103 target): fp16 hi/lo-split GEMMs on
// mma.sync.m16n8k16 + ldmatrix + cp.async.
// R6: 4 warps/CTA, 64x64 warp tiles (2x2 grid) -> 1.5x less LDSM traffic/MAC.
// Error-critical small GEMMs (Wm, Z, ZW, QK): 3-pass.
// Big GEMMs (Wh, A*v, Wo): 1-pass fp16 (hi only).
// B=4, S=2048, D=512, QKD=256, HID=1536

constexpr int Bn = 4, Sn = 2048, Dn = 512, QKDn = 256, HIDn = 1536;
constexpr int BSn = Bn * Sn;                 // 8192
constexpr float LN_EPS = 1e-5f;

// ----------------------------------------------------------------------------
// scratch (device globals)
// ----------------------------------------------------------------------------
static __device__ __align__(16) __half g_xh[BSn * Dn],        g_xl[BSn * Dn];
static __device__ __align__(16) __half g_Wmh[Dn * Dn],        g_Wml[Dn * Dn];
static __device__ __align__(16) __half g_Whh[2 * HIDn * Dn];             // hi only
static __device__ __align__(16) __half g_Wqh[QKDn * Dn],      g_Wql[QKDn * Dn];
static __device__ __align__(16) __half g_Woh[Dn * HIDn];                 // hi only
static __device__ __align__(16) __half g_WbTh[QKDn * QKDn],   g_WbTl[QKDn * QKDn];
static __device__ __align__(16) float  g_tmp1[BSn * Dn];
static __device__ __align__(16) __half g_nh[BSn * Dn],        g_nl[BSn * Dn];
static __device__ __align__(16) float  g_hbuf[BSn * 2 * HIDn];          // [v | gate]
static __device__ __align__(16) __half g_Zh[BSn * QKDn],      g_Zl[BSn * QKDn];
static __device__ __align__(16) __half g_ZWh[BSn * QKDn],     g_ZWl[BSn * QKDn];
static __device__ __align__(16) __half g_Amh[(long long)Bn * Sn * Sn];  // hi only
static __device__ __align__(16) __half g_vTh[(long long)Bn * HIDn * Sn];// hi only
static __device__ __align__(16) __half g_Vh[BSn * HIDn];                // hi only
static __device__ __align__(16) float  g_U[BSn * Dn];

// ----------------------------------------------------------------------------
// PTX helpers (sm_80-class, valid on plain sm_103)
// ----------------------------------------------------------------------------
__device__ __forceinline__ uint32_t smem_u32(const void* p) {
    uint32_t a;
    asm("{ .reg .u64 t; cvta.to.shared.u64 t, %1; cvt.u32.u64 %0, t; }"
        : "=r"(a) : "l"(p));
    return a;
}
__device__ __forceinline__ void cpa16(uint32_t saddr, const void* gaddr) {
    asm volatile("cp.async.cg.shared.global [%0], [%1], 16;"
                 :: "r"(saddr), "l"(gaddr) : "memory");
}
__device__ __forceinline__ void cpa_commit() {
    asm volatile("cp.async.commit_group;" ::: "memory");
}
template<int N>
__device__ __forceinline__ void cpa_wait() {
    asm volatile("cp.async.wait_group %0;" :: "n"(N) : "memory");
}
__device__ __forceinline__ void ldm_x4(uint32_t a, uint32_t& r0, uint32_t& r1,
                                       uint32_t& r2, uint32_t& r3) {
    asm volatile("ldmatrix.sync.aligned.m8n8.x4.shared.b16 {%0,%1,%2,%3}, [%4];"
                 : "=r"(r0), "=r"(r1), "=r"(r2), "=r"(r3) : "r"(a));
}
__device__ __forceinline__ void mma_f16(float* c, const uint32_t* a, uint32_t b0, uint32_t b1) {
    asm volatile(
        "mma.sync.aligned.m16n8k16.row.col.f32.f16.f16.f32 "
        "{%0,%1,%2,%3}, {%4,%5,%6,%7}, {%8,%9}, {%0,%1,%2,%3};"
        : "+f"(c[0]), "+f"(c[1]), "+f"(c[2]), "+f"(c[3])
        : "r"(a[0]), "r"(a[1]), "r"(a[2]), "r"(a[3]), "r"(b0), "r"(b1));
}
__device__ __forceinline__ void fsplit(float v, __half& h, __half& l) {
    h = __float2half_rn(v);
    l = __float2half_rn(v - __half2float(h));
}
__device__ __forceinline__ uint32_t pack2(__half a, __half b) {
    return (uint32_t)__half_as_ushort(a) | ((uint32_t)__half_as_ushort(b) << 16);
}

// ----------------------------------------------------------------------------
// tensor GEMM: C[m,n] = sum_k A[m,k]*B[n,k]  (both K-major)
// NPASS==3: acc = Ah*Bh + Ah*Bl + Al*Bh
// NPASS==1: acc = Ah*Bh
// CTA 128x128, K-tile 32, 4 warps (2m x 2n, 64x64 warp tiles),
// 2-stage cp.async pipeline. OUT: 0 = fp32, 1 = fp16 hi only, 2 = fp16 hi+lo
// ----------------------------------------------------------------------------
enum { EPI_NONE = 0, EPI_BIAS = 1, EPI_BIAS_RELU = 2, EPI_BIAS_ADDX = 3,
       EPI_RELUSQ = 4, EPI_GATE = 5 };

constexpr int TROW = 80;                         // padded row bytes (64B data + 16B)
constexpr int TILE_B = 128 * TROW;               // 10240
template<int NPASS> struct StageCfg {
    static constexpr int NT = (NPASS == 3) ? 4 : (NPASS == 2 ? 3 : 2);
    static constexpr int STAGE_B = NT * TILE_B;
    static constexpr int SMEM = 2 * STAGE_B;
};

__device__ __forceinline__ void fill_tile(uint32_t sbase,
                                          const __half* __restrict__ g,
                                          long long row0, int ld, long long k0, int tid)
{
    #pragma unroll
    for (int it = 0; it < 4; ++it) {
        int q = tid + it * 128;               // 0..511 chunks of 16B
        int r = q >> 2, c = q & 3;
        cpa16(sbase + r * TROW + c * 16,
              g + (row0 + r) * (long long)ld + k0 + c * 8);
    }
}

template<int EPI, int OUT, int NPASS>
__global__ void __launch_bounds__(128, 2)
tgemm(const __half* __restrict__ pAh, const __half* __restrict__ pAl,
      const __half* __restrict__ pBh, const __half* __restrict__ pBl,
      const float* __restrict__ bias, const float* __restrict__ extra,
      float* __restrict__ Cf, __half* __restrict__ Ch, __half* __restrict__ Cl,
      int K, int lda, int ldb, int ldc,
      long long sA, long long sB, long long sC, long long sE,
      int lde, float scale)
{
    constexpr int STAGE_B = StageCfg<NPASS>::STAGE_B;
    extern __shared__ char smem[];
    const int tid = threadIdx.x;
    const int wid = tid >> 5, lane = tid & 31;
    const int z = blockIdx.z;
    pAh += (long long)z * sA;
    if (NPASS == 3) pAl += (long long)z * sA;
    pBh += (long long)z * sB;
    if (NPASS >= 2) pBl += (long long)z * sB;
    const float* Ex = extra ? extra + (long long)z * sE : nullptr;
    const long long coff = (long long)z * sC;
    const long long m0 = (long long)blockIdx.y * 128;
    const long long n0 = (long long)blockIdx.x * 128;
    const uint32_t sb = smem_u32(smem);

    const int wm = (wid >> 1) * 64;      // warp m offset (0, 64)
    const int wn = (wid & 1) * 64;       // warp n offset (0, 64)
    const int rowL = (lane & 7) + ((lane >> 3) & 1) * 8;
    const int cOff = lane >> 4;

    float acc[4][8][4];
    #pragma unroll
    for (int i = 0; i < 4; ++i)
        #pragma unroll
        for (int j = 0; j < 8; ++j)
            #pragma unroll
            for (int t = 0; t < 4; ++t) acc[i][j][t] = 0.0f;

    const int KT = K >> 5;

    auto fill_stage = [&](int stage, long long k0) {
        uint32_t s = sb + stage * STAGE_B;
        fill_tile(s,              pAh, m0, lda, k0, tid);
        fill_tile(s + TILE_B,     pBh, n0, ldb, k0, tid);
        if (NPASS >= 2)
            fill_tile(s + 2 * TILE_B, pBl, n0, ldb, k0, tid);
        if (NPASS == 3)
            fill_tile(s + 3 * TILE_B, pAl, m0, lda, k0, tid);
        cpa_commit();
    };

    fill_stage(0, 0);

    for (int kt = 0; kt < KT; ++kt) {
        if (kt + 1 < KT) {
            fill_stage((kt + 1) & 1, (long long)(kt + 1) * 32);
            cpa_wait<1>();
        } else {
            cpa_wait<0>();
        }
        __syncthreads();

        const uint32_t st  = sb + (kt & 1) * STAGE_B;
        const uint32_t aH  = st;
        const uint32_t bH  = st + TILE_B;
        const uint32_t bL  = st + 2 * TILE_B;   // valid NPASS>=2
        const uint32_t aL  = st + 3 * TILE_B;   // valid NPASS==3

        #pragma unroll
        for (int kk = 0; kk < 2; ++kk) {
            const int cc = kk * 2 + cOff;
            uint32_t ah[4][4], al[4][4];
            #pragma unroll
            for (int im = 0; im < 4; ++im) {
                uint32_t off = (uint32_t)((wm + im * 16 + rowL) * TROW + cc * 16);
                ldm_x4(aH + off, ah[im][0], ah[im][1], ah[im][2], ah[im][3]);
                if (NPASS == 3)
                    ldm_x4(aL + off, al[im][0], al[im][1], al[im][2], al[im][3]);
            }
            uint32_t bh[4][4], bl[4][4];
            #pragma unroll
            for (int nb = 0; nb < 4; ++nb) {
                uint32_t off = (uint32_t)((wn + nb * 16 + rowL) * TROW + cc * 16);
                ldm_x4(bH + off, bh[nb][0], bh[nb][1], bh[nb][2], bh[nb][3]);
                if (NPASS >= 2)
                    ldm_x4(bL + off, bl[nb][0], bl[nb][1], bl[nb][2], bl[nb][3]);
            }
            #pragma unroll
            for (int im = 0; im < 4; ++im) {
                #pragma unroll
                for (int j = 0; j < 8; ++j) {
                    const int nb = j >> 1, sel = j & 1;
                    mma_f16(acc[im][j], ah[im], bh[nb][sel], bh[nb][sel + 2]);
                    if (NPASS >= 2)
                        mma_f16(acc[im][j], ah[im], bl[nb][sel], bl[nb][sel + 2]);
                    if (NPASS == 3)
                        mma_f16(acc[im][j], al[im], bh[nb][sel], bh[nb][sel + 2]);
                }
            }
        }
        __syncthreads();
    }

    // ---- epilogue ----
    const int rql = lane >> 2;
    const int cql = (lane & 3) * 2;

    #pragma unroll
    for (int im = 0; im < 4; ++im) {
        #pragma unroll
        for (int j = 0; j < 8; ++j) {
            #pragma unroll
            for (int half = 0; half < 2; ++half) {
                const long long gm = m0 + wm + im * 16 + rql + half * 8;
                const long long gn = n0 + wn + j * 8 + cql;
                float v0 = acc[im][j][half * 2 + 0];
                float v1 = acc[im][j][half * 2 + 1];

                if (EPI == EPI_BIAS || EPI == EPI_BIAS_RELU || EPI == EPI_BIAS_ADDX) {
                    float2 bv = *reinterpret_cast<const float2*>(&bias[gn]);
                    v0 += bv.x; v1 += bv.y;
                }
                if (EPI == EPI_BIAS_RELU) { v0 = fmaxf(v0, 0.0f); v1 = fmaxf(v1, 0.0f); }
                if (EPI == EPI_BIAS_ADDX || EPI == EPI_GATE) {
                    float2 ev = *reinterpret_cast<const float2*>(&Ex[gm * lde + gn]);
                    if (EPI == EPI_BIAS_ADDX) { v0 += ev.x; v1 += ev.y; }
                    else                      { v0 *= ev.x; v1 *= ev.y; }
                }
                if (EPI == EPI_RELUSQ) {
                    float r0 = fmaxf(v0 * scale, 0.0f), r1 = fmaxf(v1 * scale, 0.0f);
                    v0 = r0 * r0; v1 = r1 * r1;
                }

                const long long oi = coff + gm * ldc + gn;
                if (OUT == 0) {
                    *reinterpret_cast<float2*>(&Cf[oi]) = make_float2(v0, v1);
                } else if (OUT == 1) {
                    *reinterpret_cast<uint32_t*>(&Ch[oi]) =
                        pack2(__float2half_rn(v0), __float2half_rn(v1));
                } else {
                    __half h0, l0, h1, l1;
                    fsplit(v0, h0, l0);
                    fsplit(v1, h1, l1);
                    *reinterpret_cast<uint32_t*>(&Ch[oi]) = pack2(h0, h1);
                    *reinterpret_cast<uint32_t*>(&Cl[oi]) = pack2(l0, l1);
                }
            }
        }
    }
}

// ----------------------------------------------------------------------------
// LayerNorm (D=512)
// ----------------------------------------------------------------------------
__device__ __forceinline__ float block_sum_512(float v, float* red)
{
    #pragma unroll
    for (int o = 16; o > 0; o >>= 1) v += __shfl_down_sync(0xffffffffu, v, o);
    if ((threadIdx.x & 31) == 0) red[threadIdx.x >> 5] = v;
    __syncthreads();
    if (threadIdx.x == 0) {
        float s = 0.0f;
        #pragma unroll
        for (int i = 0; i < 8; i++) s += red[i];
        red[0] = s;
    }
    __syncthreads();
    float r = red[0];
    __syncthreads();
    return r;
}

template<bool SPLIT>
__global__ void __launch_bounds__(256)
ln_kernel(const float* __restrict__ in, const float* __restrict__ g,
          const float* __restrict__ b, const float* __restrict__ resid,
          float* __restrict__ outf, __half* __restrict__ oh, __half* __restrict__ ol)
{
    __shared__ float red[8];
    const long long row = blockIdx.x;
    const int t = threadIdx.x;
    const float* rp = in + row * Dn;

    float v0 = rp[t], v1 = rp[t + 256];
    float mean = block_sum_512(v0 + v1, red) * (1.0f / Dn);
    float d0 = v0 - mean, d1 = v1 - mean;
    float var = block_sum_512(d0 * d0 + d1 * d1, red) * (1.0f / Dn);
    float inv = rsqrtf(var + LN_EPS);

    float o0 = d0 * inv * g[t]       + b[t];
    float o1 = d1 * inv * g[t + 256] + b[t + 256];
    if (SPLIT) {
        __half h0, l0, h1, l1;
        fsplit(o0, h0, l0);
        fsplit(o1, h1, l1);
        oh[row * Dn + t]       = h0;  ol[row * Dn + t]       = l0;
        oh[row * Dn + t + 256] = h1;  ol[row * Dn + t + 256] = l1;
    } else {
        if (resid) {
            o0 += resid[row * Dn + t];
            o1 += resid[row * Dn + t + 256];
        }
        outf[row * Dn + t]       = o0;
        outf[row * Dn + t + 256] = o1;
    }
}

// ----------------------------------------------------------------------------
// fused fp32 -> (hi[, lo]) fp16 converter for x + 4 weights
// ----------------------------------------------------------------------------
constexpr int Q_X  = BSn * Dn / 4;
constexpr int Q_WM = Dn * Dn / 4;
constexpr int Q_WH = 2 * HIDn * Dn / 4;
constexpr int Q_WQ = QKDn * Dn / 4;
constexpr int Q_WO = Dn * HIDn / 4;
constexpr int Q_TOT = Q_X + Q_WM + Q_WH + Q_WQ + Q_WO;

__global__ void __launch_bounds__(256)
cvt_all_kernel(const float* __restrict__ x,  __half* xh,  __half* xl,
               const float* __restrict__ wm, __half* wmh, __half* wml,
               const float* __restrict__ wh, __half* whh,
               const float* __restrict__ wq, __half* wqh, __half* wql,
               const float* __restrict__ wo, __half* woh)
{
    int i = blockIdx.x * 256 + threadIdx.x;
    if (i >= Q_TOT) return;
    const float* in; __half *oh, *ol;
    if (i < Q_X)                        { in = x;  oh = xh;  ol = xl; }
    else if ((i -= Q_X)  < Q_WM)        { in = wm; oh = wmh; ol = wml; }
    else if ((i -= Q_WM) < Q_WH)        { in = wh; oh = whh; ol = nullptr; }
    else if ((i -= Q_WH) < Q_WQ)        { in = wq; oh = wqh; ol = wql; }
    else     { i -= Q_WQ;                 in = wo; oh = woh; ol = nullptr; }

    float4 v = reinterpret_cast<const float4*>(in)[i];
    __half h0, l0, h1, l1, h2, l2, h3, l3;
    fsplit(v.x, h0, l0); fsplit(v.y, h1, l1);
    fsplit(v.z, h2, l2); fsplit(v.w, h3, l3);
    reinterpret_cast<uint2*>(oh)[i] = make_uint2(pack2(h0, h1), pack2(h2, h3));
    if (ol)
        reinterpret_cast<uint2*>(ol)[i] = make_uint2(pack2(l0, l1), pack2(l2, l3));
}

// transpose + split: out[c][r] = in[r][c]; lo optional
__global__ void __launch_bounds__(256)
cvt_tr_kernel(const float* __restrict__ in, __half* __restrict__ oh,
              __half* __restrict__ ol,
              int ldin, long long sIn, long long sOut, int ldout)
{
    __shared__ float tbuf[32][33];
    const int z = blockIdx.z;
    const float* ip = in + (long long)z * sIn;
    const long long obase = (long long)z * sOut;
    const int c0 = blockIdx.x * 32, r0 = blockIdx.y * 32;
    const int tx = threadIdx.x & 31, ty = threadIdx.x >> 5;

    #pragma unroll
    for (int i = 0; i < 4; i++)
        tbuf[ty + i * 8][tx] = ip[(long long)(r0 + ty + i * 8) * ldin + c0 + tx];
    __syncthreads();
    #pragma unroll
    for (int i = 0; i < 4; i++) {
        float v = tbuf[tx][ty + i * 8];
        long long oi = obase + (long long)(c0 + ty + i * 8) * ldout + r0 + tx;
        if (ol) {
            __half h, l;
            fsplit(v, h, l);
            oh[oi] = h;
            ol[oi] = l;
        } else {
            oh[oi] = __float2half_rn(v);
        }
    }
}

// ----------------------------------------------------------------------------
// launch
// ----------------------------------------------------------------------------
extern "C" void kernel_launch(void* const* d_in, const int* in_sizes, int n_in,
                              void* d_out, int out_size)
{
    const float* x  = (const float*)d_in[0];
    const float* Wm = (const float*)d_in[1];
    const float* bm = (const float*)d_in[2];
    const float* g1 = (const float*)d_in[3];
    const float* b1 = (const float*)d_in[4];
    const float* Wh = (const float*)d_in[5];
    const float* bh = (const float*)d_in[6];
    const float* Wq = (const float*)d_in[7];
    const float* bq = (const float*)d_in[8];
    const float* Wb = (const float*)d_in[9];
    const float* Wo = (const float*)d_in[10];
    const float* bo = (const float*)d_in[11];
    const float* g2 = (const float*)d_in[12];
    const float* b2 = (const float*)d_in[13];
    float* out = (float*)d_out;

    __half *xh, *xl, *Wmh, *Wml, *Whh, *Wqh, *Wql, *Woh, *WbTh, *WbTl;
    __half *nh, *nl, *Zh, *Zl, *ZWh, *ZWl, *Amh, *vTh, *Vh;
    float *tmp1, *hb, *U;
    cudaGetSymbolAddress((void**)&xh, g_xh);     cudaGetSymbolAddress((void**)&xl, g_xl);
    cudaGetSymbolAddress((void**)&Wmh, g_Wmh);   cudaGetSymbolAddress((void**)&Wml, g_Wml);
    cudaGetSymbolAddress((void**)&Whh, g_Whh);
    cudaGetSymbolAddress((void**)&Wqh, g_Wqh);   cudaGetSymbolAddress((void**)&Wql, g_Wql);
    cudaGetSymbolAddress((void**)&Woh, g_Woh);
    cudaGetSymbolAddress((void**)&WbTh, g_WbTh); cudaGetSymbolAddress((void**)&WbTl, g_WbTl);
    cudaGetSymbolAddress((void**)&nh, g_nh);     cudaGetSymbolAddress((void**)&nl, g_nl);
    cudaGetSymbolAddress((void**)&Zh, g_Zh);     cudaGetSymbolAddress((void**)&Zl, g_Zl);
    cudaGetSymbolAddress((void**)&ZWh, g_ZWh);   cudaGetSymbolAddress((void**)&ZWl, g_ZWl);
    cudaGetSymbolAddress((void**)&Amh, g_Amh);
    cudaGetSymbolAddress((void**)&vTh, g_vTh);
    cudaGetSymbolAddress((void**)&Vh, g_Vh);
    cudaGetSymbolAddress((void**)&tmp1, g_tmp1);
    cudaGetSymbolAddress((void**)&hb, g_hbuf);
    cudaGetSymbolAddress((void**)&U, g_U);

    constexpr int SM3 = StageCfg<3>::SMEM;   // 81920
    constexpr int SM1 = StageCfg<1>::SMEM;   // 40960
    cudaFuncSetAttribute((const void*)tgemm<EPI_BIAS_ADDX, 0, 3>, cudaFuncAttributeMaxDynamicSharedMemorySize, SM3);
    cudaFuncSetAttribute((const void*)tgemm<EPI_BIAS_RELU, 0, 1>, cudaFuncAttributeMaxDynamicSharedMemorySize, SM1);
    cudaFuncSetAttribute((const void*)tgemm<EPI_BIAS_RELU, 2, 3>, cudaFuncAttributeMaxDynamicSharedMemorySize, SM3);
    cudaFuncSetAttribute((const void*)tgemm<EPI_NONE, 2, 3>,      cudaFuncAttributeMaxDynamicSharedMemorySize, SM3);
    cudaFuncSetAttribute((const void*)tgemm<EPI_RELUSQ, 1, 3>,    cudaFuncAttributeMaxDynamicSharedMemorySize, SM3);
    cudaFuncSetAttribute((const void*)tgemm<EPI_GATE, 1, 1>,      cudaFuncAttributeMaxDynamicSharedMemorySize, SM1);
    cudaFuncSetAttribute((const void*)tgemm<EPI_BIAS, 0, 1>,      cudaFuncAttributeMaxDynamicSharedMemorySize, SM1);

    const float inv_s = 1.0f / (float)Sn;

    // 0) conversions
    cvt_all_kernel<<<(Q_TOT + 255) / 256, 256>>>(
        x, xh, xl, Wm, Wmh, Wml, Wh, Whh, Wq, Wqh, Wql, Wo, Woh);
    cvt_tr_kernel<<<dim3(QKDn / 32, QKDn / 32, 1), 256>>>(Wb, WbTh, WbTl, QKDn, 0, 0, QKDn);

    // 1) tmp1 = x @ Wm^T + bm + x            [3-pass]
    tgemm<EPI_BIAS_ADDX, 0, 3><<<dim3(Dn / 128, BSn / 128, 1), 128, SM3>>>(
        xh, xl, Wmh, Wml, bm, x, tmp1, nullptr, nullptr,
        Dn, Dn, Dn, Dn, 0, 0, 0, 0, Dn, 1.0f);

    // 2) nrm = LN(tmp1) -> hi/lo
    ln_kernel<true><<<BSn, 256>>>(tmp1, g1, b1, nullptr, nullptr, nh, nl);

    // 3) h = relu(nrm @ Wh^T + bh) fp32      [1-pass]
    tgemm<EPI_BIAS_RELU, 0, 1><<<dim3(2 * HIDn / 128, BSn / 128, 1), 128, SM1>>>(
        nh, nullptr, Whh, nullptr, bh, nullptr, hb, nullptr, nullptr,
        Dn, Dn, Dn, 2 * HIDn, 0, 0, 0, 0, 0, 1.0f);

    // 4) Z = relu(nrm @ Wq^T + bq) -> hi/lo  [3-pass]
    tgemm<EPI_BIAS_RELU, 2, 3><<<dim3(QKDn / 128, BSn / 128, 1), 128, SM3>>>(
        nh, nl, Wqh, Wql, bq, nullptr, nullptr, Zh, Zl,
        Dn, Dn, Dn, QKDn, 0, 0, 0, 0, 0, 1.0f);

    // 5) ZW = Z @ Wb -> hi/lo                [3-pass]
    tgemm<EPI_NONE, 2, 3><<<dim3(QKDn / 128, BSn / 128, 1), 128, SM3>>>(
        Zh, Zl, WbTh, WbTl, nullptr, nullptr, nullptr, ZWh, ZWl,
        QKDn, QKDn, QKDn, QKDn, 0, 0, 0, 0, 0, 1.0f);

    // 6) A = relu((ZW @ Z^T)/S)^2 -> hi only [3-pass]
    tgemm<EPI_RELUSQ, 1, 3><<<dim3(Sn / 128, Sn / 128, Bn), 128, SM3>>>(
        ZWh, ZWl, Zh, Zl, nullptr, nullptr, nullptr, Amh, nullptr,
        QKDn, QKDn, QKDn, Sn,
        (long long)Sn * QKDn, (long long)Sn * QKDn, (long long)Sn * Sn, 0, 0, inv_s);

    // 7) vT = transpose(v) -> hi only
    cvt_tr_kernel<<<dim3(HIDn / 32, Sn / 32, Bn), 256>>>(
        hb, vTh, nullptr, 2 * HIDn, (long long)Sn * 2 * HIDn, (long long)HIDn * Sn, Sn);

    // 8) V = (A @ v) * gate -> hi only       [1-pass]
    tgemm<EPI_GATE, 1, 1><<<dim3(HIDn / 128, Sn / 128, Bn), 128, SM1>>>(
        Amh, nullptr, vTh, nullptr, nullptr, hb + HIDn, nullptr, Vh, nullptr,
        Sn, Sn, Sn, HIDn,
        (long long)Sn * Sn, (long long)HIDn * Sn, (long long)Sn * HIDn,
        (long long)Sn * 2 * HIDn, 2 * HIDn, 1.0f);

    // 9) U = V @ Wo^T + bo fp32              [1-pass]
    tgemm<EPI_BIAS, 0, 1><<<dim3(Dn / 128, BSn / 128, 1), 128, SM1>>>(
        Vh, nullptr, Woh, nullptr, bo, nullptr, U, nullptr, nullptr,
        HIDn, HIDn, HIDn, Dn, 0, 0, 0, 0, 0, 1.0f);

    // 10) out = LN(U) + x
    ln_kernel<false><<<BSn, 256>>>(U, g2, b2, x, out, nullptr, nullptr);
}

// round 7
// speedup vs baseline: 6.7620x; 1.0819x over previous
#include <cuda_runtime.h>
#include <cuda_fp16.h>
#include <cstdint>

// GAU block on GB300 (plain sm_103 target): fp16 hi/lo-split GEMMs on
// mma.sync.m16n8k16 + ldmatrix + cp.async.
// R7: pass-trim (Wm/ZW/QK -> 2-pass) + 3-stage pipeline on 1/2-pass GEMMs.
// B=4, S=2048, D=512, QKD=256, HID=1536

constexpr int Bn = 4, Sn = 2048, Dn = 512, QKDn = 256, HIDn = 1536;
constexpr int BSn = Bn * Sn;                 // 8192
constexpr float LN_EPS = 1e-5f;

// ----------------------------------------------------------------------------
// scratch (device globals)
// ----------------------------------------------------------------------------
static __device__ __align__(16) __half g_xh[BSn * Dn];                   // hi only
static __device__ __align__(16) __half g_Wmh[Dn * Dn],        g_Wml[Dn * Dn];
static __device__ __align__(16) __half g_Whh[2 * HIDn * Dn];             // hi only
static __device__ __align__(16) __half g_Wqh[QKDn * Dn],      g_Wql[QKDn * Dn];
static __device__ __align__(16) __half g_Woh[Dn * HIDn];                 // hi only
static __device__ __align__(16) __half g_WbTh[QKDn * QKDn],   g_WbTl[QKDn * QKDn];
static __device__ __align__(16) float  g_tmp1[BSn * Dn];
static __device__ __align__(16) __half g_nh[BSn * Dn],        g_nl[BSn * Dn];
static __device__ __align__(16) float  g_hbuf[BSn * 2 * HIDn];          // [v | gate]
static __device__ __align__(16) __half g_Zh[BSn * QKDn],      g_Zl[BSn * QKDn];
static __device__ __align__(16) __half g_ZWh[BSn * QKDn];                // hi only
static __device__ __align__(16) __half g_Amh[(long long)Bn * Sn * Sn];  // hi only
static __device__ __align__(16) __half g_vTh[(long long)Bn * HIDn * Sn];// hi only
static __device__ __align__(16) __half g_Vh[BSn * HIDn];                // hi only
static __device__ __align__(16) float  g_U[BSn * Dn];

// ----------------------------------------------------------------------------
// PTX helpers (sm_80-class, valid on plain sm_103)
// ----------------------------------------------------------------------------
__device__ __forceinline__ uint32_t smem_u32(const void* p) {
    uint32_t a;
    asm("{ .reg .u64 t; cvta.to.shared.u64 t, %1; cvt.u32.u64 %0, t; }"
        : "=r"(a) : "l"(p));
    return a;
}
__device__ __forceinline__ void cpa16(uint32_t saddr, const void* gaddr) {
    asm volatile("cp.async.cg.shared.global [%0], [%1], 16;"
                 :: "r"(saddr), "l"(gaddr) : "memory");
}
__device__ __forceinline__ void cpa_commit() {
    asm volatile("cp.async.commit_group;" ::: "memory");
}
template<int N>
__device__ __forceinline__ void cpa_wait() {
    asm volatile("cp.async.wait_group %0;" :: "n"(N) : "memory");
}
__device__ __forceinline__ void ldm_x4(uint32_t a, uint32_t& r0, uint32_t& r1,
                                       uint32_t& r2, uint32_t& r3) {
    asm volatile("ldmatrix.sync.aligned.m8n8.x4.shared.b16 {%0,%1,%2,%3}, [%4];"
                 : "=r"(r0), "=r"(r1), "=r"(r2), "=r"(r3) : "r"(a));
}
__device__ __forceinline__ void mma_f16(float* c, const uint32_t* a, uint32_t b0, uint32_t b1) {
    asm volatile(
        "mma.sync.aligned.m16n8k16.row.col.f32.f16.f16.f32 "
        "{%0,%1,%2,%3}, {%4,%5,%6,%7}, {%8,%9}, {%0,%1,%2,%3};"
        : "+f"(c[0]), "+f"(c[1]), "+f"(c[2]), "+f"(c[3])
        : "r"(a[0]), "r"(a[1]), "r"(a[2]), "r"(a[3]), "r"(b0), "r"(b1));
}
__device__ __forceinline__ void fsplit(float v, __half& h, __half& l) {
    h = __float2half_rn(v);
    l = __float2half_rn(v - __half2float(h));
}
__device__ __forceinline__ uint32_t pack2(__half a, __half b) {
    return (uint32_t)__half_as_ushort(a) | ((uint32_t)__half_as_ushort(b) << 16);
}

// ----------------------------------------------------------------------------
// tensor GEMM: C[m,n] = sum_k A[m,k]*B[n,k]  (both K-major)
// NPASS==3: acc = Ah*Bh + Ah*Bl + Al*Bh   (2-stage pipe)
// NPASS==2: acc = Ah*Bh + Ah*Bl           (3-stage pipe)
// NPASS==1: acc = Ah*Bh                   (3-stage pipe)
// CTA 128x128, K-tile 32, 4 warps (2x2, 64x64 warp tiles).
// OUT: 0 = fp32, 1 = fp16 hi only, 2 = fp16 hi+lo
// ----------------------------------------------------------------------------
enum { EPI_NONE = 0, EPI_BIAS = 1, EPI_BIAS_RELU = 2, EPI_BIAS_ADDX = 3,
       EPI_RELUSQ = 4, EPI_GATE = 5 };

constexpr int TROW = 80;                         // padded row bytes (64B data + 16B)
constexpr int TILE_B = 128 * TROW;               // 10240
template<int NPASS> struct StageCfg {
    static constexpr int NT = (NPASS == 3) ? 4 : (NPASS == 2 ? 3 : 2);
    static constexpr int NSTAGE = (NPASS == 3) ? 2 : 3;
    static constexpr int STAGE_B = NT * TILE_B;
    static constexpr int SMEM = NSTAGE * STAGE_B;
};

__device__ __forceinline__ void fill_tile(uint32_t sbase,
                                          const __half* __restrict__ g,
                                          long long row0, int ld, long long k0, int tid)
{
    #pragma unroll
    for (int it = 0; it < 4; ++it) {
        int q = tid + it * 128;               // 0..511 chunks of 16B
        int r = q >> 2, c = q & 3;
        cpa16(sbase + r * TROW + c * 16,
              g + (row0 + r) * (long long)ld + k0 + c * 8);
    }
}

template<int EPI, int OUT, int NPASS>
__global__ void __launch_bounds__(128, 2)
tgemm(const __half* __restrict__ pAh, const __half* __restrict__ pAl,
      const __half* __restrict__ pBh, const __half* __restrict__ pBl,
      const float* __restrict__ bias, const float* __restrict__ extra,
      float* __restrict__ Cf, __half* __restrict__ Ch, __half* __restrict__ Cl,
      int K, int lda, int ldb, int ldc,
      long long sA, long long sB, long long sC, long long sE,
      int lde, float scale)
{
    constexpr int STAGE_B = StageCfg<NPASS>::STAGE_B;
    constexpr int NSTAGE  = StageCfg<NPASS>::NSTAGE;
    extern __shared__ char smem[];
    const int tid = threadIdx.x;
    const int wid = tid >> 5, lane = tid & 31;
    const int z = blockIdx.z;
    pAh += (long long)z * sA;
    if (NPASS == 3) pAl += (long long)z * sA;
    pBh += (long long)z * sB;
    if (NPASS >= 2) pBl += (long long)z * sB;
    const float* Ex = extra ? extra + (long long)z * sE : nullptr;
    const long long coff = (long long)z * sC;
    const long long m0 = (long long)blockIdx.y * 128;
    const long long n0 = (long long)blockIdx.x * 128;
    const uint32_t sb = smem_u32(smem);

    const int wm = (wid >> 1) * 64;      // warp m offset (0, 64)
    const int wn = (wid & 1) * 64;       // warp n offset (0, 64)
    const int rowL = (lane & 7) + ((lane >> 3) & 1) * 8;
    const int cOff = lane >> 4;

    float acc[4][8][4];
    #pragma unroll
    for (int i = 0; i < 4; ++i)
        #pragma unroll
        for (int j = 0; j < 8; ++j)
            #pragma unroll
            for (int t = 0; t < 4; ++t) acc[i][j][t] = 0.0f;

    const int KT = K >> 5;

    auto fill_stage = [&](int stage, long long k0) {
        uint32_t s = sb + stage * STAGE_B;
        fill_tile(s,              pAh, m0, lda, k0, tid);
        fill_tile(s + TILE_B,     pBh, n0, ldb, k0, tid);
        if (NPASS >= 2)
            fill_tile(s + 2 * TILE_B, pBl, n0, ldb, k0, tid);
        if (NPASS == 3)
            fill_tile(s + 3 * TILE_B, pAl, m0, lda, k0, tid);
    };

    // prologue: fill stages 0 .. NSTAGE-2   (KT >= NSTAGE-1 for all our shapes)
    #pragma unroll
    for (int s = 0; s < NSTAGE - 1; ++s) {
        fill_stage(s, (long long)s * 32);
        cpa_commit();
    }

    for (int kt = 0; kt < KT; ++kt) {
        const int fs = kt + NSTAGE - 1;
        if (fs < KT) fill_stage(fs % NSTAGE, (long long)fs * 32);
        cpa_commit();                         // always (empty group allowed)
        cpa_wait<NSTAGE - 1>();
        __syncthreads();

        const uint32_t st  = sb + (kt % NSTAGE) * STAGE_B;
        const uint32_t aH  = st;
        const uint32_t bH  = st + TILE_B;
        const uint32_t bL  = st + 2 * TILE_B;   // valid NPASS>=2
        const uint32_t aL  = st + 3 * TILE_B;   // valid NPASS==3

        #pragma unroll
        for (int kk = 0; kk < 2; ++kk) {
            const int cc = kk * 2 + cOff;
            uint32_t ah[4][4], al[4][4];
            #pragma unroll
            for (int im = 0; im < 4; ++im) {
                uint32_t off = (uint32_t)((wm + im * 16 + rowL) * TROW + cc * 16);
                ldm_x4(aH + off, ah[im][0], ah[im][1], ah[im][2], ah[im][3]);
                if (NPASS == 3)
                    ldm_x4(aL + off, al[im][0], al[im][1], al[im][2], al[im][3]);
            }
            uint32_t bh[4][4], bl[4][4];
            #pragma unroll
            for (int nb = 0; nb < 4; ++nb) {
                uint32_t off = (uint32_t)((wn + nb * 16 + rowL) * TROW + cc * 16);
                ldm_x4(bH + off, bh[nb][0], bh[nb][1], bh[nb][2], bh[nb][3]);
                if (NPASS >= 2)
                    ldm_x4(bL + off, bl[nb][0], bl[nb][1], bl[nb][2], bl[nb][3]);
            }
            #pragma unroll
            for (int im = 0; im < 4; ++im) {
                #pragma unroll
                for (int j = 0; j < 8; ++j) {
                    const int nb = j >> 1, sel = j & 1;
                    mma_f16(acc[im][j], ah[im], bh[nb][sel], bh[nb][sel + 2]);
                    if (NPASS >= 2)
                        mma_f16(acc[im][j], ah[im], bl[nb][sel], bl[nb][sel + 2]);
                    if (NPASS == 3)
                        mma_f16(acc[im][j], al[im], bh[nb][sel], bh[nb][sel + 2]);
                }
            }
        }
        __syncthreads();
    }

    // ---- epilogue ----
    const int rql = lane >> 2;
    const int cql = (lane & 3) * 2;

    #pragma unroll
    for (int im = 0; im < 4; ++im) {
        #pragma unroll
        for (int j = 0; j < 8; ++j) {
            #pragma unroll
            for (int half = 0; half < 2; ++half) {
                const long long gm = m0 + wm + im * 16 + rql + half * 8;
                const long long gn = n0 + wn + j * 8 + cql;
                float v0 = acc[im][j][half * 2 + 0];
                float v1 = acc[im][j][half * 2 + 1];

                if (EPI == EPI_BIAS || EPI == EPI_BIAS_RELU || EPI == EPI_BIAS_ADDX) {
                    float2 bv = *reinterpret_cast<const float2*>(&bias[gn]);
                    v0 += bv.x; v1 += bv.y;
                }
                if (EPI == EPI_BIAS_RELU) { v0 = fmaxf(v0, 0.0f); v1 = fmaxf(v1, 0.0f); }
                if (EPI == EPI_BIAS_ADDX || EPI == EPI_GATE) {
                    float2 ev = *reinterpret_cast<const float2*>(&Ex[gm * lde + gn]);
                    if (EPI == EPI_BIAS_ADDX) { v0 += ev.x; v1 += ev.y; }
                    else                      { v0 *= ev.x; v1 *= ev.y; }
                }
                if (EPI == EPI_RELUSQ) {
                    float r0 = fmaxf(v0 * scale, 0.0f), r1 = fmaxf(v1 * scale, 0.0f);
                    v0 = r0 * r0; v1 = r1 * r1;
                }

                const long long oi = coff + gm * ldc + gn;
                if (OUT == 0) {
                    *reinterpret_cast<float2*>(&Cf[oi]) = make_float2(v0, v1);
                } else if (OUT == 1) {
                    *reinterpret_cast<uint32_t*>(&Ch[oi]) =
                        pack2(__float2half_rn(v0), __float2half_rn(v1));
                } else {
                    __half h0, l0, h1, l1;
                    fsplit(v0, h0, l0);
                    fsplit(v1, h1, l1);
                    *reinterpret_cast<uint32_t*>(&Ch[oi]) = pack2(h0, h1);
                    *reinterpret_cast<uint32_t*>(&Cl[oi]) = pack2(l0, l1);
                }
            }
        }
    }
}

// ----------------------------------------------------------------------------
// LayerNorm (D=512)
// ----------------------------------------------------------------------------
__device__ __forceinline__ float block_sum_512(float v, float* red)
{
    #pragma unroll
    for (int o = 16; o > 0; o >>= 1) v += __shfl_down_sync(0xffffffffu, v, o);
    if ((threadIdx.x & 31) == 0) red[threadIdx.x >> 5] = v;
    __syncthreads();
    if (threadIdx.x == 0) {
        float s = 0.0f;
        #pragma unroll
        for (int i = 0; i < 8; i++) s += red[i];
        red[0] = s;
    }
    __syncthreads();
    float r = red[0];
    __syncthreads();
    return r;
}

template<bool SPLIT>
__global__ void __launch_bounds__(256)
ln_kernel(const float* __restrict__ in, const float* __restrict__ g,
          const float* __restrict__ b, const float* __restrict__ resid,
          float* __restrict__ outf, __half* __restrict__ oh, __half* __restrict__ ol)
{
    __shared__ float red[8];
    const long long row = blockIdx.x;
    const int t = threadIdx.x;
    const float* rp = in + row * Dn;

    float v0 = rp[t], v1 = rp[t + 256];
    float mean = block_sum_512(v0 + v1, red) * (1.0f / Dn);
    float d0 = v0 - mean, d1 = v1 - mean;
    float var = block_sum_512(d0 * d0 + d1 * d1, red) * (1.0f / Dn);
    float inv = rsqrtf(var + LN_EPS);

    float o0 = d0 * inv * g[t]       + b[t];
    float o1 = d1 * inv * g[t + 256] + b[t + 256];
    if (SPLIT) {
        __half h0, l0, h1, l1;
        fsplit(o0, h0, l0);
        fsplit(o1, h1, l1);
        oh[row * Dn + t]       = h0;  ol[row * Dn + t]       = l0;
        oh[row * Dn + t + 256] = h1;  ol[row * Dn + t + 256] = l1;
    } else {
        if (resid) {
            o0 += resid[row * Dn + t];
            o1 += resid[row * Dn + t + 256];
        }
        outf[row * Dn + t]       = o0;
        outf[row * Dn + t + 256] = o1;
    }
}

// ----------------------------------------------------------------------------
// fused fp32 -> (hi[, lo]) fp16 converter for x + 4 weights
// ----------------------------------------------------------------------------
constexpr int Q_X  = BSn * Dn / 4;
constexpr int Q_WM = Dn * Dn / 4;
constexpr int Q_WH = 2 * HIDn * Dn / 4;
constexpr int Q_WQ = QKDn * Dn / 4;
constexpr int Q_WO = Dn * HIDn / 4;
constexpr int Q_TOT = Q_X + Q_WM + Q_WH + Q_WQ + Q_WO;

__global__ void __launch_bounds__(256)
cvt_all_kernel(const float* __restrict__ x,  __half* xh,
               const float* __restrict__ wm, __half* wmh, __half* wml,
               const float* __restrict__ wh, __half* whh,
               const float* __restrict__ wq, __half* wqh, __half* wql,
               const float* __restrict__ wo, __half* woh)
{
    int i = blockIdx.x * 256 + threadIdx.x;
    if (i >= Q_TOT) return;
    const float* in; __half *oh, *ol;
    if (i < Q_X)                        { in = x;  oh = xh;  ol = nullptr; }
    else if ((i -= Q_X)  < Q_WM)        { in = wm; oh = wmh; ol = wml; }
    else if ((i -= Q_WM) < Q_WH)        { in = wh; oh = whh; ol = nullptr; }
    else if ((i -= Q_WH) < Q_WQ)        { in = wq; oh = wqh; ol = wql; }
    else     { i -= Q_WQ;                 in = wo; oh = woh; ol = nullptr; }

    float4 v = reinterpret_cast<const float4*>(in)[i];
    __half h0, l0, h1, l1, h2, l2, h3, l3;
    fsplit(v.x, h0, l0); fsplit(v.y, h1, l1);
    fsplit(v.z, h2, l2); fsplit(v.w, h3, l3);
    reinterpret_cast<uint2*>(oh)[i] = make_uint2(pack2(h0, h1), pack2(h2, h3));
    if (ol)
        reinterpret_cast<uint2*>(ol)[i] = make_uint2(pack2(l0, l1), pack2(l2, l3));
}

// transpose + split: out[c][r] = in[r][c]; lo optional
__global__ void __launch_bounds__(256)
cvt_tr_kernel(const float* __restrict__ in, __half* __restrict__ oh,
              __half* __restrict__ ol,
              int ldin, long long sIn, long long sOut, int ldout)
{
    __shared__ float tbuf[32][33];
    const int z = blockIdx.z;
    const float* ip = in + (long long)z * sIn;
    const long long obase = (long long)z * sOut;
    const int c0 = blockIdx.x * 32, r0 = blockIdx.y * 32;
    const int tx = threadIdx.x & 31, ty = threadIdx.x >> 5;

    #pragma unroll
    for (int i = 0; i < 4; i++)
        tbuf[ty + i * 8][tx] = ip[(long long)(r0 + ty + i * 8) * ldin + c0 + tx];
    __syncthreads();
    #pragma unroll
    for (int i = 0; i < 4; i++) {
        float v = tbuf[tx][ty + i * 8];
        long long oi = obase + (long long)(c0 + ty + i * 8) * ldout + r0 + tx;
        if (ol) {
            __half h, l;
            fsplit(v, h, l);
            oh[oi] = h;
            ol[oi] = l;
        } else {
            oh[oi] = __float2half_rn(v);
        }
    }
}

// ----------------------------------------------------------------------------
// launch
// ----------------------------------------------------------------------------
extern "C" void kernel_launch(void* const* d_in, const int* in_sizes, int n_in,
                              void* d_out, int out_size)
{
    const float* x  = (const float*)d_in[0];
    const float* Wm = (const float*)d_in[1];
    const float* bm = (const float*)d_in[2];
    const float* g1 = (const float*)d_in[3];
    const float* b1 = (const float*)d_in[4];
    const float* Wh = (const float*)d_in[5];
    const float* bh = (const float*)d_in[6];
    const float* Wq = (const float*)d_in[7];
    const float* bq = (const float*)d_in[8];
    const float* Wb = (const float*)d_in[9];
    const float* Wo = (const float*)d_in[10];
    const float* bo = (const float*)d_in[11];
    const float* g2 = (const float*)d_in[12];
    const float* b2 = (const float*)d_in[13];
    float* out = (float*)d_out;

    __half *xh, *Wmh, *Wml, *Whh, *Wqh, *Wql, *Woh, *WbTh, *WbTl;
    __half *nh, *nl, *Zh, *Zl, *ZWh, *Amh, *vTh, *Vh;
    float *tmp1, *hb, *U;
    cudaGetSymbolAddress((void**)&xh, g_xh);
    cudaGetSymbolAddress((void**)&Wmh, g_Wmh);   cudaGetSymbolAddress((void**)&Wml, g_Wml);
    cudaGetSymbolAddress((void**)&Whh, g_Whh);
    cudaGetSymbolAddress((void**)&Wqh, g_Wqh);   cudaGetSymbolAddress((void**)&Wql, g_Wql);
    cudaGetSymbolAddress((void**)&Woh, g_Woh);
    cudaGetSymbolAddress((void**)&WbTh, g_WbTh); cudaGetSymbolAddress((void**)&WbTl, g_WbTl);
    cudaGetSymbolAddress((void**)&nh, g_nh);     cudaGetSymbolAddress((void**)&nl, g_nl);
    cudaGetSymbolAddress((void**)&Zh, g_Zh);     cudaGetSymbolAddress((void**)&Zl, g_Zl);
    cudaGetSymbolAddress((void**)&ZWh, g_ZWh);
    cudaGetSymbolAddress((void**)&Amh, g_Amh);
    cudaGetSymbolAddress((void**)&vTh, g_vTh);
    cudaGetSymbolAddress((void**)&Vh, g_Vh);
    cudaGetSymbolAddress((void**)&tmp1, g_tmp1);
    cudaGetSymbolAddress((void**)&hb, g_hbuf);
    cudaGetSymbolAddress((void**)&U, g_U);

    constexpr int SM3 = StageCfg<3>::SMEM;   // 2 x 40960 = 81920
    constexpr int SM2 = StageCfg<2>::SMEM;   // 3 x 30720 = 92160
    constexpr int SM1 = StageCfg<1>::SMEM;   // 3 x 20480 = 61440
    cudaFuncSetAttribute((const void*)tgemm<EPI_BIAS_ADDX, 0, 2>, cudaFuncAttributeMaxDynamicSharedMemorySize, SM2);
    cudaFuncSetAttribute((const void*)tgemm<EPI_BIAS_RELU, 0, 1>, cudaFuncAttributeMaxDynamicSharedMemorySize, SM1);
    cudaFuncSetAttribute((const void*)tgemm<EPI_BIAS_RELU, 2, 3>, cudaFuncAttributeMaxDynamicSharedMemorySize, SM3);
    cudaFuncSetAttribute((const void*)tgemm<EPI_NONE, 1, 2>,      cudaFuncAttributeMaxDynamicSharedMemorySize, SM2);
    cudaFuncSetAttribute((const void*)tgemm<EPI_RELUSQ, 1, 2>,    cudaFuncAttributeMaxDynamicSharedMemorySize, SM2);
    cudaFuncSetAttribute((const void*)tgemm<EPI_GATE, 1, 1>,      cudaFuncAttributeMaxDynamicSharedMemorySize, SM1);
    cudaFuncSetAttribute((const void*)tgemm<EPI_BIAS, 0, 1>,      cudaFuncAttributeMaxDynamicSharedMemorySize, SM1);

    const float inv_s = 1.0f / (float)Sn;

    // 0) conversions
    cvt_all_kernel<<<(Q_TOT + 255) / 256, 256>>>(
        x, xh, Wm, Wmh, Wml, Wh, Whh, Wq, Wqh, Wql, Wo, Woh);
    cvt_tr_kernel<<<dim3(QKDn / 32, QKDn / 32, 1), 256>>>(Wb, WbTh, WbTl, QKDn, 0, 0, QKDn);

    // 1) tmp1 = x @ Wm^T + bm + x            [2-pass]
    tgemm<EPI_BIAS_ADDX, 0, 2><<<dim3(Dn / 128, BSn / 128, 1), 128, SM2>>>(
        xh, nullptr, Wmh, Wml, bm, x, tmp1, nullptr, nullptr,
        Dn, Dn, Dn, Dn, 0, 0, 0, 0, Dn, 1.0f);

    // 2) nrm = LN(tmp1) -> hi/lo
    ln_kernel<true><<<BSn, 256>>>(tmp1, g1, b1, nullptr, nullptr, nh, nl);

    // 3) h = relu(nrm @ Wh^T + bh) fp32      [1-pass]
    tgemm<EPI_BIAS_RELU, 0, 1><<<dim3(2 * HIDn / 128, BSn / 128, 1), 128, SM1>>>(
        nh, nullptr, Whh, nullptr, bh, nullptr, hb, nullptr, nullptr,
        Dn, Dn, Dn, 2 * HIDn, 0, 0, 0, 0, 0, 1.0f);

    // 4) Z = relu(nrm @ Wq^T + bq) -> hi/lo  [3-pass]
    tgemm<EPI_BIAS_RELU, 2, 3><<<dim3(QKDn / 128, BSn / 128, 1), 128, SM3>>>(
        nh, nl, Wqh, Wql, bq, nullptr, nullptr, Zh, Zl,
        Dn, Dn, Dn, QKDn, 0, 0, 0, 0, 0, 1.0f);

    // 5) ZW = Z @ Wb -> hi only              [2-pass]
    tgemm<EPI_NONE, 1, 2><<<dim3(QKDn / 128, BSn / 128, 1), 128, SM2>>>(
        Zh, nullptr, WbTh, WbTl, nullptr, nullptr, nullptr, ZWh, nullptr,
        QKDn, QKDn, QKDn, QKDn, 0, 0, 0, 0, 0, 1.0f);

    // 6) A = relu((ZW @ Z^T)/S)^2 -> hi only [2-pass]
    tgemm<EPI_RELUSQ, 1, 2><<<dim3(Sn / 128, Sn / 128, Bn), 128, SM2>>>(
        ZWh, nullptr, Zh, Zl, nullptr, nullptr, nullptr, Amh, nullptr,
        QKDn, QKDn, QKDn, Sn,
        (long long)Sn * QKDn, (long long)Sn * QKDn, (long long)Sn * Sn, 0, 0, inv_s);

    // 7) vT = transpose(v) -> hi only
    cvt_tr_kernel<<<dim3(HIDn / 32, Sn / 32, Bn), 256>>>(
        hb, vTh, nullptr, 2 * HIDn, (long long)Sn * 2 * HIDn, (long long)HIDn * Sn, Sn);

    // 8) V = (A @ v) * gate -> hi only       [1-pass]
    tgemm<EPI_GATE, 1, 1><<<dim3(HIDn / 128, Sn / 128, Bn), 128, SM1>>>(
        Amh, nullptr, vTh, nullptr, nullptr, hb + HIDn, nullptr, Vh, nullptr,
        Sn, Sn, Sn, HIDn,
        (long long)Sn * Sn, (long long)HIDn * Sn, (long long)Sn * HIDn,
        (long long)Sn * 2 * HIDn, 2 * HIDn, 1.0f);

    // 9) U = V @ Wo^T + bo fp32              [1-pass]
    tgemm<EPI_BIAS, 0, 1><<<dim3(Dn / 128, BSn / 128, 1), 128, SM1>>>(
        Vh, nullptr, Woh, nullptr, bo, nullptr, U, nullptr, nullptr,
        HIDn, HIDn, HIDn, Dn, 0, 0, 0, 0, 0, 1.0f);

    // 10) out = LN(U) + x
    ln_kernel<false><<<BSn, 256>>>(U, g2, b2, x, out, nullptr, nullptr);
}

// round 8
// speedup vs baseline: 7.1487x; 1.0572x over previous
#include <cuda_runtime.h>
#include <cuda_fp16.h>
#include <cstdint>

// GAU block on GB300 (plain sm_103 target): fp16 hi/lo-split GEMMs on
// mma.sync.m16n8k16 + ldmatrix + cp.async.
// R8: QK -> 1-pass, Z hi-only, h buffer fp16 (halves hb+gate+transpose traffic).
// B=4, S=2048, D=512, QKD=256, HID=1536

constexpr int Bn = 4, Sn = 2048, Dn = 512, QKDn = 256, HIDn = 1536;
constexpr int BSn = Bn * Sn;                 // 8192
constexpr float LN_EPS = 1e-5f;

// ----------------------------------------------------------------------------
// scratch (device globals)
// ----------------------------------------------------------------------------
static __device__ __align__(16) __half g_xh[BSn * Dn];                   // hi only
static __device__ __align__(16) __half g_Wmh[Dn * Dn],        g_Wml[Dn * Dn];
static __device__ __align__(16) __half g_Whh[2 * HIDn * Dn];             // hi only
static __device__ __align__(16) __half g_Wqh[QKDn * Dn],      g_Wql[QKDn * Dn];
static __device__ __align__(16) __half g_Woh[Dn * HIDn];                 // hi only
static __device__ __align__(16) __half g_WbTh[QKDn * QKDn],   g_WbTl[QKDn * QKDn];
static __device__ __align__(16) float  g_tmp1[BSn * Dn];
static __device__ __align__(16) __half g_nh[BSn * Dn],        g_nl[BSn * Dn];
static __device__ __align__(16) __half g_hbuf[BSn * 2 * HIDn];          // [v | gate] fp16
static __device__ __align__(16) __half g_Zh[BSn * QKDn];                 // hi only
static __device__ __align__(16) __half g_ZWh[BSn * QKDn];                // hi only
static __device__ __align__(16) __half g_Amh[(long long)Bn * Sn * Sn];  // hi only
static __device__ __align__(16) __half g_vTh[(long long)Bn * HIDn * Sn];// hi only
static __device__ __align__(16) __half g_Vh[BSn * HIDn];                // hi only
static __device__ __align__(16) float  g_U[BSn * Dn];

// ----------------------------------------------------------------------------
// PTX helpers (sm_80-class, valid on plain sm_103)
// ----------------------------------------------------------------------------
__device__ __forceinline__ uint32_t smem_u32(const void* p) {
    uint32_t a;
    asm("{ .reg .u64 t; cvta.to.shared.u64 t, %1; cvt.u32.u64 %0, t; }"
        : "=r"(a) : "l"(p));
    return a;
}
__device__ __forceinline__ void cpa16(uint32_t saddr, const void* gaddr) {
    asm volatile("cp.async.cg.shared.global [%0], [%1], 16;"
                 :: "r"(saddr), "l"(gaddr) : "memory");
}
__device__ __forceinline__ void cpa_commit() {
    asm volatile("cp.async.commit_group;" ::: "memory");
}
template<int N>
__device__ __forceinline__ void cpa_wait() {
    asm volatile("cp.async.wait_group %0;" :: "n"(N) : "memory");
}
__device__ __forceinline__ void ldm_x4(uint32_t a, uint32_t& r0, uint32_t& r1,
                                       uint32_t& r2, uint32_t& r3) {
    asm volatile("ldmatrix.sync.aligned.m8n8.x4.shared.b16 {%0,%1,%2,%3}, [%4];"
                 : "=r"(r0), "=r"(r1), "=r"(r2), "=r"(r3) : "r"(a));
}
__device__ __forceinline__ void mma_f16(float* c, const uint32_t* a, uint32_t b0, uint32_t b1) {
    asm volatile(
        "mma.sync.aligned.m16n8k16.row.col.f32.f16.f16.f32 "
        "{%0,%1,%2,%3}, {%4,%5,%6,%7}, {%8,%9}, {%0,%1,%2,%3};"
        : "+f"(c[0]), "+f"(c[1]), "+f"(c[2]), "+f"(c[3])
        : "r"(a[0]), "r"(a[1]), "r"(a[2]), "r"(a[3]), "r"(b0), "r"(b1));
}
__device__ __forceinline__ void fsplit(float v, __half& h, __half& l) {
    h = __float2half_rn(v);
    l = __float2half_rn(v - __half2float(h));
}
__device__ __forceinline__ uint32_t pack2(__half a, __half b) {
    return (uint32_t)__half_as_ushort(a) | ((uint32_t)__half_as_ushort(b) << 16);
}

// ----------------------------------------------------------------------------
// tensor GEMM: C[m,n] = sum_k A[m,k]*B[n,k]  (both K-major)
// NPASS==3: acc = Ah*Bh + Ah*Bl + Al*Bh   (2-stage pipe)
// NPASS==2: acc = Ah*Bh + Ah*Bl           (3-stage pipe)
// NPASS==1: acc = Ah*Bh                   (3-stage pipe)
// CTA 128x128, K-tile 32, 4 warps (2x2, 64x64 warp tiles).
// OUT: 0 = fp32, 1 = fp16 hi only, 2 = fp16 hi+lo
// EPI_GATE reads `extra` as fp16.
// ----------------------------------------------------------------------------
enum { EPI_NONE = 0, EPI_BIAS = 1, EPI_BIAS_RELU = 2, EPI_BIAS_ADDX = 3,
       EPI_RELUSQ = 4, EPI_GATE = 5 };

constexpr int TROW = 80;                         // padded row bytes (64B data + 16B)
constexpr int TILE_B = 128 * TROW;               // 10240
template<int NPASS> struct StageCfg {
    static constexpr int NT = (NPASS == 3) ? 4 : (NPASS == 2 ? 3 : 2);
    static constexpr int NSTAGE = (NPASS == 3) ? 2 : 3;
    static constexpr int STAGE_B = NT * TILE_B;
    static constexpr int SMEM = NSTAGE * STAGE_B;
};

__device__ __forceinline__ void fill_tile(uint32_t sbase,
                                          const __half* __restrict__ g,
                                          long long row0, int ld, long long k0, int tid)
{
    #pragma unroll
    for (int it = 0; it < 4; ++it) {
        int q = tid + it * 128;               // 0..511 chunks of 16B
        int r = q >> 2, c = q & 3;
        cpa16(sbase + r * TROW + c * 16,
              g + (row0 + r) * (long long)ld + k0 + c * 8);
    }
}

template<int EPI, int OUT, int NPASS>
__global__ void __launch_bounds__(128, 2)
tgemm(const __half* __restrict__ pAh, const __half* __restrict__ pAl,
      const __half* __restrict__ pBh, const __half* __restrict__ pBl,
      const float* __restrict__ bias, const void* __restrict__ extra,
      float* __restrict__ Cf, __half* __restrict__ Ch, __half* __restrict__ Cl,
      int K, int lda, int ldb, int ldc,
      long long sA, long long sB, long long sC, long long sE,
      int lde, float scale)
{
    constexpr int STAGE_B = StageCfg<NPASS>::STAGE_B;
    constexpr int NSTAGE  = StageCfg<NPASS>::NSTAGE;
    extern __shared__ char smem[];
    const int tid = threadIdx.x;
    const int wid = tid >> 5, lane = tid & 31;
    const int z = blockIdx.z;
    pAh += (long long)z * sA;
    if (NPASS == 3) pAl += (long long)z * sA;
    pBh += (long long)z * sB;
    if (NPASS >= 2) pBl += (long long)z * sB;
    const float*  Exf = (EPI == EPI_BIAS_ADDX && extra)
                        ? (const float*)extra + (long long)z * sE : nullptr;
    const __half* Exh = (EPI == EPI_GATE && extra)
                        ? (const __half*)extra + (long long)z * sE : nullptr;
    const long long coff = (long long)z * sC;
    const long long m0 = (long long)blockIdx.y * 128;
    const long long n0 = (long long)blockIdx.x * 128;
    const uint32_t sb = smem_u32(smem);

    const int wm = (wid >> 1) * 64;      // warp m offset (0, 64)
    const int wn = (wid & 1) * 64;       // warp n offset (0, 64)
    const int rowL = (lane & 7) + ((lane >> 3) & 1) * 8;
    const int cOff = lane >> 4;

    float acc[4][8][4];
    #pragma unroll
    for (int i = 0; i < 4; ++i)
        #pragma unroll
        for (int j = 0; j < 8; ++j)
            #pragma unroll
            for (int t = 0; t < 4; ++t) acc[i][j][t] = 0.0f;

    const int KT = K >> 5;

    auto fill_stage = [&](int stage, long long k0) {
        uint32_t s = sb + stage * STAGE_B;
        fill_tile(s,              pAh, m0, lda, k0, tid);
        fill_tile(s + TILE_B,     pBh, n0, ldb, k0, tid);
        if (NPASS >= 2)
            fill_tile(s + 2 * TILE_B, pBl, n0, ldb, k0, tid);
        if (NPASS == 3)
            fill_tile(s + 3 * TILE_B, pAl, m0, lda, k0, tid);
    };

    // prologue
    #pragma unroll
    for (int s = 0; s < NSTAGE - 1; ++s) {
        fill_stage(s, (long long)s * 32);
        cpa_commit();
    }

    for (int kt = 0; kt < KT; ++kt) {
        const int fs = kt + NSTAGE - 1;
        if (fs < KT) fill_stage(fs % NSTAGE, (long long)fs * 32);
        cpa_commit();
        cpa_wait<NSTAGE - 1>();
        __syncthreads();

        const uint32_t st  = sb + (kt % NSTAGE) * STAGE_B;
        const uint32_t aH  = st;
        const uint32_t bH  = st + TILE_B;
        const uint32_t bL  = st + 2 * TILE_B;   // valid NPASS>=2
        const uint32_t aL  = st + 3 * TILE_B;   // valid NPASS==3

        #pragma unroll
        for (int kk = 0; kk < 2; ++kk) {
            const int cc = kk * 2 + cOff;
            uint32_t ah[4][4], al[4][4];
            #pragma unroll
            for (int im = 0; im < 4; ++im) {
                uint32_t off = (uint32_t)((wm + im * 16 + rowL) * TROW + cc * 16);
                ldm_x4(aH + off, ah[im][0], ah[im][1], ah[im][2], ah[im][3]);
                if (NPASS == 3)
                    ldm_x4(aL + off, al[im][0], al[im][1], al[im][2], al[im][3]);
            }
            uint32_t bh[4][4], bl[4][4];
            #pragma unroll
            for (int nb = 0; nb < 4; ++nb) {
                uint32_t off = (uint32_t)((wn + nb * 16 + rowL) * TROW + cc * 16);
                ldm_x4(bH + off, bh[nb][0], bh[nb][1], bh[nb][2], bh[nb][3]);
                if (NPASS >= 2)
                    ldm_x4(bL + off, bl[nb][0], bl[nb][1], bl[nb][2], bl[nb][3]);
            }
            #pragma unroll
            for (int im = 0; im < 4; ++im) {
                #pragma unroll
                for (int j = 0; j < 8; ++j) {
                    const int nb = j >> 1, sel = j & 1;
                    mma_f16(acc[im][j], ah[im], bh[nb][sel], bh[nb][sel + 2]);
                    if (NPASS >= 2)
                        mma_f16(acc[im][j], ah[im], bl[nb][sel], bl[nb][sel + 2]);
                    if (NPASS == 3)
                        mma_f16(acc[im][j], al[im], bh[nb][sel], bh[nb][sel + 2]);
                }
            }
        }
        __syncthreads();
    }

    // ---- epilogue ----
    const int rql = lane >> 2;
    const int cql = (lane & 3) * 2;

    #pragma unroll
    for (int im = 0; im < 4; ++im) {
        #pragma unroll
        for (int j = 0; j < 8; ++j) {
            #pragma unroll
            for (int half = 0; half < 2; ++half) {
                const long long gm = m0 + wm + im * 16 + rql + half * 8;
                const long long gn = n0 + wn + j * 8 + cql;
                float v0 = acc[im][j][half * 2 + 0];
                float v1 = acc[im][j][half * 2 + 1];

                if (EPI == EPI_BIAS || EPI == EPI_BIAS_RELU || EPI == EPI_BIAS_ADDX) {
                    float2 bv = *reinterpret_cast<const float2*>(&bias[gn]);
                    v0 += bv.x; v1 += bv.y;
                }
                if (EPI == EPI_BIAS_RELU) { v0 = fmaxf(v0, 0.0f); v1 = fmaxf(v1, 0.0f); }
                if (EPI == EPI_BIAS_ADDX) {
                    float2 ev = *reinterpret_cast<const float2*>(&Exf[gm * lde + gn]);
                    v0 += ev.x; v1 += ev.y;
                }
                if (EPI == EPI_GATE) {
                    uint32_t gp = *reinterpret_cast<const uint32_t*>(&Exh[gm * lde + gn]);
                    v0 *= __half2float(__ushort_as_half((unsigned short)(gp & 0xFFFF)));
                    v1 *= __half2float(__ushort_as_half((unsigned short)(gp >> 16)));
                }
                if (EPI == EPI_RELUSQ) {
                    float r0 = fmaxf(v0 * scale, 0.0f), r1 = fmaxf(v1 * scale, 0.0f);
                    v0 = r0 * r0; v1 = r1 * r1;
                }

                const long long oi = coff + gm * ldc + gn;
                if (OUT == 0) {
                    *reinterpret_cast<float2*>(&Cf[oi]) = make_float2(v0, v1);
                } else if (OUT == 1) {
                    *reinterpret_cast<uint32_t*>(&Ch[oi]) =
                        pack2(__float2half_rn(v0), __float2half_rn(v1));
                } else {
                    __half h0, l0, h1, l1;
                    fsplit(v0, h0, l0);
                    fsplit(v1, h1, l1);
                    *reinterpret_cast<uint32_t*>(&Ch[oi]) = pack2(h0, h1);
                    *reinterpret_cast<uint32_t*>(&Cl[oi]) = pack2(l0, l1);
                }
            }
        }
    }
}

// ----------------------------------------------------------------------------
// LayerNorm (D=512)
// ----------------------------------------------------------------------------
__device__ __forceinline__ float block_sum_512(float v, float* red)
{
    #pragma unroll
    for (int o = 16; o > 0; o >>= 1) v += __shfl_down_sync(0xffffffffu, v, o);
    if ((threadIdx.x & 31) == 0) red[threadIdx.x >> 5] = v;
    __syncthreads();
    if (threadIdx.x == 0) {
        float s = 0.0f;
        #pragma unroll
        for (int i = 0; i < 8; i++) s += red[i];
        red[0] = s;
    }
    __syncthreads();
    float r = red[0];
    __syncthreads();
    return r;
}

template<bool SPLIT>
__global__ void __launch_bounds__(256)
ln_kernel(const float* __restrict__ in, const float* __restrict__ g,
          const float* __restrict__ b, const float* __restrict__ resid,
          float* __restrict__ outf, __half* __restrict__ oh, __half* __restrict__ ol)
{
    __shared__ float red[8];
    const long long row = blockIdx.x;
    const int t = threadIdx.x;
    const float* rp = in + row * Dn;

    float v0 = rp[t], v1 = rp[t + 256];
    float mean = block_sum_512(v0 + v1, red) * (1.0f / Dn);
    float d0 = v0 - mean, d1 = v1 - mean;
    float var = block_sum_512(d0 * d0 + d1 * d1, red) * (1.0f / Dn);
    float inv = rsqrtf(var + LN_EPS);

    float o0 = d0 * inv * g[t]       + b[t];
    float o1 = d1 * inv * g[t + 256] + b[t + 256];
    if (SPLIT) {
        __half h0, l0, h1, l1;
        fsplit(o0, h0, l0);
        fsplit(o1, h1, l1);
        oh[row * Dn + t]       = h0;  ol[row * Dn + t]       = l0;
        oh[row * Dn + t + 256] = h1;  ol[row * Dn + t + 256] = l1;
    } else {
        if (resid) {
            o0 += resid[row * Dn + t];
            o1 += resid[row * Dn + t + 256];
        }
        outf[row * Dn + t]       = o0;
        outf[row * Dn + t + 256] = o1;
    }
}

// ----------------------------------------------------------------------------
// fused fp32 -> (hi[, lo]) fp16 converter for x + 4 weights
// ----------------------------------------------------------------------------
constexpr int Q_X  = BSn * Dn / 4;
constexpr int Q_WM = Dn * Dn / 4;
constexpr int Q_WH = 2 * HIDn * Dn / 4;
constexpr int Q_WQ = QKDn * Dn / 4;
constexpr int Q_WO = Dn * HIDn / 4;
constexpr int Q_TOT = Q_X + Q_WM + Q_WH + Q_WQ + Q_WO;

__global__ void __launch_bounds__(256)
cvt_all_kernel(const float* __restrict__ x,  __half* xh,
               const float* __restrict__ wm, __half* wmh, __half* wml,
               const float* __restrict__ wh, __half* whh,
               const float* __restrict__ wq, __half* wqh, __half* wql,
               const float* __restrict__ wo, __half* woh)
{
    int i = blockIdx.x * 256 + threadIdx.x;
    if (i >= Q_TOT) return;
    const float* in; __half *oh, *ol;
    if (i < Q_X)                        { in = x;  oh = xh;  ol = nullptr; }
    else if ((i -= Q_X)  < Q_WM)        { in = wm; oh = wmh; ol = wml; }
    else if ((i -= Q_WM) < Q_WH)        { in = wh; oh = whh; ol = nullptr; }
    else if ((i -= Q_WH) < Q_WQ)        { in = wq; oh = wqh; ol = wql; }
    else     { i -= Q_WQ;                 in = wo; oh = woh; ol = nullptr; }

    float4 v = reinterpret_cast<const float4*>(in)[i];
    __half h0, l0, h1, l1, h2, l2, h3, l3;
    fsplit(v.x, h0, l0); fsplit(v.y, h1, l1);
    fsplit(v.z, h2, l2); fsplit(v.w, h3, l3);
    reinterpret_cast<uint2*>(oh)[i] = make_uint2(pack2(h0, h1), pack2(h2, h3));
    if (ol)
        reinterpret_cast<uint2*>(ol)[i] = make_uint2(pack2(l0, l1), pack2(l2, l3));
}

// transpose + split (fp32 in): out[c][r] = in[r][c]
__global__ void __launch_bounds__(256)
cvt_tr_kernel(const float* __restrict__ in, __half* __restrict__ oh,
              __half* __restrict__ ol,
              int ldin, long long sIn, long long sOut, int ldout)
{
    __shared__ float tbuf[32][33];
    const int z = blockIdx.z;
    const float* ip = in + (long long)z * sIn;
    const long long obase = (long long)z * sOut;
    const int c0 = blockIdx.x * 32, r0 = blockIdx.y * 32;
    const int tx = threadIdx.x & 31, ty = threadIdx.x >> 5;

    #pragma unroll
    for (int i = 0; i < 4; i++)
        tbuf[ty + i * 8][tx] = ip[(long long)(r0 + ty + i * 8) * ldin + c0 + tx];
    __syncthreads();
    #pragma unroll
    for (int i = 0; i < 4; i++) {
        float v = tbuf[tx][ty + i * 8];
        long long oi = obase + (long long)(c0 + ty + i * 8) * ldout + r0 + tx;
        __half h, l;
        fsplit(v, h, l);
        oh[oi] = h;
        ol[oi] = l;
    }
}

// fp16 transpose: out[c][r] = in[r][c]
__global__ void __launch_bounds__(256)
tr_h_kernel(const __half* __restrict__ in, __half* __restrict__ out,
            int ldin, long long sIn, long long sOut, int ldout)
{
    __shared__ __half tbuf[32][34];
    const int z = blockIdx.z;
    const __half* ip = in + (long long)z * sIn;
    const long long obase = (long long)z * sOut;
    const int c0 = blockIdx.x * 32, r0 = blockIdx.y * 32;
    const int tx = threadIdx.x & 31, ty = threadIdx.x >> 5;

    #pragma unroll
    for (int i = 0; i < 4; i++)
        tbuf[ty + i * 8][tx] = ip[(long long)(r0 + ty + i * 8) * ldin + c0 + tx];
    __syncthreads();
    #pragma unroll
    for (int i = 0; i < 4; i++) {
        long long oi = obase + (long long)(c0 + ty + i * 8) * ldout + r0 + tx;
        out[oi] = tbuf[tx][ty + i * 8];
    }
}

// ----------------------------------------------------------------------------
// launch
// ----------------------------------------------------------------------------
extern "C" void kernel_launch(void* const* d_in, const int* in_sizes, int n_in,
                              void* d_out, int out_size)
{
    const float* x  = (const float*)d_in[0];
    const float* Wm = (const float*)d_in[1];
    const float* bm = (const float*)d_in[2];
    const float* g1 = (const float*)d_in[3];
    const float* b1 = (const float*)d_in[4];
    const float* Wh = (const float*)d_in[5];
    const float* bh = (const float*)d_in[6];
    const float* Wq = (const float*)d_in[7];
    const float* bq = (const float*)d_in[8];
    const float* Wb = (const float*)d_in[9];
    const float* Wo = (const float*)d_in[10];
    const float* bo = (const float*)d_in[11];
    const float* g2 = (const float*)d_in[12];
    const float* b2 = (const float*)d_in[13];
    float* out = (float*)d_out;

    __half *xh, *Wmh, *Wml, *Whh, *Wqh, *Wql, *Woh, *WbTh, *WbTl;
    __half *nh, *nl, *Zh, *ZWh, *Amh, *vTh, *Vh, *hb;
    float *tmp1, *U;
    cudaGetSymbolAddress((void**)&xh, g_xh);
    cudaGetSymbolAddress((void**)&Wmh, g_Wmh);   cudaGetSymbolAddress((void**)&Wml, g_Wml);
    cudaGetSymbolAddress((void**)&Whh, g_Whh);
    cudaGetSymbolAddress((void**)&Wqh, g_Wqh);   cudaGetSymbolAddress((void**)&Wql, g_Wql);
    cudaGetSymbolAddress((void**)&Woh, g_Woh);
    cudaGetSymbolAddress((void**)&WbTh, g_WbTh); cudaGetSymbolAddress((void**)&WbTl, g_WbTl);
    cudaGetSymbolAddress((void**)&nh, g_nh);     cudaGetSymbolAddress((void**)&nl, g_nl);
    cudaGetSymbolAddress((void**)&Zh, g_Zh);
    cudaGetSymbolAddress((void**)&ZWh, g_ZWh);
    cudaGetSymbolAddress((void**)&Amh, g_Amh);
    cudaGetSymbolAddress((void**)&vTh, g_vTh);
    cudaGetSymbolAddress((void**)&Vh, g_Vh);
    cudaGetSymbolAddress((void**)&hb, g_hbuf);
    cudaGetSymbolAddress((void**)&tmp1, g_tmp1);
    cudaGetSymbolAddress((void**)&U, g_U);

    constexpr int SM3 = StageCfg<3>::SMEM;   // 81920
    constexpr int SM2 = StageCfg<2>::SMEM;   // 92160
    constexpr int SM1 = StageCfg<1>::SMEM;   // 61440
    cudaFuncSetAttribute((const void*)tgemm<EPI_BIAS_ADDX, 0, 2>, cudaFuncAttributeMaxDynamicSharedMemorySize, SM2);
    cudaFuncSetAttribute((const void*)tgemm<EPI_BIAS_RELU, 1, 1>, cudaFuncAttributeMaxDynamicSharedMemorySize, SM1);
    cudaFuncSetAttribute((const void*)tgemm<EPI_BIAS_RELU, 1, 3>, cudaFuncAttributeMaxDynamicSharedMemorySize, SM3);
    cudaFuncSetAttribute((const void*)tgemm<EPI_NONE, 1, 2>,      cudaFuncAttributeMaxDynamicSharedMemorySize, SM2);
    cudaFuncSetAttribute((const void*)tgemm<EPI_RELUSQ, 1, 1>,    cudaFuncAttributeMaxDynamicSharedMemorySize, SM1);
    cudaFuncSetAttribute((const void*)tgemm<EPI_GATE, 1, 1>,      cudaFuncAttributeMaxDynamicSharedMemorySize, SM1);
    cudaFuncSetAttribute((const void*)tgemm<EPI_BIAS, 0, 1>,      cudaFuncAttributeMaxDynamicSharedMemorySize, SM1);

    const float inv_s = 1.0f / (float)Sn;

    // 0) conversions
    cvt_all_kernel<<<(Q_TOT + 255) / 256, 256>>>(
        x, xh, Wm, Wmh, Wml, Wh, Whh, Wq, Wqh, Wql, Wo, Woh);
    cvt_tr_kernel<<<dim3(QKDn / 32, QKDn / 32, 1), 256>>>(Wb, WbTh, WbTl, QKDn, 0, 0, QKDn);

    // 1) tmp1 = x @ Wm^T + bm + x            [2-pass]
    tgemm<EPI_BIAS_ADDX, 0, 2><<<dim3(Dn / 128, BSn / 128, 1), 128, SM2>>>(
        xh, nullptr, Wmh, Wml, bm, x, tmp1, nullptr, nullptr,
        Dn, Dn, Dn, Dn, 0, 0, 0, 0, Dn, 1.0f);

    // 2) nrm = LN(tmp1) -> hi/lo
    ln_kernel<true><<<BSn, 256>>>(tmp1, g1, b1, nullptr, nullptr, nh, nl);

    // 3) h = relu(nrm @ Wh^T + bh) -> fp16   [1-pass]
    tgemm<EPI_BIAS_RELU, 1, 1><<<dim3(2 * HIDn / 128, BSn / 128, 1), 128, SM1>>>(
        nh, nullptr, Whh, nullptr, bh, nullptr, nullptr, hb, nullptr,
        Dn, Dn, Dn, 2 * HIDn, 0, 0, 0, 0, 0, 1.0f);

    // 4) Z = relu(nrm @ Wq^T + bq) -> hi     [3-pass]
    tgemm<EPI_BIAS_RELU, 1, 3><<<dim3(QKDn / 128, BSn / 128, 1), 128, SM3>>>(
        nh, nl, Wqh, Wql, bq, nullptr, nullptr, Zh, nullptr,
        Dn, Dn, Dn, QKDn, 0, 0, 0, 0, 0, 1.0f);

    // 5) ZW = Z @ Wb -> hi                   [2-pass]
    tgemm<EPI_NONE, 1, 2><<<dim3(QKDn / 128, BSn / 128, 1), 128, SM2>>>(
        Zh, nullptr, WbTh, WbTl, nullptr, nullptr, nullptr, ZWh, nullptr,
        QKDn, QKDn, QKDn, QKDn, 0, 0, 0, 0, 0, 1.0f);

    // 6) A = relu((ZW @ Z^T)/S)^2 -> hi      [1-pass]
    tgemm<EPI_RELUSQ, 1, 1><<<dim3(Sn / 128, Sn / 128, Bn), 128, SM1>>>(
        ZWh, nullptr, Zh, nullptr, nullptr, nullptr, nullptr, Amh, nullptr,
        QKDn, QKDn, QKDn, Sn,
        (long long)Sn * QKDn, (long long)Sn * QKDn, (long long)Sn * Sn, 0, 0, inv_s);

    // 7) vT = transpose(v) fp16 -> fp16
    tr_h_kernel<<<dim3(HIDn / 32, Sn / 32, Bn), 256>>>(
        hb, vTh, 2 * HIDn, (long long)Sn * 2 * HIDn, (long long)HIDn * Sn, Sn);

    // 8) V = (A @ v) * gate -> hi            [1-pass, gate fp16]
    tgemm<EPI_GATE, 1, 1><<<dim3(HIDn / 128, Sn / 128, Bn), 128, SM1>>>(
        Amh, nullptr, vTh, nullptr, nullptr, hb + HIDn, nullptr, Vh, nullptr,
        Sn, Sn, Sn, HIDn,
        (long long)Sn * Sn, (long long)HIDn * Sn, (long long)Sn * HIDn,
        (long long)Sn * 2 * HIDn, 2 * HIDn, 1.0f);

    // 9) U = V @ Wo^T + bo fp32              [1-pass]
    tgemm<EPI_BIAS, 0, 1><<<dim3(Dn / 128, BSn / 128, 1), 128, SM1>>>(
        Vh, nullptr, Woh, nullptr, bo, nullptr, U, nullptr, nullptr,
        HIDn, HIDn, HIDn, Dn, 0, 0, 0, 0, 0, 1.0f);

    // 10) out = LN(U) + x
    ln_kernel<false><<<BSn, 256>>>(U, g2, b2, x, out, nullptr, nullptr);
}

// round 9
// speedup vs baseline: 7.4696x; 1.0449x over previous
#include <cuda_runtime.h>
#include <cuda_fp16.h>
#include <cstdint>

// GAU block on GB300 (plain sm_103 target): fp16 hi/lo-split GEMMs on
// mma.sync.m16n8k16 + ldmatrix + cp.async.
// R9: Wm->1-pass, Wq->2-pass, ZW->1-pass; n_lo/Wml/WbTl eliminated.
// B=4, S=2048, D=512, QKD=256, HID=1536

constexpr int Bn = 4, Sn = 2048, Dn = 512, QKDn = 256, HIDn = 1536;
constexpr int BSn = Bn * Sn;                 // 8192
constexpr float LN_EPS = 1e-5f;

// ----------------------------------------------------------------------------
// scratch (device globals)
// ----------------------------------------------------------------------------
static __device__ __align__(16) __half g_xh[BSn * Dn];                   // hi only
static __device__ __align__(16) __half g_Wmh[Dn * Dn];                   // hi only
static __device__ __align__(16) __half g_Whh[2 * HIDn * Dn];             // hi only
static __device__ __align__(16) __half g_Wqh[QKDn * Dn],      g_Wql[QKDn * Dn];
static __device__ __align__(16) __half g_Woh[Dn * HIDn];                 // hi only
static __device__ __align__(16) __half g_WbTh[QKDn * QKDn];              // hi only
static __device__ __align__(16) float  g_tmp1[BSn * Dn];
static __device__ __align__(16) __half g_nh[BSn * Dn];                   // hi only
static __device__ __align__(16) __half g_hbuf[BSn * 2 * HIDn];          // [v | gate] fp16
static __device__ __align__(16) __half g_Zh[BSn * QKDn];                 // hi only
static __device__ __align__(16) __half g_ZWh[BSn * QKDn];                // hi only
static __device__ __align__(16) __half g_Amh[(long long)Bn * Sn * Sn];  // hi only
static __device__ __align__(16) __half g_vTh[(long long)Bn * HIDn * Sn];// hi only
static __device__ __align__(16) __half g_Vh[BSn * HIDn];                 // hi only
static __device__ __align__(16) float  g_U[BSn * Dn];

// ----------------------------------------------------------------------------
// PTX helpers (sm_80-class, valid on plain sm_103)
// ----------------------------------------------------------------------------
__device__ __forceinline__ uint32_t smem_u32(const void* p) {
    uint32_t a;
    asm("{ .reg .u64 t; cvta.to.shared.u64 t, %1; cvt.u32.u64 %0, t; }"
        : "=r"(a) : "l"(p));
    return a;
}
__device__ __forceinline__ void cpa16(uint32_t saddr, const void* gaddr) {
    asm volatile("cp.async.cg.shared.global [%0], [%1], 16;"
                 :: "r"(saddr), "l"(gaddr) : "memory");
}
__device__ __forceinline__ void cpa_commit() {
    asm volatile("cp.async.commit_group;" ::: "memory");
}
template<int N>
__device__ __forceinline__ void cpa_wait() {
    asm volatile("cp.async.wait_group %0;" :: "n"(N) : "memory");
}
__device__ __forceinline__ void ldm_x4(uint32_t a, uint32_t& r0, uint32_t& r1,
                                       uint32_t& r2, uint32_t& r3) {
    asm volatile("ldmatrix.sync.aligned.m8n8.x4.shared.b16 {%0,%1,%2,%3}, [%4];"
                 : "=r"(r0), "=r"(r1), "=r"(r2), "=r"(r3) : "r"(a));
}
__device__ __forceinline__ void mma_f16(float* c, const uint32_t* a, uint32_t b0, uint32_t b1) {
    asm volatile(
        "mma.sync.aligned.m16n8k16.row.col.f32.f16.f16.f32 "
        "{%0,%1,%2,%3}, {%4,%5,%6,%7}, {%8,%9}, {%0,%1,%2,%3};"
        : "+f"(c[0]), "+f"(c[1]), "+f"(c[2]), "+f"(c[3])
        : "r"(a[0]), "r"(a[1]), "r"(a[2]), "r"(a[3]), "r"(b0), "r"(b1));
}
__device__ __forceinline__ void fsplit(float v, __half& h, __half& l) {
    h = __float2half_rn(v);
    l = __float2half_rn(v - __half2float(h));
}
__device__ __forceinline__ uint32_t pack2(__half a, __half b) {
    return (uint32_t)__half_as_ushort(a) | ((uint32_t)__half_as_ushort(b) << 16);
}

// ----------------------------------------------------------------------------
// tensor GEMM: C[m,n] = sum_k A[m,k]*B[n,k]  (both K-major)
// NPASS==2: acc = Ah*Bh + Ah*Bl           (3-stage pipe)
// NPASS==1: acc = Ah*Bh                   (3-stage pipe)
// CTA 128x128, K-tile 32, 4 warps (2x2, 64x64 warp tiles).
// OUT: 0 = fp32, 1 = fp16 hi only
// EPI_GATE reads `extra` as fp16; EPI_BIAS_ADDX as fp32.
// ----------------------------------------------------------------------------
enum { EPI_NONE = 0, EPI_BIAS = 1, EPI_BIAS_RELU = 2, EPI_BIAS_ADDX = 3,
       EPI_RELUSQ = 4, EPI_GATE = 5 };

constexpr int TROW = 80;                         // padded row bytes (64B data + 16B)
constexpr int TILE_B = 128 * TROW;               // 10240
template<int NPASS> struct StageCfg {
    static constexpr int NT = (NPASS == 2) ? 3 : 2;
    static constexpr int NSTAGE = 3;
    static constexpr int STAGE_B = NT * TILE_B;
    static constexpr int SMEM = NSTAGE * STAGE_B;
};

__device__ __forceinline__ void fill_tile(uint32_t sbase,
                                          const __half* __restrict__ g,
                                          long long row0, int ld, long long k0, int tid)
{
    #pragma unroll
    for (int it = 0; it < 4; ++it) {
        int q = tid + it * 128;               // 0..511 chunks of 16B
        int r = q >> 2, c = q & 3;
        cpa16(sbase + r * TROW + c * 16,
              g + (row0 + r) * (long long)ld + k0 + c * 8);
    }
}

template<int EPI, int OUT, int NPASS>
__global__ void __launch_bounds__(128, 2)
tgemm(const __half* __restrict__ pAh,
      const __half* __restrict__ pBh, const __half* __restrict__ pBl,
      const float* __restrict__ bias, const void* __restrict__ extra,
      float* __restrict__ Cf, __half* __restrict__ Ch,
      int K, int lda, int ldb, int ldc,
      long long sA, long long sB, long long sC, long long sE,
      int lde, float scale)
{
    constexpr int STAGE_B = StageCfg<NPASS>::STAGE_B;
    constexpr int NSTAGE  = StageCfg<NPASS>::NSTAGE;
    extern __shared__ char smem[];
    const int tid = threadIdx.x;
    const int wid = tid >> 5, lane = tid & 31;
    const int z = blockIdx.z;
    pAh += (long long)z * sA;
    pBh += (long long)z * sB;
    if (NPASS >= 2) pBl += (long long)z * sB;
    const float*  Exf = (EPI == EPI_BIAS_ADDX && extra)
                        ? (const float*)extra + (long long)z * sE : nullptr;
    const __half* Exh = (EPI == EPI_GATE && extra)
                        ? (const __half*)extra + (long long)z * sE : nullptr;
    const long long coff = (long long)z * sC;
    const long long m0 = (long long)blockIdx.y * 128;
    const long long n0 = (long long)blockIdx.x * 128;
    const uint32_t sb = smem_u32(smem);

    const int wm = (wid >> 1) * 64;      // warp m offset (0, 64)
    const int wn = (wid & 1) * 64;       // warp n offset (0, 64)
    const int rowL = (lane & 7) + ((lane >> 3) & 1) * 8;
    const int cOff = lane >> 4;

    float acc[4][8][4];
    #pragma unroll
    for (int i = 0; i < 4; ++i)
        #pragma unroll
        for (int j = 0; j < 8; ++j)
            #pragma unroll
            for (int t = 0; t < 4; ++t) acc[i][j][t] = 0.0f;

    const int KT = K >> 5;

    auto fill_stage = [&](int stage, long long k0) {
        uint32_t s = sb + stage * STAGE_B;
        fill_tile(s,              pAh, m0, lda, k0, tid);
        fill_tile(s + TILE_B,     pBh, n0, ldb, k0, tid);
        if (NPASS >= 2)
            fill_tile(s + 2 * TILE_B, pBl, n0, ldb, k0, tid);
    };

    // prologue
    #pragma unroll
    for (int s = 0; s < NSTAGE - 1; ++s) {
        fill_stage(s, (long long)s * 32);
        cpa_commit();
    }

    for (int kt = 0; kt < KT; ++kt) {
        const int fs = kt + NSTAGE - 1;
        if (fs < KT) fill_stage(fs % NSTAGE, (long long)fs * 32);
        cpa_commit();
        cpa_wait<NSTAGE - 1>();
        __syncthreads();

        const uint32_t st  = sb + (kt % NSTAGE) * STAGE_B;
        const uint32_t aH  = st;
        const uint32_t bH  = st + TILE_B;
        const uint32_t bL  = st + 2 * TILE_B;   // valid NPASS>=2

        #pragma unroll
        for (int kk = 0; kk < 2; ++kk) {
            const int cc = kk * 2 + cOff;
            uint32_t ah[4][4];
            #pragma unroll
            for (int im = 0; im < 4; ++im) {
                uint32_t off = (uint32_t)((wm + im * 16 + rowL) * TROW + cc * 16);
                ldm_x4(aH + off, ah[im][0], ah[im][1], ah[im][2], ah[im][3]);
            }
            uint32_t bh[4][4], bl[4][4];
            #pragma unroll
            for (int nb = 0; nb < 4; ++nb) {
                uint32_t off = (uint32_t)((wn + nb * 16 + rowL) * TROW + cc * 16);
                ldm_x4(bH + off, bh[nb][0], bh[nb][1], bh[nb][2], bh[nb][3]);
                if (NPASS >= 2)
                    ldm_x4(bL + off, bl[nb][0], bl[nb][1], bl[nb][2], bl[nb][3]);
            }
            #pragma unroll
            for (int im = 0; im < 4; ++im) {
                #pragma unroll
                for (int j = 0; j < 8; ++j) {
                    const int nb = j >> 1, sel = j & 1;
                    mma_f16(acc[im][j], ah[im], bh[nb][sel], bh[nb][sel + 2]);
                    if (NPASS >= 2)
                        mma_f16(acc[im][j], ah[im], bl[nb][sel], bl[nb][sel + 2]);
                }
            }
        }
        __syncthreads();
    }

    // ---- epilogue ----
    const int rql = lane >> 2;
    const int cql = (lane & 3) * 2;

    #pragma unroll
    for (int im = 0; im < 4; ++im) {
        #pragma unroll
        for (int j = 0; j < 8; ++j) {
            #pragma unroll
            for (int half = 0; half < 2; ++half) {
                const long long gm = m0 + wm + im * 16 + rql + half * 8;
                const long long gn = n0 + wn + j * 8 + cql;
                float v0 = acc[im][j][half * 2 + 0];
                float v1 = acc[im][j][half * 2 + 1];

                if (EPI == EPI_BIAS || EPI == EPI_BIAS_RELU || EPI == EPI_BIAS_ADDX) {
                    float2 bv = *reinterpret_cast<const float2*>(&bias[gn]);
                    v0 += bv.x; v1 += bv.y;
                }
                if (EPI == EPI_BIAS_RELU) { v0 = fmaxf(v0, 0.0f); v1 = fmaxf(v1, 0.0f); }
                if (EPI == EPI_BIAS_ADDX) {
                    float2 ev = *reinterpret_cast<const float2*>(&Exf[gm * lde + gn]);
                    v0 += ev.x; v1 += ev.y;
                }
                if (EPI == EPI_GATE) {
                    uint32_t gp = *reinterpret_cast<const uint32_t*>(&Exh[gm * lde + gn]);
                    v0 *= __half2float(__ushort_as_half((unsigned short)(gp & 0xFFFF)));
                    v1 *= __half2float(__ushort_as_half((unsigned short)(gp >> 16)));
                }
                if (EPI == EPI_RELUSQ) {
                    float r0 = fmaxf(v0 * scale, 0.0f), r1 = fmaxf(v1 * scale, 0.0f);
                    v0 = r0 * r0; v1 = r1 * r1;
                }

                const long long oi = coff + gm * ldc + gn;
                if (OUT == 0) {
                    *reinterpret_cast<float2*>(&Cf[oi]) = make_float2(v0, v1);
                } else {
                    *reinterpret_cast<uint32_t*>(&Ch[oi]) =
                        pack2(__float2half_rn(v0), __float2half_rn(v1));
                }
            }
        }
    }
}

// ----------------------------------------------------------------------------
// LayerNorm (D=512)
// ----------------------------------------------------------------------------
__device__ __forceinline__ float block_sum_512(float v, float* red)
{
    #pragma unroll
    for (int o = 16; o > 0; o >>= 1) v += __shfl_down_sync(0xffffffffu, v, o);
    if ((threadIdx.x & 31) == 0) red[threadIdx.x >> 5] = v;
    __syncthreads();
    if (threadIdx.x == 0) {
        float s = 0.0f;
        #pragma unroll
        for (int i = 0; i < 8; i++) s += red[i];
        red[0] = s;
    }
    __syncthreads();
    float r = red[0];
    __syncthreads();
    return r;
}

template<bool HALF_OUT>
__global__ void __launch_bounds__(256)
ln_kernel(const float* __restrict__ in, const float* __restrict__ g,
          const float* __restrict__ b, const float* __restrict__ resid,
          float* __restrict__ outf, __half* __restrict__ oh)
{
    __shared__ float red[8];
    const long long row = blockIdx.x;
    const int t = threadIdx.x;
    const float* rp = in + row * Dn;

    float v0 = rp[t], v1 = rp[t + 256];
    float mean = block_sum_512(v0 + v1, red) * (1.0f / Dn);
    float d0 = v0 - mean, d1 = v1 - mean;
    float var = block_sum_512(d0 * d0 + d1 * d1, red) * (1.0f / Dn);
    float inv = rsqrtf(var + LN_EPS);

    float o0 = d0 * inv * g[t]       + b[t];
    float o1 = d1 * inv * g[t + 256] + b[t + 256];
    if (HALF_OUT) {
        oh[row * Dn + t]       = __float2half_rn(o0);
        oh[row * Dn + t + 256] = __float2half_rn(o1);
    } else {
        if (resid) {
            o0 += resid[row * Dn + t];
            o1 += resid[row * Dn + t + 256];
        }
        outf[row * Dn + t]       = o0;
        outf[row * Dn + t + 256] = o1;
    }
}

// ----------------------------------------------------------------------------
// fused fp32 -> (hi[, lo]) fp16 converter for x + 4 weights
// ----------------------------------------------------------------------------
constexpr int Q_X  = BSn * Dn / 4;
constexpr int Q_WM = Dn * Dn / 4;
constexpr int Q_WH = 2 * HIDn * Dn / 4;
constexpr int Q_WQ = QKDn * Dn / 4;
constexpr int Q_WO = Dn * HIDn / 4;
constexpr int Q_TOT = Q_X + Q_WM + Q_WH + Q_WQ + Q_WO;

__global__ void __launch_bounds__(256)
cvt_all_kernel(const float* __restrict__ x,  __half* xh,
               const float* __restrict__ wm, __half* wmh,
               const float* __restrict__ wh, __half* whh,
               const float* __restrict__ wq, __half* wqh, __half* wql,
               const float* __restrict__ wo, __half* woh)
{
    int i = blockIdx.x * 256 + threadIdx.x;
    if (i >= Q_TOT) return;
    const float* in; __half *oh, *ol;
    if (i < Q_X)                        { in = x;  oh = xh;  ol = nullptr; }
    else if ((i -= Q_X)  < Q_WM)        { in = wm; oh = wmh; ol = nullptr; }
    else if ((i -= Q_WM) < Q_WH)        { in = wh; oh = whh; ol = nullptr; }
    else if ((i -= Q_WH) < Q_WQ)        { in = wq; oh = wqh; ol = wql; }
    else     { i -= Q_WQ;                 in = wo; oh = woh; ol = nullptr; }

    float4 v = reinterpret_cast<const float4*>(in)[i];
    __half h0, l0, h1, l1, h2, l2, h3, l3;
    fsplit(v.x, h0, l0); fsplit(v.y, h1, l1);
    fsplit(v.z, h2, l2); fsplit(v.w, h3, l3);
    reinterpret_cast<uint2*>(oh)[i] = make_uint2(pack2(h0, h1), pack2(h2, h3));
    if (ol)
        reinterpret_cast<uint2*>(ol)[i] = make_uint2(pack2(l0, l1), pack2(l2, l3));
}

// transpose (fp32 in, hi fp16 out): out[c][r] = in[r][c]
__global__ void __launch_bounds__(256)
cvt_tr_kernel(const float* __restrict__ in, __half* __restrict__ oh,
              int ldin, long long sIn, long long sOut, int ldout)
{
    __shared__ float tbuf[32][33];
    const int z = blockIdx.z;
    const float* ip = in + (long long)z * sIn;
    const long long obase = (long long)z * sOut;
    const int c0 = blockIdx.x * 32, r0 = blockIdx.y * 32;
    const int tx = threadIdx.x & 31, ty = threadIdx.x >> 5;

    #pragma unroll
    for (int i = 0; i < 4; i++)
        tbuf[ty + i * 8][tx] = ip[(long long)(r0 + ty + i * 8) * ldin + c0 + tx];
    __syncthreads();
    #pragma unroll
    for (int i = 0; i < 4; i++) {
        float v = tbuf[tx][ty + i * 8];
        long long oi = obase + (long long)(c0 + ty + i * 8) * ldout + r0 + tx;
        oh[oi] = __float2half_rn(v);
    }
}

// fp16 transpose: out[c][r] = in[r][c]
__global__ void __launch_bounds__(256)
tr_h_kernel(const __half* __restrict__ in, __half* __restrict__ out,
            int ldin, long long sIn, long long sOut, int ldout)
{
    __shared__ __half tbuf[32][34];
    const int z = blockIdx.z;
    const __half* ip = in + (long long)z * sIn;
    const long long obase = (long long)z * sOut;
    const int c0 = blockIdx.x * 32, r0 = blockIdx.y * 32;
    const int tx = threadIdx.x & 31, ty = threadIdx.x >> 5;

    #pragma unroll
    for (int i = 0; i < 4; i++)
        tbuf[ty + i * 8][tx] = ip[(long long)(r0 + ty + i * 8) * ldin + c0 + tx];
    __syncthreads();
    #pragma unroll
    for (int i = 0; i < 4; i++) {
        long long oi = obase + (long long)(c0 + ty + i * 8) * ldout + r0 + tx;
        out[oi] = tbuf[tx][ty + i * 8];
    }
}

// ----------------------------------------------------------------------------
// launch
// ----------------------------------------------------------------------------
extern "C" void kernel_launch(void* const* d_in, const int* in_sizes, int n_in,
                              void* d_out, int out_size)
{
    const float* x  = (const float*)d_in[0];
    const float* Wm = (const float*)d_in[1];
    const float* bm = (const float*)d_in[2];
    const float* g1 = (const float*)d_in[3];
    const float* b1 = (const float*)d_in[4];
    const float* Wh = (const float*)d_in[5];
    const float* bh = (const float*)d_in[6];
    const float* Wq = (const float*)d_in[7];
    const float* bq = (const float*)d_in[8];
    const float* Wb = (const float*)d_in[9];
    const float* Wo = (const float*)d_in[10];
    const float* bo = (const float*)d_in[11];
    const float* g2 = (const float*)d_in[12];
    const float* b2 = (const float*)d_in[13];
    float* out = (float*)d_out;

    __half *xh, *Wmh, *Whh, *Wqh, *Wql, *Woh, *WbTh;
    __half *nh, *Zh, *ZWh, *Amh, *vTh, *Vh, *hb;
    float *tmp1, *U;
    cudaGetSymbolAddress((void**)&xh, g_xh);
    cudaGetSymbolAddress((void**)&Wmh, g_Wmh);
    cudaGetSymbolAddress((void**)&Whh, g_Whh);
    cudaGetSymbolAddress((void**)&Wqh, g_Wqh);   cudaGetSymbolAddress((void**)&Wql, g_Wql);
    cudaGetSymbolAddress((void**)&Woh, g_Woh);
    cudaGetSymbolAddress((void**)&WbTh, g_WbTh);
    cudaGetSymbolAddress((void**)&nh, g_nh);
    cudaGetSymbolAddress((void**)&Zh, g_Zh);
    cudaGetSymbolAddress((void**)&ZWh, g_ZWh);
    cudaGetSymbolAddress((void**)&Amh, g_Amh);
    cudaGetSymbolAddress((void**)&vTh, g_vTh);
    cudaGetSymbolAddress((void**)&Vh, g_Vh);
    cudaGetSymbolAddress((void**)&hb, g_hbuf);
    cudaGetSymbolAddress((void**)&tmp1, g_tmp1);
    cudaGetSymbolAddress((void**)&U, g_U);

    constexpr int SM2 = StageCfg<2>::SMEM;   // 3 x 30720 = 92160
    constexpr int SM1 = StageCfg<1>::SMEM;   // 3 x 20480 = 61440
    cudaFuncSetAttribute((const void*)tgemm<EPI_BIAS_ADDX, 0, 1>, cudaFuncAttributeMaxDynamicSharedMemorySize, SM1);
    cudaFuncSetAttribute((const void*)tgemm<EPI_BIAS_RELU, 1, 1>, cudaFuncAttributeMaxDynamicSharedMemorySize, SM1);
    cudaFuncSetAttribute((const void*)tgemm<EPI_BIAS_RELU, 1, 2>, cudaFuncAttributeMaxDynamicSharedMemorySize, SM2);
    cudaFuncSetAttribute((const void*)tgemm<EPI_NONE, 1, 1>,      cudaFuncAttributeMaxDynamicSharedMemorySize, SM1);
    cudaFuncSetAttribute((const void*)tgemm<EPI_RELUSQ, 1, 1>,    cudaFuncAttributeMaxDynamicSharedMemorySize, SM1);
    cudaFuncSetAttribute((const void*)tgemm<EPI_GATE, 1, 1>,      cudaFuncAttributeMaxDynamicSharedMemorySize, SM1);
    cudaFuncSetAttribute((const void*)tgemm<EPI_BIAS, 0, 1>,      cudaFuncAttributeMaxDynamicSharedMemorySize, SM1);

    const float inv_s = 1.0f / (float)Sn;

    // 0) conversions
    cvt_all_kernel<<<(Q_TOT + 255) / 256, 256>>>(
        x, xh, Wm, Wmh, Wh, Whh, Wq, Wqh, Wql, Wo, Woh);
    cvt_tr_kernel<<<dim3(QKDn / 32, QKDn / 32, 1), 256>>>(Wb, WbTh, QKDn, 0, 0, QKDn);

    // 1) tmp1 = x @ Wm^T + bm + x            [1-pass]
    tgemm<EPI_BIAS_ADDX, 0, 1><<<dim3(Dn / 128, BSn / 128, 1), 128, SM1>>>(
        xh, Wmh, nullptr, bm, x, tmp1, nullptr,
        Dn, Dn, Dn, Dn, 0, 0, 0, 0, Dn, 1.0f);

    // 2) nrm = LN(tmp1) -> fp16 hi
    ln_kernel<true><<<BSn, 256>>>(tmp1, g1, b1, nullptr, nullptr, nh);

    // 3) h = relu(nrm @ Wh^T + bh) -> fp16   [1-pass]
    tgemm<EPI_BIAS_RELU, 1, 1><<<dim3(2 * HIDn / 128, BSn / 128, 1), 128, SM1>>>(
        nh, Whh, nullptr, bh, nullptr, nullptr, hb,
        Dn, Dn, Dn, 2 * HIDn, 0, 0, 0, 0, 0, 1.0f);

    // 4) Z = relu(nrm @ Wq^T + bq) -> hi     [2-pass]
    tgemm<EPI_BIAS_RELU, 1, 2><<<dim3(QKDn / 128, BSn / 128, 1), 128, SM2>>>(
        nh, Wqh, Wql, bq, nullptr, nullptr, Zh,
        Dn, Dn, Dn, QKDn, 0, 0, 0, 0, 0, 1.0f);

    // 5) ZW = Z @ Wb -> hi                   [1-pass]
    tgemm<EPI_NONE, 1, 1><<<dim3(QKDn / 128, BSn / 128, 1), 128, SM1>>>(
        Zh, WbTh, nullptr, nullptr, nullptr, nullptr, ZWh,
        QKDn, QKDn, QKDn, QKDn, 0, 0, 0, 0, 0, 1.0f);

    // 6) A = relu((ZW @ Z^T)/S)^2 -> hi      [1-pass]
    tgemm<EPI_RELUSQ, 1, 1><<<dim3(Sn / 128, Sn / 128, Bn), 128, SM1>>>(
        ZWh, Zh, nullptr, nullptr, nullptr, nullptr, Amh,
        QKDn, QKDn, QKDn, Sn,
        (long long)Sn * QKDn, (long long)Sn * QKDn, (long long)Sn * Sn, 0, 0, inv_s);

    // 7) vT = transpose(v) fp16 -> fp16
    tr_h_kernel<<<dim3(HIDn / 32, Sn / 32, Bn), 256>>>(
        hb, vTh, 2 * HIDn, (long long)Sn * 2 * HIDn, (long long)HIDn * Sn, Sn);

    // 8) V = (A @ v) * gate -> hi            [1-pass, gate fp16]
    tgemm<EPI_GATE, 1, 1><<<dim3(HIDn / 128, Sn / 128, Bn), 128, SM1>>>(
        Amh, vTh, nullptr, nullptr, hb + HIDn, nullptr, Vh,
        Sn, Sn, Sn, HIDn,
        (long long)Sn * Sn, (long long)HIDn * Sn, (long long)Sn * HIDn,
        (long long)Sn * 2 * HIDn, 2 * HIDn, 1.0f);

    // 9) U = V @ Wo^T + bo fp32              [1-pass]
    tgemm<EPI_BIAS, 0, 1><<<dim3(Dn / 128, BSn / 128, 1), 128, SM1>>>(
        Vh, Woh, nullptr, bo, nullptr, U, nullptr,
        HIDn, HIDn, HIDn, Dn, 0, 0, 0, 0, 0, 1.0f);

    // 10) out = LN(U) + x
    ln_kernel<false><<<BSn, 256>>>(U, g2, b2, x, out, nullptr);
}

// round 10
// speedup vs baseline: 8.4141x; 1.1264x over previous
#include <cuda_runtime.h>
#include <cuda_fp16.h>
#include <cstdint>

// GAU block on GB300 (plain sm_103 target): fp16 1-pass GEMMs on
// mma.sync.m16n8k16 + ldmatrix + cp.async.
// R10: all GEMMs 1-pass; A*v reads v in-place via ldmatrix.trans (no transpose
// kernel); Wh GEMM overlapped with Z/ZW/QK chain via stream fork-join.
// B=4, S=2048, D=512, QKD=256, HID=1536

constexpr int Bn = 4, Sn = 2048, Dn = 512, QKDn = 256, HIDn = 1536;
constexpr int BSn = Bn * Sn;                 // 8192
constexpr float LN_EPS = 1e-5f;

// ----------------------------------------------------------------------------
// scratch (device globals)
// ----------------------------------------------------------------------------
static __device__ __align__(16) __half g_xh[BSn * Dn];
static __device__ __align__(16) __half g_Wmh[Dn * Dn];
static __device__ __align__(16) __half g_Whh[2 * HIDn * Dn];
static __device__ __align__(16) __half g_Wqh[QKDn * Dn];
static __device__ __align__(16) __half g_Woh[Dn * HIDn];
static __device__ __align__(16) __half g_WbTh[QKDn * QKDn];
static __device__ __align__(16) float  g_tmp1[BSn * Dn];
static __device__ __align__(16) __half g_nh[BSn * Dn];
static __device__ __align__(16) __half g_hbuf[BSn * 2 * HIDn];          // [v | gate]
static __device__ __align__(16) __half g_Zh[BSn * QKDn];
static __device__ __align__(16) __half g_ZWh[BSn * QKDn];
static __device__ __align__(16) __half g_Amh[(long long)Bn * Sn * Sn];
static __device__ __align__(16) __half g_Vh[BSn * HIDn];
static __device__ __align__(16) float  g_U[BSn * Dn];

// ----------------------------------------------------------------------------
// PTX helpers
// ----------------------------------------------------------------------------
__device__ __forceinline__ uint32_t smem_u32(const void* p) {
    uint32_t a;
    asm("{ .reg .u64 t; cvta.to.shared.u64 t, %1; cvt.u32.u64 %0, t; }"
        : "=r"(a) : "l"(p));
    return a;
}
__device__ __forceinline__ void cpa16(uint32_t saddr, const void* gaddr) {
    asm volatile("cp.async.cg.shared.global [%0], [%1], 16;"
                 :: "r"(saddr), "l"(gaddr) : "memory");
}
__device__ __forceinline__ void cpa_commit() {
    asm volatile("cp.async.commit_group;" ::: "memory");
}
template<int N>
__device__ __forceinline__ void cpa_wait() {
    asm volatile("cp.async.wait_group %0;" :: "n"(N) : "memory");
}
__device__ __forceinline__ void ldm_x4(uint32_t a, uint32_t& r0, uint32_t& r1,
                                       uint32_t& r2, uint32_t& r3) {
    asm volatile("ldmatrix.sync.aligned.m8n8.x4.shared.b16 {%0,%1,%2,%3}, [%4];"
                 : "=r"(r0), "=r"(r1), "=r"(r2), "=r"(r3) : "r"(a));
}
__device__ __forceinline__ void ldm_x4_trans(uint32_t a, uint32_t& r0, uint32_t& r1,
                                             uint32_t& r2, uint32_t& r3) {
    asm volatile("ldmatrix.sync.aligned.m8n8.x4.trans.shared.b16 {%0,%1,%2,%3}, [%4];"
                 : "=r"(r0), "=r"(r1), "=r"(r2), "=r"(r3) : "r"(a));
}
__device__ __forceinline__ void mma_f16(float* c, const uint32_t* a, uint32_t b0, uint32_t b1) {
    asm volatile(
        "mma.sync.aligned.m16n8k16.row.col.f32.f16.f16.f32 "
        "{%0,%1,%2,%3}, {%4,%5,%6,%7}, {%8,%9}, {%0,%1,%2,%3};"
        : "+f"(c[0]), "+f"(c[1]), "+f"(c[2]), "+f"(c[3])
        : "r"(a[0]), "r"(a[1]), "r"(a[2]), "r"(a[3]), "r"(b0), "r"(b1));
}
__device__ __forceinline__ uint32_t pack2(__half a, __half b) {
    return (uint32_t)__half_as_ushort(a) | ((uint32_t)__half_as_ushort(b) << 16);
}

// ----------------------------------------------------------------------------
// tensor GEMM (all 1-pass): C[m,n] = sum_k A[m,k]*B[n,k]
// A K-major. B: TRB==false -> K-major (B[n][k]); TRB==true -> N-major source
// (B stored as V[k][n], loaded via ldmatrix.trans).
// CTA 128x128, K-tile 32, 4 warps (2x2, 64x64 warp tiles), 3-stage cp.async.
// OUT: 0 = fp32, 1 = fp16.  EPI_GATE extra fp16, EPI_BIAS_ADDX extra fp32.
// ----------------------------------------------------------------------------
enum { EPI_NONE = 0, EPI_BIAS = 1, EPI_BIAS_RELU = 2, EPI_BIAS_ADDX = 3,
       EPI_RELUSQ = 4, EPI_GATE = 5 };

constexpr int TROW = 80;                       // K-major tile row bytes (64 + 16 pad)
constexpr int TILE_B = 128 * TROW;             // 10240
constexpr int TRB_ROW = 272;                   // N-major tile row bytes (256 + 16 pad)
constexpr int TRB_TILE = 32 * TRB_ROW;         // 8704
template<bool TRB> struct StageCfg {
    static constexpr int STAGE_B = TILE_B + (TRB ? TRB_TILE : TILE_B);
    static constexpr int SMEM = 3 * STAGE_B;   // 56832 (TRB) / 61440
};

__device__ __forceinline__ void fill_tile(uint32_t sbase,
                                          const __half* __restrict__ g,
                                          long long row0, int ld, long long k0, int tid)
{
    #pragma unroll
    for (int it = 0; it < 4; ++it) {
        int q = tid + it * 128;               // 512 chunks of 16B
        int r = q >> 2, c = q & 3;
        cpa16(sbase + r * TROW + c * 16,
              g + (row0 + r) * (long long)ld + k0 + c * 8);
    }
}

// N-major fill: 32 k-rows x 256B (128 halves), padded stride 272B
__device__ __forceinline__ void fill_tile_trb(uint32_t sbase,
                                              const __half* __restrict__ g,
                                              long long n0, int ld, long long k0, int tid)
{
    #pragma unroll
    for (int it = 0; it < 4; ++it) {
        int q = tid + it * 128;               // 512 chunks of 16B
        int r = q >> 4, c = q & 15;
        cpa16(sbase + r * TRB_ROW + c * 16,
              g + (k0 + r) * (long long)ld + n0 + c * 8);
    }
}

template<int EPI, int OUT, bool TRB = false>
__global__ void __launch_bounds__(128, 2)
tgemm(const __half* __restrict__ pA,
      const __half* __restrict__ pB,
      const float* __restrict__ bias, const void* __restrict__ extra,
      float* __restrict__ Cf, __half* __restrict__ Ch,
      int K, int lda, int ldb, int ldc,
      long long sA, long long sB, long long sC, long long sE,
      int lde, float scale)
{
    constexpr int STAGE_B = StageCfg<TRB>::STAGE_B;
    extern __shared__ char smem[];
    const int tid = threadIdx.x;
    const int wid = tid >> 5, lane = tid & 31;
    const int z = blockIdx.z;
    pA += (long long)z * sA;
    pB += (long long)z * sB;
    const float*  Exf = (EPI == EPI_BIAS_ADDX && extra)
                        ? (const float*)extra + (long long)z * sE : nullptr;
    const __half* Exh = (EPI == EPI_GATE && extra)
                        ? (const __half*)extra + (long long)z * sE : nullptr;
    const long long coff = (long long)z * sC;
    const long long m0 = (long long)blockIdx.y * 128;
    const long long n0 = (long long)blockIdx.x * 128;
    const uint32_t sb = smem_u32(smem);

    const int wm = (wid >> 1) * 64;      // warp m offset (0, 64)
    const int wn = (wid & 1) * 64;       // warp n offset (0, 64)
    const int rowL = (lane & 7) + ((lane >> 3) & 1) * 8;
    const int cOff = lane >> 4;

    float acc[4][8][4];
    #pragma unroll
    for (int i = 0; i < 4; ++i)
        #pragma unroll
        for (int j = 0; j < 8; ++j)
            #pragma unroll
            for (int t = 0; t < 4; ++t) acc[i][j][t] = 0.0f;

    const int KT = K >> 5;

    auto fill_stage = [&](int stage, long long k0) {
        uint32_t s = sb + stage * STAGE_B;
        fill_tile(s, pA, m0, lda, k0, tid);
        if (TRB) fill_tile_trb(s + TILE_B, pB, n0, ldb, k0, tid);
        else     fill_tile(s + TILE_B, pB, n0, ldb, k0, tid);
    };

    // prologue: 2 stages ahead
    #pragma unroll
    for (int s = 0; s < 2; ++s) {
        fill_stage(s, (long long)s * 32);
        cpa_commit();
    }

    for (int kt = 0; kt < KT; ++kt) {
        const int fs = kt + 2;
        if (fs < KT) fill_stage(fs % 3, (long long)fs * 32);
        cpa_commit();
        cpa_wait<2>();
        __syncthreads();

        const uint32_t st = sb + (kt % 3) * STAGE_B;
        const uint32_t aB = st;
        const uint32_t bB = st + TILE_B;

        #pragma unroll
        for (int kk = 0; kk < 2; ++kk) {
            const int cc = kk * 2 + cOff;
            uint32_t ah[4][4];
            #pragma unroll
            for (int im = 0; im < 4; ++im) {
                uint32_t off = (uint32_t)((wm + im * 16 + rowL) * TROW + cc * 16);
                ldm_x4(aB + off, ah[im][0], ah[im][1], ah[im][2], ah[im][3]);
            }
            uint32_t bh[4][4];
            #pragma unroll
            for (int nb = 0; nb < 4; ++nb) {
                if (TRB) {
                    // trans load from N-major tile: r0=(n0-7,k0-7) r1=(n8-15,k0-7)
                    // r2=(n0-7,k8-15) r3=(n8-15,k8-15)  -- matches non-trans order
                    uint32_t off = (uint32_t)(
                        (kk * 16 + ((lane >> 4) & 1) * 8 + (lane & 7)) * TRB_ROW +
                        (wn + nb * 16 + ((lane >> 3) & 1) * 8) * 2);
                    ldm_x4_trans(bB + off, bh[nb][0], bh[nb][1], bh[nb][2], bh[nb][3]);
                } else {
                    uint32_t off = (uint32_t)((wn + nb * 16 + rowL) * TROW + cc * 16);
                    ldm_x4(bB + off, bh[nb][0], bh[nb][1], bh[nb][2], bh[nb][3]);
                }
            }
            #pragma unroll
            for (int im = 0; im < 4; ++im) {
                #pragma unroll
                for (int j = 0; j < 8; ++j) {
                    const int nb = j >> 1, sel = j & 1;
                    mma_f16(acc[im][j], ah[im], bh[nb][sel], bh[nb][sel + 2]);
                }
            }
        }
        __syncthreads();
    }

    // ---- epilogue ----
    const int rql = lane >> 2;
    const int cql = (lane & 3) * 2;

    #pragma unroll
    for (int im = 0; im < 4; ++im) {
        #pragma unroll
        for (int j = 0; j < 8; ++j) {
            #pragma unroll
            for (int half = 0; half < 2; ++half) {
                const long long gm = m0 + wm + im * 16 + rql + half * 8;
                const long long gn = n0 + wn + j * 8 + cql;
                float v0 = acc[im][j][half * 2 + 0];
                float v1 = acc[im][j][half * 2 + 1];

                if (EPI == EPI_BIAS || EPI == EPI_BIAS_RELU || EPI == EPI_BIAS_ADDX) {
                    float2 bv = *reinterpret_cast<const float2*>(&bias[gn]);
                    v0 += bv.x; v1 += bv.y;
                }
                if (EPI == EPI_BIAS_RELU) { v0 = fmaxf(v0, 0.0f); v1 = fmaxf(v1, 0.0f); }
                if (EPI == EPI_BIAS_ADDX) {
                    float2 ev = *reinterpret_cast<const float2*>(&Exf[gm * lde + gn]);
                    v0 += ev.x; v1 += ev.y;
                }
                if (EPI == EPI_GATE) {
                    uint32_t gp = *reinterpret_cast<const uint32_t*>(&Exh[gm * lde + gn]);
                    v0 *= __half2float(__ushort_as_half((unsigned short)(gp & 0xFFFF)));
                    v1 *= __half2float(__ushort_as_half((unsigned short)(gp >> 16)));
                }
                if (EPI == EPI_RELUSQ) {
                    float r0 = fmaxf(v0 * scale, 0.0f), r1 = fmaxf(v1 * scale, 0.0f);
                    v0 = r0 * r0; v1 = r1 * r1;
                }

                const long long oi = coff + gm * ldc + gn;
                if (OUT == 0) {
                    *reinterpret_cast<float2*>(&Cf[oi]) = make_float2(v0, v1);
                } else {
                    *reinterpret_cast<uint32_t*>(&Ch[oi]) =
                        pack2(__float2half_rn(v0), __float2half_rn(v1));
                }
            }
        }
    }
}

// ----------------------------------------------------------------------------
// LayerNorm (D=512)
// ----------------------------------------------------------------------------
__device__ __forceinline__ float block_sum_512(float v, float* red)
{
    #pragma unroll
    for (int o = 16; o > 0; o >>= 1) v += __shfl_down_sync(0xffffffffu, v, o);
    if ((threadIdx.x & 31) == 0) red[threadIdx.x >> 5] = v;
    __syncthreads();
    if (threadIdx.x == 0) {
        float s = 0.0f;
        #pragma unroll
        for (int i = 0; i < 8; i++) s += red[i];
        red[0] = s;
    }
    __syncthreads();
    float r = red[0];
    __syncthreads();
    return r;
}

template<bool HALF_OUT>
__global__ void __launch_bounds__(256)
ln_kernel(const float* __restrict__ in, const float* __restrict__ g,
          const float* __restrict__ b, const float* __restrict__ resid,
          float* __restrict__ outf, __half* __restrict__ oh)
{
    __shared__ float red[8];
    const long long row = blockIdx.x;
    const int t = threadIdx.x;
    const float* rp = in + row * Dn;

    float v0 = rp[t], v1 = rp[t + 256];
    float mean = block_sum_512(v0 + v1, red) * (1.0f / Dn);
    float d0 = v0 - mean, d1 = v1 - mean;
    float var = block_sum_512(d0 * d0 + d1 * d1, red) * (1.0f / Dn);
    float inv = rsqrtf(var + LN_EPS);

    float o0 = d0 * inv * g[t]       + b[t];
    float o1 = d1 * inv * g[t + 256] + b[t + 256];
    if (HALF_OUT) {
        oh[row * Dn + t]       = __float2half_rn(o0);
        oh[row * Dn + t + 256] = __float2half_rn(o1);
    } else {
        if (resid) {
            o0 += resid[row * Dn + t];
            o1 += resid[row * Dn + t + 256];
        }
        outf[row * Dn + t]       = o0;
        outf[row * Dn + t + 256] = o1;
    }
}

// ----------------------------------------------------------------------------
// fused fp32 -> fp16 converter for x + 4 weights
// ----------------------------------------------------------------------------
constexpr int Q_X  = BSn * Dn / 4;
constexpr int Q_WM = Dn * Dn / 4;
constexpr int Q_WH = 2 * HIDn * Dn / 4;
constexpr int Q_WQ = QKDn * Dn / 4;
constexpr int Q_WO = Dn * HIDn / 4;
constexpr int Q_TOT = Q_X + Q_WM + Q_WH + Q_WQ + Q_WO;

__global__ void __launch_bounds__(256)
cvt_all_kernel(const float* __restrict__ x,  __half* xh,
               const float* __restrict__ wm, __half* wmh,
               const float* __restrict__ wh, __half* whh,
               const float* __restrict__ wq, __half* wqh,
               const float* __restrict__ wo, __half* woh)
{
    int i = blockIdx.x * 256 + threadIdx.x;
    if (i >= Q_TOT) return;
    const float* in; __half* oh;
    if (i < Q_X)                        { in = x;  oh = xh;  }
    else if ((i -= Q_X)  < Q_WM)        { in = wm; oh = wmh; }
    else if ((i -= Q_WM) < Q_WH)        { in = wh; oh = whh; }
    else if ((i -= Q_WH) < Q_WQ)        { in = wq; oh = wqh; }
    else     { i -= Q_WQ;                 in = wo; oh = woh; }

    float4 v = reinterpret_cast<const float4*>(in)[i];
    reinterpret_cast<uint2*>(oh)[i] = make_uint2(
        pack2(__float2half_rn(v.x), __float2half_rn(v.y)),
        pack2(__float2half_rn(v.z), __float2half_rn(v.w)));
}

// transpose (fp32 in, fp16 out): out[c][r] = in[r][c]   (Wb only)
__global__ void __launch_bounds__(256)
cvt_tr_kernel(const float* __restrict__ in, __half* __restrict__ oh,
              int ldin, int ldout)
{
    __shared__ float tbuf[32][33];
    const int c0 = blockIdx.x * 32, r0 = blockIdx.y * 32;
    const int tx = threadIdx.x & 31, ty = threadIdx.x >> 5;

    #pragma unroll
    for (int i = 0; i < 4; i++)
        tbuf[ty + i * 8][tx] = in[(long long)(r0 + ty + i * 8) * ldin + c0 + tx];
    __syncthreads();
    #pragma unroll
    for (int i = 0; i < 4; i++) {
        float v = tbuf[tx][ty + i * 8];
        long long oi = (long long)(c0 + ty + i * 8) * ldout + r0 + tx;
        oh[oi] = __float2half_rn(v);
    }
}

// ----------------------------------------------------------------------------
// launch
// ----------------------------------------------------------------------------
extern "C" void kernel_launch(void* const* d_in, const int* in_sizes, int n_in,
                              void* d_out, int out_size)
{
    const float* x  = (const float*)d_in[0];
    const float* Wm = (const float*)d_in[1];
    const float* bm = (const float*)d_in[2];
    const float* g1 = (const float*)d_in[3];
    const float* b1 = (const float*)d_in[4];
    const float* Wh = (const float*)d_in[5];
    const float* bh = (const float*)d_in[6];
    const float* Wq = (const float*)d_in[7];
    const float* bq = (const float*)d_in[8];
    const float* Wb = (const float*)d_in[9];
    const float* Wo = (const float*)d_in[10];
    const float* bo = (const float*)d_in[11];
    const float* g2 = (const float*)d_in[12];
    const float* b2 = (const float*)d_in[13];
    float* out = (float*)d_out;

    __half *xh, *Wmh, *Whh, *Wqh, *Woh, *WbTh;
    __half *nh, *Zh, *ZWh, *Amh, *Vh, *hb;
    float *tmp1, *U;
    cudaGetSymbolAddress((void**)&xh, g_xh);
    cudaGetSymbolAddress((void**)&Wmh, g_Wmh);
    cudaGetSymbolAddress((void**)&Whh, g_Whh);
    cudaGetSymbolAddress((void**)&Wqh, g_Wqh);
    cudaGetSymbolAddress((void**)&Woh, g_Woh);
    cudaGetSymbolAddress((void**)&WbTh, g_WbTh);
    cudaGetSymbolAddress((void**)&nh, g_nh);
    cudaGetSymbolAddress((void**)&Zh, g_Zh);
    cudaGetSymbolAddress((void**)&ZWh, g_ZWh);
    cudaGetSymbolAddress((void**)&Amh, g_Amh);
    cudaGetSymbolAddress((void**)&Vh, g_Vh);
    cudaGetSymbolAddress((void**)&hb, g_hbuf);
    cudaGetSymbolAddress((void**)&tmp1, g_tmp1);
    cudaGetSymbolAddress((void**)&U, g_U);

    constexpr int SM1 = StageCfg<false>::SMEM;   // 61440
    constexpr int SMT = StageCfg<true>::SMEM;    // 56832
    cudaFuncSetAttribute((const void*)tgemm<EPI_BIAS_ADDX, 0>, cudaFuncAttributeMaxDynamicSharedMemorySize, SM1);
    cudaFuncSetAttribute((const void*)tgemm<EPI_BIAS_RELU, 1>, cudaFuncAttributeMaxDynamicSharedMemorySize, SM1);
    cudaFuncSetAttribute((const void*)tgemm<EPI_NONE, 1>,      cudaFuncAttributeMaxDynamicSharedMemorySize, SM1);
    cudaFuncSetAttribute((const void*)tgemm<EPI_RELUSQ, 1>,    cudaFuncAttributeMaxDynamicSharedMemorySize, SM1);
    cudaFuncSetAttribute((const void*)tgemm<EPI_GATE, 1, true>,cudaFuncAttributeMaxDynamicSharedMemorySize, SMT);
    cudaFuncSetAttribute((const void*)tgemm<EPI_BIAS, 0>,      cudaFuncAttributeMaxDynamicSharedMemorySize, SM1);

    // fork-join plumbing (created fresh per call; kernel_launch is invoked
    // only a handful of times, handles are tiny host-side objects)
    cudaStream_t s1;
    cudaEvent_t evF, evJ;
    cudaStreamCreateWithFlags(&s1, cudaStreamNonBlocking);
    cudaEventCreateWithFlags(&evF, cudaEventDisableTiming);
    cudaEventCreateWithFlags(&evJ, cudaEventDisableTiming);

    const float inv_s = 1.0f / (float)Sn;

    // 0) conversions
    cvt_all_kernel<<<(Q_TOT + 255) / 256, 256>>>(
        x, xh, Wm, Wmh, Wh, Whh, Wq, Wqh, Wo, Woh);
    cvt_tr_kernel<<<dim3(QKDn / 32, QKDn / 32, 1), 256>>>(Wb, WbTh, QKDn, QKDn);

    // 1) tmp1 = x @ Wm^T + bm + x
    tgemm<EPI_BIAS_ADDX, 0><<<dim3(Dn / 128, BSn / 128, 1), 128, SM1>>>(
        xh, Wmh, bm, x, tmp1, nullptr,
        Dn, Dn, Dn, Dn, 0, 0, 0, 0, Dn, 1.0f);

    // 2) nrm = LN(tmp1) -> fp16
    ln_kernel<true><<<BSn, 256>>>(tmp1, g1, b1, nullptr, nullptr, nh);

    // fork: branch B (Z -> ZW -> QK) on s1, branch A (Wh) stays on default
    cudaEventRecord(evF, 0);
    cudaStreamWaitEvent(s1, evF, 0);

    // 4) Z = relu(nrm @ Wq^T + bq)   (s1)
    tgemm<EPI_BIAS_RELU, 1><<<dim3(QKDn / 128, BSn / 128, 1), 128, SM1, s1>>>(
        nh, Wqh, bq, nullptr, nullptr, Zh,
        Dn, Dn, Dn, QKDn, 0, 0, 0, 0, 0, 1.0f);

    // 5) ZW = Z @ Wb                 (s1)
    tgemm<EPI_NONE, 1><<<dim3(QKDn / 128, BSn / 128, 1), 128, SM1, s1>>>(
        Zh, WbTh, nullptr, nullptr, nullptr, ZWh,
        QKDn, QKDn, QKDn, QKDn, 0, 0, 0, 0, 0, 1.0f);

    // 6) A = relu((ZW @ Z^T)/S)^2    (s1)
    tgemm<EPI_RELUSQ, 1><<<dim3(Sn / 128, Sn / 128, Bn), 128, SM1, s1>>>(
        ZWh, Zh, nullptr, nullptr, nullptr, Amh,
        QKDn, QKDn, QKDn, Sn,
        (long long)Sn * QKDn, (long long)Sn * QKDn, (long long)Sn * Sn, 0, 0, inv_s);

    // 3) h = relu(nrm @ Wh^T + bh) -> fp16   (default stream, overlaps 4-6)
    tgemm<EPI_BIAS_RELU, 1><<<dim3(2 * HIDn / 128, BSn / 128, 1), 128, SM1>>>(
        nh, Whh, bh, nullptr, nullptr, hb,
        Dn, Dn, Dn, 2 * HIDn, 0, 0, 0, 0, 0, 1.0f);

    // join
    cudaEventRecord(evJ, s1);
    cudaStreamWaitEvent(0, evJ, 0);

    // 8) V = (A @ v) * gate   (v read in-place from hb via ldmatrix.trans)
    tgemm<EPI_GATE, 1, true><<<dim3(HIDn / 128, Sn / 128, Bn), 128, SMT>>>(
        Amh, hb, nullptr, hb + HIDn, nullptr, Vh,
        Sn, Sn, 2 * HIDn, HIDn,
        (long long)Sn * Sn, (long long)Sn * 2 * HIDn, (long long)Sn * HIDn,
        (long long)Sn * 2 * HIDn, 2 * HIDn, 1.0f);

    // 9) U = V @ Wo^T + bo
    tgemm<EPI_BIAS, 0><<<dim3(Dn / 128, BSn / 128, 1), 128, SM1>>>(
        Vh, Woh, bo, nullptr, U, nullptr,
        HIDn, HIDn, HIDn, Dn, 0, 0, 0, 0, 0, 1.0f);

    // 10) out = LN(U) + x
    ln_kernel<false><<<BSn, 256>>>(U, g2, b2, x, out, nullptr);
}